// round 3
// baseline (speedup 1.0000x reference)
#include <cuda_runtime.h>
#include <math_constants.h>
#include <cstdint>

// Problem constants (fixed by the reference setup)
#define SEQ    2048
#define DMODEL 1024
#define NHEADS 16
#define DEPTH  64
#define BATCH  2
#define MROWS  (BATCH * SEQ)   // 4096

// Scratch (allocation-free rule: __device__ globals)
__device__ float g_q[MROWS * DMODEL];
__device__ float g_k[MROWS * DMODEL];
__device__ float g_v[MROWS * DMODEL];
__device__ float g_attn[MROWS * DMODEL];

// ---------------------------------------------------------------------------
// TF32 helpers
// ---------------------------------------------------------------------------
__device__ __forceinline__ uint32_t f2tf32(float f) {
    uint32_t r;
    asm("cvt.rna.tf32.f32 %0, %1;" : "=r"(r) : "f"(f));
    return r;
}

__device__ __forceinline__ void mma_tf32(float* c, const uint32_t* a, const uint32_t* b) {
    asm volatile(
        "mma.sync.aligned.m16n8k8.row.col.f32.tf32.tf32.f32 "
        "{%0,%1,%2,%3}, {%4,%5,%6,%7}, {%8,%9}, {%0,%1,%2,%3};"
        : "+f"(c[0]), "+f"(c[1]), "+f"(c[2]), "+f"(c[3])
        : "r"(a[0]), "r"(a[1]), "r"(a[2]), "r"(a[3]), "r"(b[0]), "r"(b[1]));
}

// ---------------------------------------------------------------------------
// 3xTF32 tensor-core GEMM: C[M,N] = alpha * A[M,K] @ B[K,N], row-major.
// 128x128 block tile, BK=16, 256 threads (8 warps), warp tile 32x64.
// A split into hi/lo tf32; error ~2^-22 (fp32-equivalent for our tolerance).
// ---------------------------------------------------------------------------
#define GBM 128
#define GBN 128
#define GBK 16
#define A_STRIDE 17     // [128][17] floats — conflict-free for stores & frag loads
#define B_STRIDE 132    // [16][132] floats

__global__ __launch_bounds__(256) void tf32_gemm_kernel(
    const float* __restrict__ A, const float* __restrict__ B,
    float* __restrict__ C, int M, int N, int K, float alpha)
{
    __shared__ uint32_t As_hi[GBM * A_STRIDE];
    __shared__ uint32_t As_lo[GBM * A_STRIDE];
    __shared__ uint32_t Bs_hi[GBK * B_STRIDE];
    __shared__ uint32_t Bs_lo[GBK * B_STRIDE];

    const int tid  = threadIdx.x;
    const int lane = tid & 31;
    const int wid  = tid >> 5;
    const int g    = lane >> 2;   // group id 0..7
    const int tig  = lane & 3;    // thread-in-group 0..3

    const int warp_m = wid & 3;   // 4 warps along M (32 rows each)
    const int warp_n = wid >> 2;  // 2 warps along N (64 cols each)

    const int blockRow = blockIdx.y * GBM;
    const int blockCol = blockIdx.x * GBN;

    float acc[2][8][4];
    #pragma unroll
    for (int mu = 0; mu < 2; mu++)
        #pragma unroll
        for (int nu = 0; nu < 8; nu++)
            #pragma unroll
            for (int r = 0; r < 4; r++)
                acc[mu][nu][r] = 0.0f;

    for (int k0 = 0; k0 < K; k0 += GBK) {
        // --- global -> shared (hi/lo split) ---
        // A tile: 128 rows x 16 cols = 512 float4, 2 per thread
        #pragma unroll
        for (int j = 0; j < 2; j++) {
            int idx = tid + j * 256;
            int row = idx >> 2;
            int c4  = (idx & 3) * 4;
            float4 a = *(const float4*)(A + (size_t)(blockRow + row) * K + k0 + c4);
            float av[4] = {a.x, a.y, a.z, a.w};
            #pragma unroll
            for (int i = 0; i < 4; i++) {
                uint32_t hi = f2tf32(av[i]);
                float lo = av[i] - __uint_as_float(hi);
                As_hi[row * A_STRIDE + c4 + i] = hi;
                As_lo[row * A_STRIDE + c4 + i] = f2tf32(lo);
            }
        }
        // B tile: 16 rows x 128 cols = 512 float4, 2 per thread
        #pragma unroll
        for (int j = 0; j < 2; j++) {
            int idx = tid + j * 256;
            int row = idx >> 5;
            int c4  = (idx & 31) * 4;
            float4 b = *(const float4*)(B + (size_t)(k0 + row) * N + blockCol + c4);
            float bv[4] = {b.x, b.y, b.z, b.w};
            #pragma unroll
            for (int i = 0; i < 4; i++) {
                uint32_t hi = f2tf32(bv[i]);
                float lo = bv[i] - __uint_as_float(hi);
                Bs_hi[row * B_STRIDE + c4 + i] = hi;
                Bs_lo[row * B_STRIDE + c4 + i] = f2tf32(lo);
            }
        }
        __syncthreads();

        // --- two k8 steps ---
        #pragma unroll
        for (int ks = 0; ks < 2; ks++) {
            const int kk = ks * 8;
            uint32_t ah[2][4], al[2][4];
            #pragma unroll
            for (int mu = 0; mu < 2; mu++) {
                int mrow = warp_m * 32 + mu * 16;
                int r0 = (mrow + g) * A_STRIDE + kk + tig;
                int r1 = (mrow + g + 8) * A_STRIDE + kk + tig;
                ah[mu][0] = As_hi[r0];     ah[mu][1] = As_hi[r1];
                ah[mu][2] = As_hi[r0 + 4]; ah[mu][3] = As_hi[r1 + 4];
                al[mu][0] = As_lo[r0];     al[mu][1] = As_lo[r1];
                al[mu][2] = As_lo[r0 + 4]; al[mu][3] = As_lo[r1 + 4];
            }
            uint32_t bh[8][2], bl[8][2];
            #pragma unroll
            for (int nu = 0; nu < 8; nu++) {
                int ncol = warp_n * 64 + nu * 8 + g;
                bh[nu][0] = Bs_hi[(kk + tig) * B_STRIDE + ncol];
                bh[nu][1] = Bs_hi[(kk + tig + 4) * B_STRIDE + ncol];
                bl[nu][0] = Bs_lo[(kk + tig) * B_STRIDE + ncol];
                bl[nu][1] = Bs_lo[(kk + tig + 4) * B_STRIDE + ncol];
            }
            #pragma unroll
            for (int mu = 0; mu < 2; mu++)
                #pragma unroll
                for (int nu = 0; nu < 8; nu++) {
                    mma_tf32(acc[mu][nu], ah[mu], bh[nu]);
                    mma_tf32(acc[mu][nu], ah[mu], bl[nu]);
                    mma_tf32(acc[mu][nu], al[mu], bh[nu]);
                }
        }
        __syncthreads();
    }

    // --- epilogue ---
    #pragma unroll
    for (int mu = 0; mu < 2; mu++) {
        #pragma unroll
        for (int nu = 0; nu < 8; nu++) {
            int row0 = blockRow + warp_m * 32 + mu * 16 + g;
            int col  = blockCol + warp_n * 64 + nu * 8 + tig * 2;
            float2 v0 = make_float2(alpha * acc[mu][nu][0], alpha * acc[mu][nu][1]);
            float2 v1 = make_float2(alpha * acc[mu][nu][2], alpha * acc[mu][nu][3]);
            *(float2*)(C + (size_t)row0 * N + col)       = v0;
            *(float2*)(C + (size_t)(row0 + 8) * N + col) = v1;
        }
    }
}

// ---------------------------------------------------------------------------
// Flash attention (fp32, online softmax), pair-split version.
// 256 threads; thread pair (2r, 2r+1) owns query row r: each thread handles
// 32 of the 64 depth dims. Full dot recovered via shfl_xor with the partner.
// Scores live in registers (no SMEM score array).
// ---------------------------------------------------------------------------
#define BQ 128
#define BKT 32

__global__ __launch_bounds__(256, 2) void flash_kernel(
    const float* __restrict__ Q, const float* __restrict__ Kg,
    const float* __restrict__ Vg, const float* __restrict__ bias,
    float* __restrict__ O)
{
    __shared__ float Ks[BKT][DEPTH];
    __shared__ float Vs[BKT][DEPTH];

    const int t    = threadIdx.x;
    const int row  = t >> 1;
    const int half = t & 1;
    const int h = blockIdx.y;
    const int b = blockIdx.z;
    const int qr = blockIdx.x * BQ + row;

    // This thread's half of the query row (8 float4 = 32 floats)
    const float* qptr = Q + ((size_t)(b * SEQ + qr)) * DMODEL + h * DEPTH + half * 32;
    float4 qv[8];
    #pragma unroll
    for (int i = 0; i < 8; i++) qv[i] = ((const float4*)qptr)[i];

    float4 o4[8];
    #pragma unroll
    for (int i = 0; i < 8; i++) o4[i] = make_float4(0.f, 0.f, 0.f, 0.f);
    float m = -CUDART_INF_F;
    float l = 0.0f;

    const float* biasrow = bias + (size_t)qr * SEQ;

    for (int kt = 0; kt < SEQ; kt += BKT) {
        // Cooperative coalesced load of K and V tiles (512 float4 each, 256 thr)
        #pragma unroll
        for (int i = 0; i < 2; i++) {
            int idx = t + i * 256;
            int r2  = idx >> 4;
            int col = idx & 15;
            const float* kbase = Kg + ((size_t)(b * SEQ + kt + r2)) * DMODEL + h * DEPTH;
            const float* vbase = Vg + ((size_t)(b * SEQ + kt + r2)) * DMODEL + h * DEPTH;
            ((float4*)&Ks[r2][0])[col] = ((const float4*)kbase)[col];
            ((float4*)&Vs[r2][0])[col] = ((const float4*)vbase)[col];
        }
        __syncthreads();

        // Scores: each thread computes half-dot; pair-combine via shfl
        float s[BKT];
        #pragma unroll 4
        for (int j = 0; j < BKT; j++) {
            float ax = 0.f, ay = 0.f, az = 0.f, aw = 0.f;
            const float4* krow = (const float4*)&Ks[j][0] + half * 8;
            #pragma unroll
            for (int i = 0; i < 8; i++) {
                float4 kv = krow[i];
                ax = fmaf(qv[i].x, kv.x, ax);
                ay = fmaf(qv[i].y, kv.y, ay);
                az = fmaf(qv[i].z, kv.z, az);
                aw = fmaf(qv[i].w, kv.w, aw);
            }
            float partial = (ax + ay) + (az + aw);
            s[j] = partial + __shfl_xor_sync(0xFFFFFFFFu, partial, 1);
        }

        // Bias + tile max
        float tmax = -CUDART_INF_F;
        #pragma unroll
        for (int jj = 0; jj < BKT / 4; jj++) {
            float4 bv = *(const float4*)(biasrow + kt + jj * 4);
            s[jj * 4 + 0] += bv.x;
            s[jj * 4 + 1] += bv.y;
            s[jj * 4 + 2] += bv.z;
            s[jj * 4 + 3] += bv.w;
            tmax = fmaxf(tmax, fmaxf(fmaxf(s[jj * 4 + 0], s[jj * 4 + 1]),
                                     fmaxf(s[jj * 4 + 2], s[jj * 4 + 3])));
        }

        // Online softmax rescale
        float newm = fmaxf(m, tmax);
        float corr = __expf(m - newm);
        l *= corr;
        #pragma unroll
        for (int i = 0; i < 8; i++) {
            o4[i].x *= corr; o4[i].y *= corr; o4[i].z *= corr; o4[i].w *= corr;
        }
        float lad = 0.f;
        #pragma unroll
        for (int j = 0; j < BKT; j++) {
            float p = __expf(s[j] - newm);
            lad += p;
            s[j] = p;
        }
        l += lad;
        m = newm;

        // O += p * V (this thread's half of V rows)
        #pragma unroll 4
        for (int j = 0; j < BKT; j++) {
            float p = s[j];
            const float4* vrow = (const float4*)&Vs[j][0] + half * 8;
            #pragma unroll
            for (int i = 0; i < 8; i++) {
                float4 vv = vrow[i];
                o4[i].x = fmaf(p, vv.x, o4[i].x);
                o4[i].y = fmaf(p, vv.y, o4[i].y);
                o4[i].z = fmaf(p, vv.z, o4[i].z);
                o4[i].w = fmaf(p, vv.w, o4[i].w);
            }
        }
        __syncthreads();
    }

    const float inv = 1.0f / l;
    float* optr = O + ((size_t)(b * SEQ + qr)) * DMODEL + h * DEPTH + half * 32;
    #pragma unroll
    for (int i = 0; i < 8; i++) {
        float4 ov;
        ov.x = o4[i].x * inv; ov.y = o4[i].y * inv;
        ov.z = o4[i].z * inv; ov.w = o4[i].w * inv;
        ((float4*)optr)[i] = ov;
    }
}

// ---------------------------------------------------------------------------
// Launch
// ---------------------------------------------------------------------------
extern "C" void kernel_launch(void* const* d_in, const int* in_sizes, int n_in,
                              void* d_out, int out_size)
{
    const float* x    = (const float*)d_in[0];
    const float* y    = (const float*)d_in[1];
    const float* bias = (const float*)d_in[2];
    const float* Wq   = (const float*)d_in[3];
    const float* Wk   = (const float*)d_in[4];
    const float* Wv   = (const float*)d_in[5];
    const float* Wo   = (const float*)d_in[6];
    float* out = (float*)d_out;

    float *q, *k, *v, *attn;
    cudaGetSymbolAddress((void**)&q,    g_q);
    cudaGetSymbolAddress((void**)&k,    g_k);
    cudaGetSymbolAddress((void**)&v,    g_v);
    cudaGetSymbolAddress((void**)&attn, g_attn);

    dim3 ggrid(DMODEL / GBN, MROWS / GBM);   // (8, 32)
    dim3 gblock(256);

    // q = (x @ Wq) * sqrt(depth) = * 8
    tf32_gemm_kernel<<<ggrid, gblock, 0, 0>>>(x, Wq, q, MROWS, DMODEL, DMODEL, 8.0f);
    tf32_gemm_kernel<<<ggrid, gblock, 0, 0>>>(y, Wk, k, MROWS, DMODEL, DMODEL, 1.0f);
    tf32_gemm_kernel<<<ggrid, gblock, 0, 0>>>(y, Wv, v, MROWS, DMODEL, DMODEL, 1.0f);

    dim3 fgrid(SEQ / BQ, NHEADS, BATCH);   // (16, 16, 2)
    flash_kernel<<<fgrid, 256, 0, 0>>>(q, k, v, bias, attn);

    tf32_gemm_kernel<<<ggrid, gblock, 0, 0>>>(attn, Wo, out, MROWS, DMODEL, DMODEL, 1.0f);
}

// round 5
// speedup vs baseline: 2.1289x; 2.1289x over previous
#include <cuda_runtime.h>
#include <math_constants.h>
#include <cstdint>

// Problem constants (fixed by the reference setup)
#define SEQ    2048
#define DMODEL 1024
#define NHEADS 16
#define DEPTH  64
#define BATCH  2
#define MROWS  (BATCH * SEQ)   // 4096

// Scratch (allocation-free rule: __device__ globals)
__device__ float g_q[MROWS * DMODEL];
__device__ float g_k[MROWS * DMODEL];
__device__ float g_v[MROWS * DMODEL];
__device__ float g_attn[MROWS * DMODEL];

// ---------------------------------------------------------------------------
// Helpers
// ---------------------------------------------------------------------------
__device__ __forceinline__ uint32_t f2tf32(float f) {
    uint32_t r;
    asm("cvt.rna.tf32.f32 %0, %1;" : "=r"(r) : "f"(f));
    return r;
}

__device__ __forceinline__ void mma_tf32(float* c, const uint32_t* a, const uint32_t* b) {
    asm volatile(
        "mma.sync.aligned.m16n8k8.row.col.f32.tf32.tf32.f32 "
        "{%0,%1,%2,%3}, {%4,%5,%6,%7}, {%8,%9}, {%0,%1,%2,%3};"
        : "+f"(c[0]), "+f"(c[1]), "+f"(c[2]), "+f"(c[3])
        : "r"(a[0]), "r"(a[1]), "r"(a[2]), "r"(a[3]), "r"(b[0]), "r"(b[1]));
}

// ---------------------------------------------------------------------------
// fp32 SGEMM (known good, R2): C[M,N] = alpha * A[M,K] @ B[K,N], row-major.
// ---------------------------------------------------------------------------
#define BM 128
#define BN 128
#define BKK 8

__global__ __launch_bounds__(256) void sgemm_kernel(
    const float* __restrict__ A, const float* __restrict__ B,
    float* __restrict__ C, int M, int N, int K, float alpha)
{
    __shared__ float As[BKK][BM];
    __shared__ float Bs[BKK][BN];

    const int tid = threadIdx.x;
    const int blockRow = blockIdx.y * BM;
    const int blockCol = blockIdx.x * BN;

    const int aRow = tid >> 1;
    const int aCol = (tid & 1) * 4;
    const int bRow = tid >> 5;
    const int bCol = (tid & 31) * 4;

    const int tRow = (tid >> 4) * 8;
    const int tCol = (tid & 15) * 8;

    float acc[8][8];
    #pragma unroll
    for (int i = 0; i < 8; i++)
        #pragma unroll
        for (int j = 0; j < 8; j++)
            acc[i][j] = 0.0f;

    for (int k0 = 0; k0 < K; k0 += BKK) {
        float4 a = *(const float4*)(A + (size_t)(blockRow + aRow) * K + k0 + aCol);
        As[aCol + 0][aRow] = a.x;
        As[aCol + 1][aRow] = a.y;
        As[aCol + 2][aRow] = a.z;
        As[aCol + 3][aRow] = a.w;
        float4 b = *(const float4*)(B + (size_t)(k0 + bRow) * N + blockCol + bCol);
        *(float4*)(&Bs[bRow][bCol]) = b;
        __syncthreads();

        #pragma unroll
        for (int k = 0; k < BKK; k++) {
            float ra[8], rb[8];
            *(float4*)(ra)     = *(const float4*)(&As[k][tRow]);
            *(float4*)(ra + 4) = *(const float4*)(&As[k][tRow + 4]);
            *(float4*)(rb)     = *(const float4*)(&Bs[k][tCol]);
            *(float4*)(rb + 4) = *(const float4*)(&Bs[k][tCol + 4]);
            #pragma unroll
            for (int i = 0; i < 8; i++)
                #pragma unroll
                for (int j = 0; j < 8; j++)
                    acc[i][j] = fmaf(ra[i], rb[j], acc[i][j]);
        }
        __syncthreads();
    }

    #pragma unroll
    for (int i = 0; i < 8; i++) {
        #pragma unroll
        for (int jj = 0; jj < 2; jj++) {
            float4 v;
            v.x = alpha * acc[i][jj * 4 + 0];
            v.y = alpha * acc[i][jj * 4 + 1];
            v.z = alpha * acc[i][jj * 4 + 2];
            v.w = alpha * acc[i][jj * 4 + 3];
            *(float4*)(C + (size_t)(blockRow + tRow + i) * N + blockCol + tCol + jj * 4) = v;
        }
    }
}

// ---------------------------------------------------------------------------
// Tensor-core flash attention.
// CTA: 128 q rows, 8 warps (m16 each). KV tile = 64 rows.
// QK^T: 3xTF32 (hi/lo split). PV: single-pass TF32.
// SMEM strides chosen conflict-free for the frag access patterns.
// ---------------------------------------------------------------------------
#define KT 64
#define KSTRIDE 76   // K tile row stride (uint32) — conflict-free B-frag loads
#define VSTRIDE 72   // V tile row stride — conflict-free B-frag loads
#define PSTRIDE 68   // P tile row stride — conflict-free A-frag loads

#define SM_KHI 0
#define SM_KLO (64 * KSTRIDE)                 // uint32 offsets
#define SM_V   (2 * 64 * KSTRIDE)
#define SM_P   (2 * 64 * KSTRIDE + 64 * VSTRIDE)
#define FLASH_SMEM_U32 (2 * 64 * KSTRIDE + 64 * VSTRIDE + 128 * PSTRIDE)
#define FLASH_SMEM_BYTES (FLASH_SMEM_U32 * 4)   // 92160

__global__ __launch_bounds__(256) void flash_mma_kernel(
    const float* __restrict__ Q, const float* __restrict__ Kg,
    const float* __restrict__ Vg, const float* __restrict__ bias,
    float* __restrict__ O)
{
    extern __shared__ uint32_t sm[];
    uint32_t* Khi = sm + SM_KHI;
    uint32_t* Klo = sm + SM_KLO;
    uint32_t* Vsm = sm + SM_V;
    uint32_t* Psm = sm + SM_P;

    const int tid  = threadIdx.x;
    const int lane = tid & 31;
    const int wid  = tid >> 5;
    const int g    = lane >> 2;   // 0..7
    const int tig  = lane & 3;    // 0..3

    const int h = blockIdx.y;
    const int b = blockIdx.z;
    const int qbase = blockIdx.x * 128;
    const int wrow  = wid * 16;          // warp's row offset within tile

    // --- Q fragments (hi/lo), rows wrow+g / wrow+g+8, 8 k-steps of 8 ---
    uint32_t qh[8][4], ql[8][4];
    {
        const float* qp = Q + ((size_t)(b * SEQ + qbase + wrow)) * DMODEL + h * DEPTH;
        #pragma unroll
        for (int ks = 0; ks < 8; ks++) {
            int c0 = ks * 8 + tig;
            float a0 = qp[(size_t)g * DMODEL + c0];
            float a1 = qp[(size_t)(g + 8) * DMODEL + c0];
            float a2 = qp[(size_t)g * DMODEL + c0 + 4];
            float a3 = qp[(size_t)(g + 8) * DMODEL + c0 + 4];
            qh[ks][0] = f2tf32(a0); ql[ks][0] = f2tf32(a0 - __uint_as_float(qh[ks][0]));
            qh[ks][1] = f2tf32(a1); ql[ks][1] = f2tf32(a1 - __uint_as_float(qh[ks][1]));
            qh[ks][2] = f2tf32(a2); ql[ks][2] = f2tf32(a2 - __uint_as_float(qh[ks][2]));
            qh[ks][3] = f2tf32(a3); ql[ks][3] = f2tf32(a3 - __uint_as_float(qh[ks][3]));
        }
    }

    float o[8][4];
    #pragma unroll
    for (int nf = 0; nf < 8; nf++)
        #pragma unroll
        for (int r = 0; r < 4; r++) o[nf][r] = 0.0f;
    float m0 = -CUDART_INF_F, m1 = -CUDART_INF_F, l0 = 0.f, l1 = 0.f;

    const float* bp0 = bias + (size_t)(qbase + wrow + g) * SEQ;
    const float* bp8 = bias + (size_t)(qbase + wrow + g + 8) * SEQ;

    for (int kt = 0; kt < SEQ; kt += KT) {
        // --- cooperative K/V tile load: 64 rows x 64 cols each ---
        #pragma unroll
        for (int j = 0; j < 4; j++) {
            int idx = tid + j * 256;          // 0..1023 float4 slots
            int row = idx >> 4;               // 16 f4 per row
            int c   = (idx & 15) * 4;
            const float* kp = Kg + ((size_t)(b * SEQ + kt + row)) * DMODEL + h * DEPTH + c;
            const float* vp = Vg + ((size_t)(b * SEQ + kt + row)) * DMODEL + h * DEPTH + c;
            float4 kv4 = *(const float4*)kp;
            float4 vv4 = *(const float4*)vp;
            float ke[4] = {kv4.x, kv4.y, kv4.z, kv4.w};
            uint32_t hi[4], lo[4], vv[4];
            #pragma unroll
            for (int i = 0; i < 4; i++) {
                hi[i] = f2tf32(ke[i]);
                lo[i] = f2tf32(ke[i] - __uint_as_float(hi[i]));
            }
            vv[0] = f2tf32(vv4.x); vv[1] = f2tf32(vv4.y);
            vv[2] = f2tf32(vv4.z); vv[3] = f2tf32(vv4.w);
            *(uint4*)(Khi + row * KSTRIDE + c) = make_uint4(hi[0], hi[1], hi[2], hi[3]);
            *(uint4*)(Klo + row * KSTRIDE + c) = make_uint4(lo[0], lo[1], lo[2], lo[3]);
            *(uint4*)(Vsm + row * VSTRIDE + c) = make_uint4(vv[0], vv[1], vv[2], vv[3]);
        }
        __syncthreads();

        // --- S = Q @ K^T (3xTF32) ---
        float s[8][4];
        #pragma unroll
        for (int nf = 0; nf < 8; nf++)
            #pragma unroll
            for (int r = 0; r < 4; r++) s[nf][r] = 0.0f;

        #pragma unroll
        for (int ks = 0; ks < 8; ks++) {
            #pragma unroll
            for (int nf = 0; nf < 8; nf++) {
                const int kr = (nf * 8 + g) * KSTRIDE + ks * 8 + tig;
                uint32_t bh[2], bl[2];
                bh[0] = Khi[kr];     bh[1] = Khi[kr + 4];
                bl[0] = Klo[kr];     bl[1] = Klo[kr + 4];
                mma_tf32(s[nf], qh[ks], bh);
                mma_tf32(s[nf], qh[ks], bl);
                mma_tf32(s[nf], ql[ks], bh);
            }
        }

        // --- bias + row max ---
        float mx0 = -CUDART_INF_F, mx1 = -CUDART_INF_F;
        #pragma unroll
        for (int nf = 0; nf < 8; nf++) {
            float2 b0 = *(const float2*)(bp0 + kt + nf * 8 + tig * 2);
            float2 b1 = *(const float2*)(bp8 + kt + nf * 8 + tig * 2);
            s[nf][0] += b0.x; s[nf][1] += b0.y;
            s[nf][2] += b1.x; s[nf][3] += b1.y;
            mx0 = fmaxf(mx0, fmaxf(s[nf][0], s[nf][1]));
            mx1 = fmaxf(mx1, fmaxf(s[nf][2], s[nf][3]));
        }
        mx0 = fmaxf(mx0, __shfl_xor_sync(0xFFFFFFFFu, mx0, 1));
        mx0 = fmaxf(mx0, __shfl_xor_sync(0xFFFFFFFFu, mx0, 2));
        mx1 = fmaxf(mx1, __shfl_xor_sync(0xFFFFFFFFu, mx1, 1));
        mx1 = fmaxf(mx1, __shfl_xor_sync(0xFFFFFFFFu, mx1, 2));

        // --- online softmax ---
        float nm0 = fmaxf(m0, mx0), nm1 = fmaxf(m1, mx1);
        float c0 = __expf(m0 - nm0), c1 = __expf(m1 - nm1);
        l0 *= c0; l1 *= c1; m0 = nm0; m1 = nm1;
        #pragma unroll
        for (int nf = 0; nf < 8; nf++) {
            o[nf][0] *= c0; o[nf][1] *= c0; o[nf][2] *= c1; o[nf][3] *= c1;
        }
        float la0 = 0.f, la1 = 0.f;
        #pragma unroll
        for (int nf = 0; nf < 8; nf++) {
            float p0 = __expf(s[nf][0] - nm0);
            float p1 = __expf(s[nf][1] - nm0);
            float p2 = __expf(s[nf][2] - nm1);
            float p3 = __expf(s[nf][3] - nm1);
            la0 += p0 + p1; la1 += p2 + p3;
            const int pr0 = (wrow + g) * PSTRIDE + nf * 8 + tig * 2;
            const int pr8 = (wrow + g + 8) * PSTRIDE + nf * 8 + tig * 2;
            Psm[pr0] = f2tf32(p0); Psm[pr0 + 1] = f2tf32(p1);
            Psm[pr8] = f2tf32(p2); Psm[pr8 + 1] = f2tf32(p3);
        }
        la0 += __shfl_xor_sync(0xFFFFFFFFu, la0, 1);
        la0 += __shfl_xor_sync(0xFFFFFFFFu, la0, 2);
        la1 += __shfl_xor_sync(0xFFFFFFFFu, la1, 1);
        la1 += __shfl_xor_sync(0xFFFFFFFFu, la1, 2);
        l0 += la0; l1 += la1;
        __syncwarp();

        // --- O += P @ V (single-pass TF32); P slice is warp-private ---
        #pragma unroll
        for (int ks = 0; ks < 8; ks++) {
            uint32_t a[4];
            a[0] = Psm[(wrow + g) * PSTRIDE + ks * 8 + tig];
            a[1] = Psm[(wrow + g + 8) * PSTRIDE + ks * 8 + tig];
            a[2] = Psm[(wrow + g) * PSTRIDE + ks * 8 + tig + 4];
            a[3] = Psm[(wrow + g + 8) * PSTRIDE + ks * 8 + tig + 4];
            #pragma unroll
            for (int nf = 0; nf < 8; nf++) {
                uint32_t bb[2];
                bb[0] = Vsm[(ks * 8 + tig) * VSTRIDE + nf * 8 + g];
                bb[1] = Vsm[(ks * 8 + tig + 4) * VSTRIDE + nf * 8 + g];
                mma_tf32(o[nf], a, bb);
            }
        }
        __syncthreads();   // protect K/V/P before next tile's stores
    }

    // --- epilogue ---
    const float inv0 = 1.0f / l0, inv1 = 1.0f / l1;
    float* op0 = O + ((size_t)(b * SEQ + qbase + wrow + g)) * DMODEL + h * DEPTH;
    float* op8 = op0 + (size_t)8 * DMODEL;
    #pragma unroll
    for (int nf = 0; nf < 8; nf++) {
        *(float2*)(op0 + nf * 8 + tig * 2) = make_float2(o[nf][0] * inv0, o[nf][1] * inv0);
        *(float2*)(op8 + nf * 8 + tig * 2) = make_float2(o[nf][2] * inv1, o[nf][3] * inv1);
    }
}

// ---------------------------------------------------------------------------
// Launch
// ---------------------------------------------------------------------------
extern "C" void kernel_launch(void* const* d_in, const int* in_sizes, int n_in,
                              void* d_out, int out_size)
{
    const float* x    = (const float*)d_in[0];
    const float* y    = (const float*)d_in[1];
    const float* bias = (const float*)d_in[2];
    const float* Wq   = (const float*)d_in[3];
    const float* Wk   = (const float*)d_in[4];
    const float* Wv   = (const float*)d_in[5];
    const float* Wo   = (const float*)d_in[6];
    float* out = (float*)d_out;

    float *q, *k, *v, *attn;
    cudaGetSymbolAddress((void**)&q,    g_q);
    cudaGetSymbolAddress((void**)&k,    g_k);
    cudaGetSymbolAddress((void**)&v,    g_v);
    cudaGetSymbolAddress((void**)&attn, g_attn);

    cudaFuncSetAttribute(flash_mma_kernel,
                         cudaFuncAttributeMaxDynamicSharedMemorySize, FLASH_SMEM_BYTES);

    dim3 ggrid(DMODEL / BN, MROWS / BM);   // (8, 32)
    dim3 gblock(256);

    // q = (x @ Wq) * sqrt(depth) = * 8
    sgemm_kernel<<<ggrid, gblock, 0, 0>>>(x, Wq, q, MROWS, DMODEL, DMODEL, 8.0f);
    sgemm_kernel<<<ggrid, gblock, 0, 0>>>(y, Wk, k, MROWS, DMODEL, DMODEL, 1.0f);
    sgemm_kernel<<<ggrid, gblock, 0, 0>>>(y, Wv, v, MROWS, DMODEL, DMODEL, 1.0f);

    dim3 fgrid(SEQ / 128, NHEADS, BATCH);  // (16, 16, 2)
    flash_mma_kernel<<<fgrid, 256, FLASH_SMEM_BYTES, 0>>>(q, k, v, bias, attn);

    sgemm_kernel<<<ggrid, gblock, 0, 0>>>(attn, Wo, out, MROWS, DMODEL, DMODEL, 1.0f);
}

// round 7
// speedup vs baseline: 3.0541x; 1.4346x over previous
#include <cuda_runtime.h>
#include <cuda_bf16.h>
#include <math_constants.h>
#include <cstdint>

// Problem constants (fixed by the reference setup)
#define SEQ    2048
#define DMODEL 1024
#define NHEADS 16
#define DEPTH  64
#define BATCH  2
#define MROWS  (BATCH * SEQ)   // 4096

// Scratch (allocation-free rule: __device__ globals)
__device__ float g_q[MROWS * DMODEL];
__device__ float g_k[MROWS * DMODEL];
__device__ float g_v[MROWS * DMODEL];
__device__ float g_attn[MROWS * DMODEL];
// bf16 hi/lo splits
__device__ __nv_bfloat16 g_ah[MROWS * DMODEL];   // x, later attn
__device__ __nv_bfloat16 g_al[MROWS * DMODEL];
__device__ __nv_bfloat16 g_yh[MROWS * DMODEL];
__device__ __nv_bfloat16 g_yl[MROWS * DMODEL];
__device__ __nv_bfloat16 g_wqh[DMODEL * DMODEL];
__device__ __nv_bfloat16 g_wql[DMODEL * DMODEL];
__device__ __nv_bfloat16 g_wkh[DMODEL * DMODEL];
__device__ __nv_bfloat16 g_wkl[DMODEL * DMODEL];
__device__ __nv_bfloat16 g_wvh[DMODEL * DMODEL];
__device__ __nv_bfloat16 g_wvl[DMODEL * DMODEL];
__device__ __nv_bfloat16 g_woh[DMODEL * DMODEL];
__device__ __nv_bfloat16 g_wol[DMODEL * DMODEL];

// ---------------------------------------------------------------------------
// Helpers
// ---------------------------------------------------------------------------
__device__ __forceinline__ uint32_t f2tf32(float f) {
    uint32_t r;
    asm("cvt.rna.tf32.f32 %0, %1;" : "=r"(r) : "f"(f));
    return r;
}

__device__ __forceinline__ void mma_tf32(float* c, const uint32_t* a, const uint32_t* b) {
    asm volatile(
        "mma.sync.aligned.m16n8k8.row.col.f32.tf32.tf32.f32 "
        "{%0,%1,%2,%3}, {%4,%5,%6,%7}, {%8,%9}, {%0,%1,%2,%3};"
        : "+f"(c[0]), "+f"(c[1]), "+f"(c[2]), "+f"(c[3])
        : "r"(a[0]), "r"(a[1]), "r"(a[2]), "r"(a[3]), "r"(b[0]), "r"(b[1]));
}

__device__ __forceinline__ void mma_bf16(float* c, const uint32_t* a, const uint32_t* b) {
    asm volatile(
        "mma.sync.aligned.m16n8k16.row.col.f32.bf16.bf16.f32 "
        "{%0,%1,%2,%3}, {%4,%5,%6,%7}, {%8,%9}, {%0,%1,%2,%3};"
        : "+f"(c[0]), "+f"(c[1]), "+f"(c[2]), "+f"(c[3])
        : "r"(a[0]), "r"(a[1]), "r"(a[2]), "r"(a[3]), "r"(b[0]), "r"(b[1]));
}

// ---------------------------------------------------------------------------
// Prep: elementwise hi/lo bf16 split (row-major, n4 float4 elements)
// ---------------------------------------------------------------------------
__global__ __launch_bounds__(256) void split_kernel(
    const float* __restrict__ in, __nv_bfloat16* __restrict__ oh,
    __nv_bfloat16* __restrict__ ol, int n4)
{
    int i = blockIdx.x * blockDim.x + threadIdx.x;
    if (i >= n4) return;
    float4 v = ((const float4*)in)[i];
    __nv_bfloat16 h0 = __float2bfloat16(v.x);
    __nv_bfloat16 h1 = __float2bfloat16(v.y);
    __nv_bfloat16 h2 = __float2bfloat16(v.z);
    __nv_bfloat16 h3 = __float2bfloat16(v.w);
    __nv_bfloat16 l0 = __float2bfloat16(v.x - __bfloat162float(h0));
    __nv_bfloat16 l1 = __float2bfloat16(v.y - __bfloat162float(h1));
    __nv_bfloat16 l2 = __float2bfloat16(v.z - __bfloat162float(h2));
    __nv_bfloat16 l3 = __float2bfloat16(v.w - __bfloat162float(h3));
    __nv_bfloat162* ph = (__nv_bfloat162*)oh;
    __nv_bfloat162* pl = (__nv_bfloat162*)ol;
    ph[i * 2 + 0] = __nv_bfloat162(h0, h1);
    ph[i * 2 + 1] = __nv_bfloat162(h2, h3);
    pl[i * 2 + 0] = __nv_bfloat162(l0, l1);
    pl[i * 2 + 1] = __nv_bfloat162(l2, l3);
}

// ---------------------------------------------------------------------------
// Prep: weight transpose + split. out[n][k] = split(in[k][n]), 1024x1024.
// ---------------------------------------------------------------------------
__global__ __launch_bounds__(256) void tsplit_kernel(
    const float* __restrict__ in, __nv_bfloat16* __restrict__ oh,
    __nv_bfloat16* __restrict__ ol)
{
    __shared__ float tile[32][33];
    int x = blockIdx.x * 32 + threadIdx.x;
    int y = blockIdx.y * 32 + threadIdx.y;
    #pragma unroll
    for (int j = 0; j < 32; j += 8)
        tile[threadIdx.y + j][threadIdx.x] = in[(size_t)(y + j) * DMODEL + x];
    __syncthreads();
    x = blockIdx.y * 32 + threadIdx.x;   // k index in output
    y = blockIdx.x * 32 + threadIdx.y;   // n index in output
    #pragma unroll
    for (int j = 0; j < 32; j += 8) {
        float v = tile[threadIdx.x][threadIdx.y + j];
        __nv_bfloat16 h = __float2bfloat16(v);
        __nv_bfloat16 l = __float2bfloat16(v - __bfloat162float(h));
        oh[(size_t)(y + j) * DMODEL + x] = h;
        ol[(size_t)(y + j) * DMODEL + x] = l;
    }
}

// ---------------------------------------------------------------------------
// 3-term bf16 tensor-core GEMM: C[4096,1024] = alpha * A @ Bt^T
// A given as (Ah, Al) bf16 [M][K]; Bt as (Bh, Bl) bf16 [N][K] (pre-transposed).
// CTA tile 128x128, K chunk 32, 8 warps, warp tile 32x64. Single-buffer SMEM,
// 2 CTAs/SM. SMEM row stride 56 bf16 (112B) => conflict-free frag loads.
// ---------------------------------------------------------------------------
#define GSTRIDE 56
#define GTILE_B (128 * GSTRIDE * 2)            // 14336 bytes per tile
#define GEMM_SMEM (4 * GTILE_B)                // 57344

__global__ __launch_bounds__(256, 2) void bf16_gemm_kernel(
    const __nv_bfloat16* __restrict__ Ah, const __nv_bfloat16* __restrict__ Al,
    const __nv_bfloat16* __restrict__ Bh, const __nv_bfloat16* __restrict__ Bl,
    float* __restrict__ C, float alpha)
{
    extern __shared__ __align__(16) char gsm[];
    uint16_t* sAh = (uint16_t*)gsm;
    uint16_t* sAl = (uint16_t*)(gsm + GTILE_B);
    uint16_t* sBh = (uint16_t*)(gsm + 2 * GTILE_B);
    uint16_t* sBl = (uint16_t*)(gsm + 3 * GTILE_B);

    const int tid  = threadIdx.x;
    const int lane = tid & 31;
    const int wid  = tid >> 5;
    const int g    = lane >> 2;
    const int tig  = lane & 3;
    const int warp_m = wid & 3;    // 4 x 32 rows
    const int warp_n = wid >> 2;   // 2 x 64 cols
    const int wrow = warp_m * 32;
    const int wcol = warp_n * 64;

    const int blockRow = blockIdx.y * 128;
    const int blockCol = blockIdx.x * 128;
    const int K = DMODEL;

    float acc[2][8][4];
    #pragma unroll
    for (int mu = 0; mu < 2; mu++)
        #pragma unroll
        for (int nf = 0; nf < 8; nf++)
            #pragma unroll
            for (int r = 0; r < 4; r++) acc[mu][nf][r] = 0.0f;

    for (int k0 = 0; k0 < K; k0 += 32) {
        // ---- load 4 tiles (Ah, Al, Bh, Bl), each 128x32 bf16 ----
        #pragma unroll
        for (int j = 0; j < 2; j++) {
            int idx = tid + j * 256;           // 0..511
            int row = idx >> 2;
            int seg = idx & 3;                 // 8 bf16 per seg
            size_t goff = (size_t)(blockRow + row) * K + k0 + seg * 8;
            *(uint4*)&sAh[row * GSTRIDE + seg * 8] = *(const uint4*)(Ah + goff);
            *(uint4*)&sAl[row * GSTRIDE + seg * 8] = *(const uint4*)(Al + goff);
            size_t boff = (size_t)(blockCol + row) * K + k0 + seg * 8;
            *(uint4*)&sBh[row * GSTRIDE + seg * 8] = *(const uint4*)(Bh + boff);
            *(uint4*)&sBl[row * GSTRIDE + seg * 8] = *(const uint4*)(Bl + boff);
        }
        __syncthreads();

        // ---- 2 k16 steps ----
        #pragma unroll
        for (int ks = 0; ks < 2; ks++) {
            const int kb = ks * 16;
            uint32_t ah[2][4], al[2][4];
            #pragma unroll
            for (int mu = 0; mu < 2; mu++) {
                const int ra = (wrow + mu * 16 + g) * GSTRIDE + kb + 2 * tig;
                const int rb = (wrow + mu * 16 + g + 8) * GSTRIDE + kb + 2 * tig;
                ah[mu][0] = *(const uint32_t*)&sAh[ra];
                ah[mu][1] = *(const uint32_t*)&sAh[rb];
                ah[mu][2] = *(const uint32_t*)&sAh[ra + 8];
                ah[mu][3] = *(const uint32_t*)&sAh[rb + 8];
                al[mu][0] = *(const uint32_t*)&sAl[ra];
                al[mu][1] = *(const uint32_t*)&sAl[rb];
                al[mu][2] = *(const uint32_t*)&sAl[ra + 8];
                al[mu][3] = *(const uint32_t*)&sAl[rb + 8];
            }
            #pragma unroll
            for (int nf = 0; nf < 8; nf++) {
                const int rn = (wcol + nf * 8 + g) * GSTRIDE + kb + 2 * tig;
                uint32_t bh[2], bl[2];
                bh[0] = *(const uint32_t*)&sBh[rn];
                bh[1] = *(const uint32_t*)&sBh[rn + 8];
                bl[0] = *(const uint32_t*)&sBl[rn];
                bl[1] = *(const uint32_t*)&sBl[rn + 8];
                #pragma unroll
                for (int mu = 0; mu < 2; mu++) {
                    mma_bf16(acc[mu][nf], ah[mu], bh);
                    mma_bf16(acc[mu][nf], al[mu], bh);
                    mma_bf16(acc[mu][nf], ah[mu], bl);
                }
            }
        }
        __syncthreads();
    }

    // ---- epilogue ----
    #pragma unroll
    for (int mu = 0; mu < 2; mu++) {
        #pragma unroll
        for (int nf = 0; nf < 8; nf++) {
            int row0 = blockRow + wrow + mu * 16 + g;
            int col  = blockCol + wcol + nf * 8 + tig * 2;
            *(float2*)(C + (size_t)row0 * DMODEL + col) =
                make_float2(alpha * acc[mu][nf][0], alpha * acc[mu][nf][1]);
            *(float2*)(C + (size_t)(row0 + 8) * DMODEL + col) =
                make_float2(alpha * acc[mu][nf][2], alpha * acc[mu][nf][3]);
        }
    }
}

// ---------------------------------------------------------------------------
// Tensor-core flash attention (R5, known good).
// QK^T: 3xTF32. PV: single-pass TF32. Online softmax on fragments.
// ---------------------------------------------------------------------------
#define KT 64
#define KSTRIDE 76
#define VSTRIDE 72
#define PSTRIDE 68

#define SM_KHI 0
#define SM_KLO (64 * KSTRIDE)
#define SM_V   (2 * 64 * KSTRIDE)
#define SM_P   (2 * 64 * KSTRIDE + 64 * VSTRIDE)
#define FLASH_SMEM_U32 (2 * 64 * KSTRIDE + 64 * VSTRIDE + 128 * PSTRIDE)
#define FLASH_SMEM_BYTES (FLASH_SMEM_U32 * 4)

__global__ __launch_bounds__(256) void flash_mma_kernel(
    const float* __restrict__ Q, const float* __restrict__ Kg,
    const float* __restrict__ Vg, const float* __restrict__ bias,
    float* __restrict__ O)
{
    extern __shared__ uint32_t sm[];
    uint32_t* Khi = sm + SM_KHI;
    uint32_t* Klo = sm + SM_KLO;
    uint32_t* Vsm = sm + SM_V;
    uint32_t* Psm = sm + SM_P;

    const int tid  = threadIdx.x;
    const int lane = tid & 31;
    const int wid  = tid >> 5;
    const int g    = lane >> 2;
    const int tig  = lane & 3;

    const int h = blockIdx.y;
    const int b = blockIdx.z;
    const int qbase = blockIdx.x * 128;
    const int wrow  = wid * 16;

    uint32_t qh[8][4], ql[8][4];
    {
        const float* qp = Q + ((size_t)(b * SEQ + qbase + wrow)) * DMODEL + h * DEPTH;
        #pragma unroll
        for (int ks = 0; ks < 8; ks++) {
            int c0 = ks * 8 + tig;
            float a0 = qp[(size_t)g * DMODEL + c0];
            float a1 = qp[(size_t)(g + 8) * DMODEL + c0];
            float a2 = qp[(size_t)g * DMODEL + c0 + 4];
            float a3 = qp[(size_t)(g + 8) * DMODEL + c0 + 4];
            qh[ks][0] = f2tf32(a0); ql[ks][0] = f2tf32(a0 - __uint_as_float(qh[ks][0]));
            qh[ks][1] = f2tf32(a1); ql[ks][1] = f2tf32(a1 - __uint_as_float(qh[ks][1]));
            qh[ks][2] = f2tf32(a2); ql[ks][2] = f2tf32(a2 - __uint_as_float(qh[ks][2]));
            qh[ks][3] = f2tf32(a3); ql[ks][3] = f2tf32(a3 - __uint_as_float(qh[ks][3]));
        }
    }

    float o[8][4];
    #pragma unroll
    for (int nf = 0; nf < 8; nf++)
        #pragma unroll
        for (int r = 0; r < 4; r++) o[nf][r] = 0.0f;
    float m0 = -CUDART_INF_F, m1 = -CUDART_INF_F, l0 = 0.f, l1 = 0.f;

    const float* bp0 = bias + (size_t)(qbase + wrow + g) * SEQ;
    const float* bp8 = bias + (size_t)(qbase + wrow + g + 8) * SEQ;

    for (int kt = 0; kt < SEQ; kt += KT) {
        #pragma unroll
        for (int j = 0; j < 4; j++) {
            int idx = tid + j * 256;
            int row = idx >> 4;
            int c   = (idx & 15) * 4;
            const float* kp = Kg + ((size_t)(b * SEQ + kt + row)) * DMODEL + h * DEPTH + c;
            const float* vp = Vg + ((size_t)(b * SEQ + kt + row)) * DMODEL + h * DEPTH + c;
            float4 kv4 = *(const float4*)kp;
            float4 vv4 = *(const float4*)vp;
            float ke[4] = {kv4.x, kv4.y, kv4.z, kv4.w};
            uint32_t hi[4], lo[4], vv[4];
            #pragma unroll
            for (int i = 0; i < 4; i++) {
                hi[i] = f2tf32(ke[i]);
                lo[i] = f2tf32(ke[i] - __uint_as_float(hi[i]));
            }
            vv[0] = f2tf32(vv4.x); vv[1] = f2tf32(vv4.y);
            vv[2] = f2tf32(vv4.z); vv[3] = f2tf32(vv4.w);
            *(uint4*)(Khi + row * KSTRIDE + c) = make_uint4(hi[0], hi[1], hi[2], hi[3]);
            *(uint4*)(Klo + row * KSTRIDE + c) = make_uint4(lo[0], lo[1], lo[2], lo[3]);
            *(uint4*)(Vsm + row * VSTRIDE + c) = make_uint4(vv[0], vv[1], vv[2], vv[3]);
        }
        __syncthreads();

        float s[8][4];
        #pragma unroll
        for (int nf = 0; nf < 8; nf++)
            #pragma unroll
            for (int r = 0; r < 4; r++) s[nf][r] = 0.0f;

        #pragma unroll
        for (int ks = 0; ks < 8; ks++) {
            #pragma unroll
            for (int nf = 0; nf < 8; nf++) {
                const int kr = (nf * 8 + g) * KSTRIDE + ks * 8 + tig;
                uint32_t bh[2], bl[2];
                bh[0] = Khi[kr];     bh[1] = Khi[kr + 4];
                bl[0] = Klo[kr];     bl[1] = Klo[kr + 4];
                mma_tf32(s[nf], qh[ks], bh);
                mma_tf32(s[nf], qh[ks], bl);
                mma_tf32(s[nf], ql[ks], bh);
            }
        }

        float mx0 = -CUDART_INF_F, mx1 = -CUDART_INF_F;
        #pragma unroll
        for (int nf = 0; nf < 8; nf++) {
            float2 b0 = *(const float2*)(bp0 + kt + nf * 8 + tig * 2);
            float2 b1 = *(const float2*)(bp8 + kt + nf * 8 + tig * 2);
            s[nf][0] += b0.x; s[nf][1] += b0.y;
            s[nf][2] += b1.x; s[nf][3] += b1.y;
            mx0 = fmaxf(mx0, fmaxf(s[nf][0], s[nf][1]));
            mx1 = fmaxf(mx1, fmaxf(s[nf][2], s[nf][3]));
        }
        mx0 = fmaxf(mx0, __shfl_xor_sync(0xFFFFFFFFu, mx0, 1));
        mx0 = fmaxf(mx0, __shfl_xor_sync(0xFFFFFFFFu, mx0, 2));
        mx1 = fmaxf(mx1, __shfl_xor_sync(0xFFFFFFFFu, mx1, 1));
        mx1 = fmaxf(mx1, __shfl_xor_sync(0xFFFFFFFFu, mx1, 2));

        float nm0 = fmaxf(m0, mx0), nm1 = fmaxf(m1, mx1);
        float c0 = __expf(m0 - nm0), c1 = __expf(m1 - nm1);
        l0 *= c0; l1 *= c1; m0 = nm0; m1 = nm1;
        #pragma unroll
        for (int nf = 0; nf < 8; nf++) {
            o[nf][0] *= c0; o[nf][1] *= c0; o[nf][2] *= c1; o[nf][3] *= c1;
        }
        float la0 = 0.f, la1 = 0.f;
        #pragma unroll
        for (int nf = 0; nf < 8; nf++) {
            float p0 = __expf(s[nf][0] - nm0);
            float p1 = __expf(s[nf][1] - nm0);
            float p2 = __expf(s[nf][2] - nm1);
            float p3 = __expf(s[nf][3] - nm1);
            la0 += p0 + p1; la1 += p2 + p3;
            const int pr0 = (wrow + g) * PSTRIDE + nf * 8 + tig * 2;
            const int pr8 = (wrow + g + 8) * PSTRIDE + nf * 8 + tig * 2;
            Psm[pr0] = f2tf32(p0); Psm[pr0 + 1] = f2tf32(p1);
            Psm[pr8] = f2tf32(p2); Psm[pr8 + 1] = f2tf32(p3);
        }
        la0 += __shfl_xor_sync(0xFFFFFFFFu, la0, 1);
        la0 += __shfl_xor_sync(0xFFFFFFFFu, la0, 2);
        la1 += __shfl_xor_sync(0xFFFFFFFFu, la1, 1);
        la1 += __shfl_xor_sync(0xFFFFFFFFu, la1, 2);
        l0 += la0; l1 += la1;
        __syncwarp();

        #pragma unroll
        for (int ks = 0; ks < 8; ks++) {
            uint32_t a[4];
            a[0] = Psm[(wrow + g) * PSTRIDE + ks * 8 + tig];
            a[1] = Psm[(wrow + g + 8) * PSTRIDE + ks * 8 + tig];
            a[2] = Psm[(wrow + g) * PSTRIDE + ks * 8 + tig + 4];
            a[3] = Psm[(wrow + g + 8) * PSTRIDE + ks * 8 + tig + 4];
            #pragma unroll
            for (int nf = 0; nf < 8; nf++) {
                uint32_t bb[2];
                bb[0] = Vsm[(ks * 8 + tig) * VSTRIDE + nf * 8 + g];
                bb[1] = Vsm[(ks * 8 + tig + 4) * VSTRIDE + nf * 8 + g];
                mma_tf32(o[nf], a, bb);
            }
        }
        __syncthreads();
    }

    const float inv0 = 1.0f / l0, inv1 = 1.0f / l1;
    float* op0 = O + ((size_t)(b * SEQ + qbase + wrow + g)) * DMODEL + h * DEPTH;
    float* op8 = op0 + (size_t)8 * DMODEL;
    #pragma unroll
    for (int nf = 0; nf < 8; nf++) {
        *(float2*)(op0 + nf * 8 + tig * 2) = make_float2(o[nf][0] * inv0, o[nf][1] * inv0);
        *(float2*)(op8 + nf * 8 + tig * 2) = make_float2(o[nf][2] * inv1, o[nf][3] * inv1);
    }
}

// ---------------------------------------------------------------------------
// Launch
// ---------------------------------------------------------------------------
extern "C" void kernel_launch(void* const* d_in, const int* in_sizes, int n_in,
                              void* d_out, int out_size)
{
    const float* x    = (const float*)d_in[0];
    const float* y    = (const float*)d_in[1];
    const float* bias = (const float*)d_in[2];
    const float* Wq   = (const float*)d_in[3];
    const float* Wk   = (const float*)d_in[4];
    const float* Wv   = (const float*)d_in[5];
    const float* Wo   = (const float*)d_in[6];
    float* out = (float*)d_out;

    float *q, *k, *v, *attn;
    __nv_bfloat16 *ah, *al, *yh, *yl, *wqh, *wql, *wkh, *wkl, *wvh, *wvl, *woh, *wol;
    cudaGetSymbolAddress((void**)&q,    g_q);
    cudaGetSymbolAddress((void**)&k,    g_k);
    cudaGetSymbolAddress((void**)&v,    g_v);
    cudaGetSymbolAddress((void**)&attn, g_attn);
    cudaGetSymbolAddress((void**)&ah,   g_ah);
    cudaGetSymbolAddress((void**)&al,   g_al);
    cudaGetSymbolAddress((void**)&yh,   g_yh);
    cudaGetSymbolAddress((void**)&yl,   g_yl);
    cudaGetSymbolAddress((void**)&wqh,  g_wqh);
    cudaGetSymbolAddress((void**)&wql,  g_wql);
    cudaGetSymbolAddress((void**)&wkh,  g_wkh);
    cudaGetSymbolAddress((void**)&wkl,  g_wkl);
    cudaGetSymbolAddress((void**)&wvh,  g_wvh);
    cudaGetSymbolAddress((void**)&wvl,  g_wvl);
    cudaGetSymbolAddress((void**)&woh,  g_woh);
    cudaGetSymbolAddress((void**)&wol,  g_wol);

    cudaFuncSetAttribute(flash_mma_kernel,
                         cudaFuncAttributeMaxDynamicSharedMemorySize, FLASH_SMEM_BYTES);
    cudaFuncSetAttribute(bf16_gemm_kernel,
                         cudaFuncAttributeMaxDynamicSharedMemorySize, GEMM_SMEM);

    const int n4 = MROWS * DMODEL / 4;
    dim3 sgrid((n4 + 255) / 256);
    split_kernel<<<sgrid, 256, 0, 0>>>(x, ah, al, n4);
    split_kernel<<<sgrid, 256, 0, 0>>>(y, yh, yl, n4);

    dim3 tgrid(32, 32), tblock(32, 8);
    tsplit_kernel<<<tgrid, tblock, 0, 0>>>(Wq, wqh, wql);
    tsplit_kernel<<<tgrid, tblock, 0, 0>>>(Wk, wkh, wkl);
    tsplit_kernel<<<tgrid, tblock, 0, 0>>>(Wv, wvh, wvl);
    tsplit_kernel<<<tgrid, tblock, 0, 0>>>(Wo, woh, wol);

    dim3 ggrid(DMODEL / 128, MROWS / 128);   // (8, 32)

    // q = (x @ Wq) * sqrt(depth) = * 8
    bf16_gemm_kernel<<<ggrid, 256, GEMM_SMEM, 0>>>(ah, al, wqh, wql, q, 8.0f);
    bf16_gemm_kernel<<<ggrid, 256, GEMM_SMEM, 0>>>(yh, yl, wkh, wkl, k, 1.0f);
    bf16_gemm_kernel<<<ggrid, 256, GEMM_SMEM, 0>>>(yh, yl, wvh, wvl, v, 1.0f);

    dim3 fgrid(SEQ / 128, NHEADS, BATCH);    // (16, 16, 2)
    flash_mma_kernel<<<fgrid, 256, FLASH_SMEM_BYTES, 0>>>(q, k, v, bias, attn);

    split_kernel<<<sgrid, 256, 0, 0>>>(attn, ah, al, n4);
    bf16_gemm_kernel<<<ggrid, 256, GEMM_SMEM, 0>>>(ah, al, woh, wol, out, 1.0f);
}

// round 8
// speedup vs baseline: 3.3248x; 1.0886x over previous
#include <cuda_runtime.h>
#include <cuda_bf16.h>
#include <math_constants.h>
#include <cstdint>

// Problem constants (fixed by the reference setup)
#define SEQ    2048
#define DMODEL 1024
#define NHEADS 16
#define DEPTH  64
#define BATCH  2
#define MROWS  (BATCH * SEQ)   // 4096

// Scratch (allocation-free rule: __device__ globals). All bf16 hi/lo pairs.
__device__ __nv_bfloat16 g_ah[MROWS * DMODEL];   // x split, later attn split
__device__ __nv_bfloat16 g_al[MROWS * DMODEL];
__device__ __nv_bfloat16 g_yh[MROWS * DMODEL];
__device__ __nv_bfloat16 g_yl[MROWS * DMODEL];
__device__ __nv_bfloat16 g_qh[MROWS * DMODEL];
__device__ __nv_bfloat16 g_ql[MROWS * DMODEL];
__device__ __nv_bfloat16 g_kh[MROWS * DMODEL];
__device__ __nv_bfloat16 g_kl[MROWS * DMODEL];
__device__ __nv_bfloat16 g_vh[MROWS * DMODEL];
__device__ __nv_bfloat16 g_vl[MROWS * DMODEL];
__device__ __nv_bfloat16 g_wqh[DMODEL * DMODEL];
__device__ __nv_bfloat16 g_wql[DMODEL * DMODEL];
__device__ __nv_bfloat16 g_wkh[DMODEL * DMODEL];
__device__ __nv_bfloat16 g_wkl[DMODEL * DMODEL];
__device__ __nv_bfloat16 g_wvh[DMODEL * DMODEL];
__device__ __nv_bfloat16 g_wvl[DMODEL * DMODEL];
__device__ __nv_bfloat16 g_woh[DMODEL * DMODEL];
__device__ __nv_bfloat16 g_wol[DMODEL * DMODEL];

// ---------------------------------------------------------------------------
// Helpers
// ---------------------------------------------------------------------------
__device__ __forceinline__ void mma_bf16(float* c, const uint32_t* a, const uint32_t* b) {
    asm volatile(
        "mma.sync.aligned.m16n8k16.row.col.f32.bf16.bf16.f32 "
        "{%0,%1,%2,%3}, {%4,%5,%6,%7}, {%8,%9}, {%0,%1,%2,%3};"
        : "+f"(c[0]), "+f"(c[1]), "+f"(c[2]), "+f"(c[3])
        : "r"(a[0]), "r"(a[1]), "r"(a[2]), "r"(a[3]), "r"(b[0]), "r"(b[1]));
}

__device__ __forceinline__ void split_bf16(float v, __nv_bfloat16& h, __nv_bfloat16& l) {
    h = __float2bfloat16(v);
    l = __float2bfloat16(v - __bfloat162float(h));
}

// ---------------------------------------------------------------------------
// Prep: elementwise hi/lo bf16 split (row-major, n4 float4 elements)
// ---------------------------------------------------------------------------
__global__ __launch_bounds__(256) void split_kernel(
    const float* __restrict__ in, __nv_bfloat16* __restrict__ oh,
    __nv_bfloat16* __restrict__ ol, int n4)
{
    int i = blockIdx.x * blockDim.x + threadIdx.x;
    if (i >= n4) return;
    float4 v = ((const float4*)in)[i];
    __nv_bfloat16 h0, h1, h2, h3, l0, l1, l2, l3;
    split_bf16(v.x, h0, l0); split_bf16(v.y, h1, l1);
    split_bf16(v.z, h2, l2); split_bf16(v.w, h3, l3);
    __nv_bfloat162* ph = (__nv_bfloat162*)oh;
    __nv_bfloat162* pl = (__nv_bfloat162*)ol;
    ph[i * 2 + 0] = __halves2bfloat162(h0, h1);
    ph[i * 2 + 1] = __halves2bfloat162(h2, h3);
    pl[i * 2 + 0] = __halves2bfloat162(l0, l1);
    pl[i * 2 + 1] = __halves2bfloat162(l2, l3);
}

// ---------------------------------------------------------------------------
// Prep: weight transpose + split. out[n][k] = split(in[k][n]), 1024x1024.
// ---------------------------------------------------------------------------
__global__ __launch_bounds__(256) void tsplit_kernel(
    const float* __restrict__ in, __nv_bfloat16* __restrict__ oh,
    __nv_bfloat16* __restrict__ ol)
{
    __shared__ float tile[32][33];
    int x = blockIdx.x * 32 + threadIdx.x;
    int y = blockIdx.y * 32 + threadIdx.y;
    #pragma unroll
    for (int j = 0; j < 32; j += 8)
        tile[threadIdx.y + j][threadIdx.x] = in[(size_t)(y + j) * DMODEL + x];
    __syncthreads();
    x = blockIdx.y * 32 + threadIdx.x;
    y = blockIdx.x * 32 + threadIdx.y;
    #pragma unroll
    for (int j = 0; j < 32; j += 8) {
        float v = tile[threadIdx.x][threadIdx.y + j];
        __nv_bfloat16 h, l;
        split_bf16(v, h, l);
        oh[(size_t)(y + j) * DMODEL + x] = h;
        ol[(size_t)(y + j) * DMODEL + x] = l;
    }
}

// ---------------------------------------------------------------------------
// 3-term bf16 tensor-core GEMM, templated epilogue:
//   BFOUT=0: C fp32;  BFOUT=1: (Ch, Cl) bf16 hi/lo split.
// CTA tile 128x128, K chunk 32, 8 warps, warp tile 32x64. 2 CTAs/SM.
// ---------------------------------------------------------------------------
#define GSTRIDE 56
#define GTILE_B (128 * GSTRIDE * 2)
#define GEMM_SMEM (4 * GTILE_B)                // 57344

template<int BFOUT>
__global__ __launch_bounds__(256, 2) void bf16_gemm_t(
    const __nv_bfloat16* __restrict__ Ah, const __nv_bfloat16* __restrict__ Al,
    const __nv_bfloat16* __restrict__ Bh, const __nv_bfloat16* __restrict__ Bl,
    float* __restrict__ C, __nv_bfloat16* __restrict__ Ch,
    __nv_bfloat16* __restrict__ Cl, float alpha)
{
    extern __shared__ __align__(16) char gsm[];
    uint16_t* sAh = (uint16_t*)gsm;
    uint16_t* sAl = (uint16_t*)(gsm + GTILE_B);
    uint16_t* sBh = (uint16_t*)(gsm + 2 * GTILE_B);
    uint16_t* sBl = (uint16_t*)(gsm + 3 * GTILE_B);

    const int tid  = threadIdx.x;
    const int lane = tid & 31;
    const int wid  = tid >> 5;
    const int g    = lane >> 2;
    const int tig  = lane & 3;
    const int wrow = (wid & 3) * 32;
    const int wcol = (wid >> 2) * 64;

    const int blockRow = blockIdx.y * 128;
    const int blockCol = blockIdx.x * 128;
    const int K = DMODEL;

    float acc[2][8][4];
    #pragma unroll
    for (int mu = 0; mu < 2; mu++)
        #pragma unroll
        for (int nf = 0; nf < 8; nf++)
            #pragma unroll
            for (int r = 0; r < 4; r++) acc[mu][nf][r] = 0.0f;

    for (int k0 = 0; k0 < K; k0 += 32) {
        #pragma unroll
        for (int j = 0; j < 2; j++) {
            int idx = tid + j * 256;
            int row = idx >> 2;
            int seg = idx & 3;
            size_t goff = (size_t)(blockRow + row) * K + k0 + seg * 8;
            *(uint4*)&sAh[row * GSTRIDE + seg * 8] = *(const uint4*)(Ah + goff);
            *(uint4*)&sAl[row * GSTRIDE + seg * 8] = *(const uint4*)(Al + goff);
            size_t boff = (size_t)(blockCol + row) * K + k0 + seg * 8;
            *(uint4*)&sBh[row * GSTRIDE + seg * 8] = *(const uint4*)(Bh + boff);
            *(uint4*)&sBl[row * GSTRIDE + seg * 8] = *(const uint4*)(Bl + boff);
        }
        __syncthreads();

        #pragma unroll
        for (int ks = 0; ks < 2; ks++) {
            const int kb = ks * 16;
            uint32_t ah[2][4], al[2][4];
            #pragma unroll
            for (int mu = 0; mu < 2; mu++) {
                const int ra = (wrow + mu * 16 + g) * GSTRIDE + kb + 2 * tig;
                const int rb = (wrow + mu * 16 + g + 8) * GSTRIDE + kb + 2 * tig;
                ah[mu][0] = *(const uint32_t*)&sAh[ra];
                ah[mu][1] = *(const uint32_t*)&sAh[rb];
                ah[mu][2] = *(const uint32_t*)&sAh[ra + 8];
                ah[mu][3] = *(const uint32_t*)&sAh[rb + 8];
                al[mu][0] = *(const uint32_t*)&sAl[ra];
                al[mu][1] = *(const uint32_t*)&sAl[rb];
                al[mu][2] = *(const uint32_t*)&sAl[ra + 8];
                al[mu][3] = *(const uint32_t*)&sAl[rb + 8];
            }
            #pragma unroll
            for (int nf = 0; nf < 8; nf++) {
                const int rn = (wcol + nf * 8 + g) * GSTRIDE + kb + 2 * tig;
                uint32_t bh[2], bl[2];
                bh[0] = *(const uint32_t*)&sBh[rn];
                bh[1] = *(const uint32_t*)&sBh[rn + 8];
                bl[0] = *(const uint32_t*)&sBl[rn];
                bl[1] = *(const uint32_t*)&sBl[rn + 8];
                #pragma unroll
                for (int mu = 0; mu < 2; mu++) {
                    mma_bf16(acc[mu][nf], ah[mu], bh);
                    mma_bf16(acc[mu][nf], al[mu], bh);
                    mma_bf16(acc[mu][nf], ah[mu], bl);
                }
            }
        }
        __syncthreads();
    }

    #pragma unroll
    for (int mu = 0; mu < 2; mu++) {
        #pragma unroll
        for (int nf = 0; nf < 8; nf++) {
            int row0 = blockRow + wrow + mu * 16 + g;
            int col  = blockCol + wcol + nf * 8 + tig * 2;
            float v0 = alpha * acc[mu][nf][0], v1 = alpha * acc[mu][nf][1];
            float v2 = alpha * acc[mu][nf][2], v3 = alpha * acc[mu][nf][3];
            if (BFOUT) {
                __nv_bfloat16 h0, h1, h2, h3, l0, l1, l2, l3;
                split_bf16(v0, h0, l0); split_bf16(v1, h1, l1);
                split_bf16(v2, h2, l2); split_bf16(v3, h3, l3);
                *(__nv_bfloat162*)(Ch + (size_t)row0 * DMODEL + col) = __halves2bfloat162(h0, h1);
                *(__nv_bfloat162*)(Cl + (size_t)row0 * DMODEL + col) = __halves2bfloat162(l0, l1);
                *(__nv_bfloat162*)(Ch + (size_t)(row0 + 8) * DMODEL + col) = __halves2bfloat162(h2, h3);
                *(__nv_bfloat162*)(Cl + (size_t)(row0 + 8) * DMODEL + col) = __halves2bfloat162(l2, l3);
            } else {
                *(float2*)(C + (size_t)row0 * DMODEL + col)       = make_float2(v0, v1);
                *(float2*)(C + (size_t)(row0 + 8) * DMODEL + col) = make_float2(v2, v3);
            }
        }
    }
}

// ---------------------------------------------------------------------------
// Full-bf16 flash attention. CTA: 128 q rows, 8 warps, KV tile 64.
// QK^T: 3-term bf16 (QhKh+QlKh+QhKl). PV: 3-term bf16 (PhVh+PlVh+PhVl).
// All SMEM strides 72 (bank-conflict-free for every hot frag pattern).
// V transposed into SMEM at load; attn output written as bf16 hi/lo.
// ---------------------------------------------------------------------------
#define KS  72
#define VT  72
#define PST 72
#define FL_KH 0
#define FL_KL (64 * KS)
#define FL_VH (2 * 64 * KS)
#define FL_VL (2 * 64 * KS + 64 * VT)
#define FL_PH (2 * 64 * KS + 2 * 64 * VT)
#define FL_PL (FL_PH + 128 * PST)
#define FLASH_SMEM_BYTES ((FL_PL + 128 * PST) * 2)   // 73728

__global__ __launch_bounds__(256, 2) void flash_bf16_kernel(
    const __nv_bfloat16* __restrict__ Qh, const __nv_bfloat16* __restrict__ Ql,
    const __nv_bfloat16* __restrict__ Kg_h, const __nv_bfloat16* __restrict__ Kg_l,
    const __nv_bfloat16* __restrict__ Vg_h, const __nv_bfloat16* __restrict__ Vg_l,
    const float* __restrict__ bias,
    __nv_bfloat16* __restrict__ Oh, __nv_bfloat16* __restrict__ Ol)
{
    extern __shared__ uint16_t fsm[];
    uint16_t* sKh = fsm + FL_KH;
    uint16_t* sKl = fsm + FL_KL;
    uint16_t* sVh = fsm + FL_VH;
    uint16_t* sVl = fsm + FL_VL;
    uint16_t* sPh = fsm + FL_PH;
    uint16_t* sPl = fsm + FL_PL;

    const int tid  = threadIdx.x;
    const int lane = tid & 31;
    const int wid  = tid >> 5;
    const int g    = lane >> 2;
    const int tig  = lane & 3;

    const int h = blockIdx.y;
    const int b = blockIdx.z;
    const int qbase = blockIdx.x * 128;
    const int wrow  = wid * 16;

    const uint16_t* qhp = (const uint16_t*)Qh + (size_t)(b * SEQ + qbase + wrow) * DMODEL + h * DEPTH;
    const uint16_t* qlp = (const uint16_t*)Ql + (size_t)(b * SEQ + qbase + wrow) * DMODEL + h * DEPTH;

    // V-transpose mapping: 4x4 block per thread
    const int vbr = tid >> 4;   // kv-row block 0..15
    const int vbc = tid & 15;   // depth block 0..15

    float o[8][4];
    #pragma unroll
    for (int nf = 0; nf < 8; nf++)
        #pragma unroll
        for (int r = 0; r < 4; r++) o[nf][r] = 0.0f;
    float m0 = -CUDART_INF_F, m1 = -CUDART_INF_F, l0 = 0.f, l1 = 0.f;

    const float* bp0 = bias + (size_t)(qbase + wrow + g) * SEQ;
    const float* bp8 = bias + (size_t)(qbase + wrow + g + 8) * SEQ;

    for (int kt = 0; kt < SEQ; kt += 64) {
        // ---- K tiles (no conversion, straight bf16 copy) ----
        #pragma unroll
        for (int j = 0; j < 2; j++) {
            int idx = tid + j * 256;
            int row = idx >> 3;
            int seg = idx & 7;
            size_t src = (size_t)(b * SEQ + kt + row) * DMODEL + h * DEPTH + seg * 8;
            *(uint4*)&sKh[row * KS + seg * 8] = *(const uint4*)((const uint16_t*)Kg_h + src);
            *(uint4*)&sKl[row * KS + seg * 8] = *(const uint4*)((const uint16_t*)Kg_l + src);
        }
        // ---- V tiles, transposed via 4x4 register blocks ----
        {
            ushort4 rh[4], rl[4];
            #pragma unroll
            for (int i = 0; i < 4; i++) {
                size_t src = (size_t)(b * SEQ + kt + 4 * vbr + i) * DMODEL + h * DEPTH + 4 * vbc;
                rh[i] = *(const ushort4*)((const uint16_t*)Vg_h + src);
                rl[i] = *(const ushort4*)((const uint16_t*)Vg_l + src);
            }
            *(ushort4*)&sVh[(4 * vbc + 0) * VT + 4 * vbr] = make_ushort4(rh[0].x, rh[1].x, rh[2].x, rh[3].x);
            *(ushort4*)&sVh[(4 * vbc + 1) * VT + 4 * vbr] = make_ushort4(rh[0].y, rh[1].y, rh[2].y, rh[3].y);
            *(ushort4*)&sVh[(4 * vbc + 2) * VT + 4 * vbr] = make_ushort4(rh[0].z, rh[1].z, rh[2].z, rh[3].z);
            *(ushort4*)&sVh[(4 * vbc + 3) * VT + 4 * vbr] = make_ushort4(rh[0].w, rh[1].w, rh[2].w, rh[3].w);
            *(ushort4*)&sVl[(4 * vbc + 0) * VT + 4 * vbr] = make_ushort4(rl[0].x, rl[1].x, rl[2].x, rl[3].x);
            *(ushort4*)&sVl[(4 * vbc + 1) * VT + 4 * vbr] = make_ushort4(rl[0].y, rl[1].y, rl[2].y, rl[3].y);
            *(ushort4*)&sVl[(4 * vbc + 2) * VT + 4 * vbr] = make_ushort4(rl[0].z, rl[1].z, rl[2].z, rl[3].z);
            *(ushort4*)&sVl[(4 * vbc + 3) * VT + 4 * vbr] = make_ushort4(rl[0].w, rl[1].w, rl[2].w, rl[3].w);
        }
        __syncthreads();

        // ---- S = Q @ K^T (3-term bf16) ----
        float s[8][4];
        #pragma unroll
        for (int nf = 0; nf < 8; nf++)
            #pragma unroll
            for (int r = 0; r < 4; r++) s[nf][r] = 0.0f;

        #pragma unroll
        for (int ks = 0; ks < 4; ks++) {
            const int c0 = ks * 16 + 2 * tig;
            uint32_t ah4[4], al4[4];
            ah4[0] = *(const uint32_t*)(qhp + (size_t)g * DMODEL + c0);
            ah4[1] = *(const uint32_t*)(qhp + (size_t)(g + 8) * DMODEL + c0);
            ah4[2] = *(const uint32_t*)(qhp + (size_t)g * DMODEL + c0 + 8);
            ah4[3] = *(const uint32_t*)(qhp + (size_t)(g + 8) * DMODEL + c0 + 8);
            al4[0] = *(const uint32_t*)(qlp + (size_t)g * DMODEL + c0);
            al4[1] = *(const uint32_t*)(qlp + (size_t)(g + 8) * DMODEL + c0);
            al4[2] = *(const uint32_t*)(qlp + (size_t)g * DMODEL + c0 + 8);
            al4[3] = *(const uint32_t*)(qlp + (size_t)(g + 8) * DMODEL + c0 + 8);
            #pragma unroll
            for (int nf = 0; nf < 8; nf++) {
                const int kr = (nf * 8 + g) * KS + c0;
                uint32_t bh2[2], bl2[2];
                bh2[0] = *(const uint32_t*)&sKh[kr];
                bh2[1] = *(const uint32_t*)&sKh[kr + 8];
                bl2[0] = *(const uint32_t*)&sKl[kr];
                bl2[1] = *(const uint32_t*)&sKl[kr + 8];
                mma_bf16(s[nf], ah4, bh2);
                mma_bf16(s[nf], al4, bh2);
                mma_bf16(s[nf], ah4, bl2);
            }
        }

        // ---- bias + row max ----
        float mx0 = -CUDART_INF_F, mx1 = -CUDART_INF_F;
        #pragma unroll
        for (int nf = 0; nf < 8; nf++) {
            float2 b0 = *(const float2*)(bp0 + kt + nf * 8 + tig * 2);
            float2 b1 = *(const float2*)(bp8 + kt + nf * 8 + tig * 2);
            s[nf][0] += b0.x; s[nf][1] += b0.y;
            s[nf][2] += b1.x; s[nf][3] += b1.y;
            mx0 = fmaxf(mx0, fmaxf(s[nf][0], s[nf][1]));
            mx1 = fmaxf(mx1, fmaxf(s[nf][2], s[nf][3]));
        }
        mx0 = fmaxf(mx0, __shfl_xor_sync(0xFFFFFFFFu, mx0, 1));
        mx0 = fmaxf(mx0, __shfl_xor_sync(0xFFFFFFFFu, mx0, 2));
        mx1 = fmaxf(mx1, __shfl_xor_sync(0xFFFFFFFFu, mx1, 1));
        mx1 = fmaxf(mx1, __shfl_xor_sync(0xFFFFFFFFu, mx1, 2));

        // ---- online softmax; P as bf16 hi/lo pairs into SMEM ----
        float nm0 = fmaxf(m0, mx0), nm1 = fmaxf(m1, mx1);
        float c0f = __expf(m0 - nm0), c1f = __expf(m1 - nm1);
        l0 *= c0f; l1 *= c1f; m0 = nm0; m1 = nm1;
        #pragma unroll
        for (int nf = 0; nf < 8; nf++) {
            o[nf][0] *= c0f; o[nf][1] *= c0f; o[nf][2] *= c1f; o[nf][3] *= c1f;
        }
        float la0 = 0.f, la1 = 0.f;
        #pragma unroll
        for (int nf = 0; nf < 8; nf++) {
            float p0 = __expf(s[nf][0] - nm0);
            float p1 = __expf(s[nf][1] - nm0);
            float p2 = __expf(s[nf][2] - nm1);
            float p3 = __expf(s[nf][3] - nm1);
            la0 += p0 + p1; la1 += p2 + p3;
            __nv_bfloat16 h0, h1, h2, h3, q0, q1, q2, q3;
            split_bf16(p0, h0, q0); split_bf16(p1, h1, q1);
            split_bf16(p2, h2, q2); split_bf16(p3, h3, q3);
            const int pr0 = (wrow + g) * PST + nf * 8 + 2 * tig;
            const int pr8 = (wrow + g + 8) * PST + nf * 8 + 2 * tig;
            *(__nv_bfloat162*)&sPh[pr0] = __halves2bfloat162(h0, h1);
            *(__nv_bfloat162*)&sPl[pr0] = __halves2bfloat162(q0, q1);
            *(__nv_bfloat162*)&sPh[pr8] = __halves2bfloat162(h2, h3);
            *(__nv_bfloat162*)&sPl[pr8] = __halves2bfloat162(q2, q3);
        }
        la0 += __shfl_xor_sync(0xFFFFFFFFu, la0, 1);
        la0 += __shfl_xor_sync(0xFFFFFFFFu, la0, 2);
        la1 += __shfl_xor_sync(0xFFFFFFFFu, la1, 1);
        la1 += __shfl_xor_sync(0xFFFFFFFFu, la1, 2);
        l0 += la0; l1 += la1;
        __syncwarp();

        // ---- O += P @ V (3-term bf16); P rows are warp-private ----
        #pragma unroll
        for (int ks = 0; ks < 4; ks++) {
            const int c0 = ks * 16 + 2 * tig;
            uint32_t pha[4], pla[4];
            pha[0] = *(const uint32_t*)&sPh[(wrow + g) * PST + c0];
            pha[1] = *(const uint32_t*)&sPh[(wrow + g + 8) * PST + c0];
            pha[2] = *(const uint32_t*)&sPh[(wrow + g) * PST + c0 + 8];
            pha[3] = *(const uint32_t*)&sPh[(wrow + g + 8) * PST + c0 + 8];
            pla[0] = *(const uint32_t*)&sPl[(wrow + g) * PST + c0];
            pla[1] = *(const uint32_t*)&sPl[(wrow + g + 8) * PST + c0];
            pla[2] = *(const uint32_t*)&sPl[(wrow + g) * PST + c0 + 8];
            pla[3] = *(const uint32_t*)&sPl[(wrow + g + 8) * PST + c0 + 8];
            #pragma unroll
            for (int nf = 0; nf < 8; nf++) {
                const int vr = (nf * 8 + g) * VT + c0;
                uint32_t vh2[2], vl2[2];
                vh2[0] = *(const uint32_t*)&sVh[vr];
                vh2[1] = *(const uint32_t*)&sVh[vr + 8];
                vl2[0] = *(const uint32_t*)&sVl[vr];
                vl2[1] = *(const uint32_t*)&sVl[vr + 8];
                mma_bf16(o[nf], pha, vh2);
                mma_bf16(o[nf], pla, vh2);
                mma_bf16(o[nf], pha, vl2);
            }
        }
        __syncthreads();
    }

    // ---- epilogue: normalize, hi/lo split, packed bf16 stores ----
    const float inv0 = 1.0f / l0, inv1 = 1.0f / l1;
    uint16_t* ohp0 = (uint16_t*)Oh + (size_t)(b * SEQ + qbase + wrow + g) * DMODEL + h * DEPTH;
    uint16_t* olp0 = (uint16_t*)Ol + (size_t)(b * SEQ + qbase + wrow + g) * DMODEL + h * DEPTH;
    uint16_t* ohp8 = ohp0 + (size_t)8 * DMODEL;
    uint16_t* olp8 = olp0 + (size_t)8 * DMODEL;
    #pragma unroll
    for (int nf = 0; nf < 8; nf++) {
        float v0 = o[nf][0] * inv0, v1 = o[nf][1] * inv0;
        float v2 = o[nf][2] * inv1, v3 = o[nf][3] * inv1;
        __nv_bfloat16 h0, h1, h2, h3, q0, q1, q2, q3;
        split_bf16(v0, h0, q0); split_bf16(v1, h1, q1);
        split_bf16(v2, h2, q2); split_bf16(v3, h3, q3);
        const int col = nf * 8 + tig * 2;
        *(__nv_bfloat162*)(ohp0 + col) = __halves2bfloat162(h0, h1);
        *(__nv_bfloat162*)(olp0 + col) = __halves2bfloat162(q0, q1);
        *(__nv_bfloat162*)(ohp8 + col) = __halves2bfloat162(h2, h3);
        *(__nv_bfloat162*)(olp8 + col) = __halves2bfloat162(q2, q3);
    }
}

// ---------------------------------------------------------------------------
// Launch
// ---------------------------------------------------------------------------
extern "C" void kernel_launch(void* const* d_in, const int* in_sizes, int n_in,
                              void* d_out, int out_size)
{
    const float* x    = (const float*)d_in[0];
    const float* y    = (const float*)d_in[1];
    const float* bias = (const float*)d_in[2];
    const float* Wq   = (const float*)d_in[3];
    const float* Wk   = (const float*)d_in[4];
    const float* Wv   = (const float*)d_in[5];
    const float* Wo   = (const float*)d_in[6];
    float* out = (float*)d_out;

    __nv_bfloat16 *ah, *al, *yh, *yl, *qh, *ql, *kh, *kl, *vh, *vl;
    __nv_bfloat16 *wqh, *wql, *wkh, *wkl, *wvh, *wvl, *woh, *wol;
    cudaGetSymbolAddress((void**)&ah,  g_ah);
    cudaGetSymbolAddress((void**)&al,  g_al);
    cudaGetSymbolAddress((void**)&yh,  g_yh);
    cudaGetSymbolAddress((void**)&yl,  g_yl);
    cudaGetSymbolAddress((void**)&qh,  g_qh);
    cudaGetSymbolAddress((void**)&ql,  g_ql);
    cudaGetSymbolAddress((void**)&kh,  g_kh);
    cudaGetSymbolAddress((void**)&kl,  g_kl);
    cudaGetSymbolAddress((void**)&vh,  g_vh);
    cudaGetSymbolAddress((void**)&vl,  g_vl);
    cudaGetSymbolAddress((void**)&wqh, g_wqh);
    cudaGetSymbolAddress((void**)&wql, g_wql);
    cudaGetSymbolAddress((void**)&wkh, g_wkh);
    cudaGetSymbolAddress((void**)&wkl, g_wkl);
    cudaGetSymbolAddress((void**)&wvh, g_wvh);
    cudaGetSymbolAddress((void**)&wvl, g_wvl);
    cudaGetSymbolAddress((void**)&woh, g_woh);
    cudaGetSymbolAddress((void**)&wol, g_wol);

    cudaFuncSetAttribute(flash_bf16_kernel,
                         cudaFuncAttributeMaxDynamicSharedMemorySize, FLASH_SMEM_BYTES);
    cudaFuncSetAttribute(bf16_gemm_t<0>,
                         cudaFuncAttributeMaxDynamicSharedMemorySize, GEMM_SMEM);
    cudaFuncSetAttribute(bf16_gemm_t<1>,
                         cudaFuncAttributeMaxDynamicSharedMemorySize, GEMM_SMEM);

    const int n4 = MROWS * DMODEL / 4;
    dim3 sgrid((n4 + 255) / 256);
    split_kernel<<<sgrid, 256, 0, 0>>>(x, ah, al, n4);
    split_kernel<<<sgrid, 256, 0, 0>>>(y, yh, yl, n4);

    dim3 tgrid(32, 32), tblock(32, 8);
    tsplit_kernel<<<tgrid, tblock, 0, 0>>>(Wq, wqh, wql);
    tsplit_kernel<<<tgrid, tblock, 0, 0>>>(Wk, wkh, wkl);
    tsplit_kernel<<<tgrid, tblock, 0, 0>>>(Wv, wvh, wvl);
    tsplit_kernel<<<tgrid, tblock, 0, 0>>>(Wo, woh, wol);

    dim3 ggrid(DMODEL / 128, MROWS / 128);   // (8, 32)

    // q = (x @ Wq) * sqrt(depth) = * 8 ; outputs split bf16
    bf16_gemm_t<1><<<ggrid, 256, GEMM_SMEM, 0>>>(ah, al, wqh, wql, nullptr, qh, ql, 8.0f);
    bf16_gemm_t<1><<<ggrid, 256, GEMM_SMEM, 0>>>(yh, yl, wkh, wkl, nullptr, kh, kl, 1.0f);
    bf16_gemm_t<1><<<ggrid, 256, GEMM_SMEM, 0>>>(yh, yl, wvh, wvl, nullptr, vh, vl, 1.0f);

    dim3 fgrid(SEQ / 128, NHEADS, BATCH);    // (16, 16, 2)
    flash_bf16_kernel<<<fgrid, 256, FLASH_SMEM_BYTES, 0>>>(
        qh, ql, kh, kl, vh, vl, bias, ah, al);

    bf16_gemm_t<0><<<ggrid, 256, GEMM_SMEM, 0>>>(ah, al, woh, wol, out, nullptr, nullptr, 1.0f);
}

// round 9
// speedup vs baseline: 3.4724x; 1.0444x over previous
#include <cuda_runtime.h>
#include <cuda_bf16.h>
#include <math_constants.h>
#include <cstdint>

// Problem constants (fixed by the reference setup)
#define SEQ    2048
#define DMODEL 1024
#define NHEADS 16
#define DEPTH  64
#define BATCH  2
#define MROWS  (BATCH * SEQ)   // 4096

// Scratch (allocation-free rule: __device__ globals). All bf16 hi/lo pairs.
__device__ __nv_bfloat16 g_ah[MROWS * DMODEL];   // x split, later attn split
__device__ __nv_bfloat16 g_al[MROWS * DMODEL];
__device__ __nv_bfloat16 g_yh[MROWS * DMODEL];
__device__ __nv_bfloat16 g_yl[MROWS * DMODEL];
__device__ __nv_bfloat16 g_qh[MROWS * DMODEL];
__device__ __nv_bfloat16 g_ql[MROWS * DMODEL];
__device__ __nv_bfloat16 g_kh[MROWS * DMODEL];
__device__ __nv_bfloat16 g_kl[MROWS * DMODEL];
__device__ __nv_bfloat16 g_vh[MROWS * DMODEL];
__device__ __nv_bfloat16 g_vl[MROWS * DMODEL];
__device__ __nv_bfloat16 g_wqh[DMODEL * DMODEL];
__device__ __nv_bfloat16 g_wql[DMODEL * DMODEL];
__device__ __nv_bfloat16 g_wkh[DMODEL * DMODEL];
__device__ __nv_bfloat16 g_wkl[DMODEL * DMODEL];
__device__ __nv_bfloat16 g_wvh[DMODEL * DMODEL];
__device__ __nv_bfloat16 g_wvl[DMODEL * DMODEL];
__device__ __nv_bfloat16 g_woh[DMODEL * DMODEL];
__device__ __nv_bfloat16 g_wol[DMODEL * DMODEL];

// ---------------------------------------------------------------------------
// Helpers
// ---------------------------------------------------------------------------
__device__ __forceinline__ void mma_bf16(float* c, const uint32_t* a, const uint32_t* b) {
    asm volatile(
        "mma.sync.aligned.m16n8k16.row.col.f32.bf16.bf16.f32 "
        "{%0,%1,%2,%3}, {%4,%5,%6,%7}, {%8,%9}, {%0,%1,%2,%3};"
        : "+f"(c[0]), "+f"(c[1]), "+f"(c[2]), "+f"(c[3])
        : "r"(a[0]), "r"(a[1]), "r"(a[2]), "r"(a[3]), "r"(b[0]), "r"(b[1]));
}

__device__ __forceinline__ void split_bf16(float v, __nv_bfloat16& h, __nv_bfloat16& l) {
    h = __float2bfloat16(v);
    l = __float2bfloat16(v - __bfloat162float(h));
}

__device__ __forceinline__ uint32_t pack2(__nv_bfloat16 a, __nv_bfloat16 b) {
    __nv_bfloat162 t = __halves2bfloat162(a, b);
    return *(uint32_t*)&t;
}

// ---------------------------------------------------------------------------
// Prep: elementwise hi/lo bf16 split (row-major, n4 float4 elements)
// ---------------------------------------------------------------------------
__global__ __launch_bounds__(256) void split_kernel(
    const float* __restrict__ in, __nv_bfloat16* __restrict__ oh,
    __nv_bfloat16* __restrict__ ol, int n4)
{
    int i = blockIdx.x * blockDim.x + threadIdx.x;
    if (i >= n4) return;
    float4 v = ((const float4*)in)[i];
    __nv_bfloat16 h0, h1, h2, h3, l0, l1, l2, l3;
    split_bf16(v.x, h0, l0); split_bf16(v.y, h1, l1);
    split_bf16(v.z, h2, l2); split_bf16(v.w, h3, l3);
    __nv_bfloat162* ph = (__nv_bfloat162*)oh;
    __nv_bfloat162* pl = (__nv_bfloat162*)ol;
    ph[i * 2 + 0] = __halves2bfloat162(h0, h1);
    ph[i * 2 + 1] = __halves2bfloat162(h2, h3);
    pl[i * 2 + 0] = __halves2bfloat162(l0, l1);
    pl[i * 2 + 1] = __halves2bfloat162(l2, l3);
}

// ---------------------------------------------------------------------------
// Prep: weight transpose + split. out[n][k] = split(in[k][n]), 1024x1024.
// ---------------------------------------------------------------------------
__global__ __launch_bounds__(256) void tsplit_kernel(
    const float* __restrict__ in, __nv_bfloat16* __restrict__ oh,
    __nv_bfloat16* __restrict__ ol)
{
    __shared__ float tile[32][33];
    int x = blockIdx.x * 32 + threadIdx.x;
    int y = blockIdx.y * 32 + threadIdx.y;
    #pragma unroll
    for (int j = 0; j < 32; j += 8)
        tile[threadIdx.y + j][threadIdx.x] = in[(size_t)(y + j) * DMODEL + x];
    __syncthreads();
    x = blockIdx.y * 32 + threadIdx.x;
    y = blockIdx.x * 32 + threadIdx.y;
    #pragma unroll
    for (int j = 0; j < 32; j += 8) {
        float v = tile[threadIdx.x][threadIdx.y + j];
        __nv_bfloat16 h, l;
        split_bf16(v, h, l);
        oh[(size_t)(y + j) * DMODEL + x] = h;
        ol[(size_t)(y + j) * DMODEL + x] = l;
    }
}

// ---------------------------------------------------------------------------
// 3-term bf16 tensor-core GEMM, templated epilogue:
//   BFOUT=0: C fp32;  BFOUT=1: (Ch, Cl) bf16 hi/lo split.
// CTA tile 128x128, K chunk 32, 8 warps, warp tile 32x64. 2 CTAs/SM.
// ---------------------------------------------------------------------------
#define GSTRIDE 56
#define GTILE_B (128 * GSTRIDE * 2)
#define GEMM_SMEM (4 * GTILE_B)                // 57344

template<int BFOUT>
__global__ __launch_bounds__(256, 2) void bf16_gemm_t(
    const __nv_bfloat16* __restrict__ Ah, const __nv_bfloat16* __restrict__ Al,
    const __nv_bfloat16* __restrict__ Bh, const __nv_bfloat16* __restrict__ Bl,
    float* __restrict__ C, __nv_bfloat16* __restrict__ Ch,
    __nv_bfloat16* __restrict__ Cl, float alpha)
{
    extern __shared__ __align__(16) char gsm[];
    uint16_t* sAh = (uint16_t*)gsm;
    uint16_t* sAl = (uint16_t*)(gsm + GTILE_B);
    uint16_t* sBh = (uint16_t*)(gsm + 2 * GTILE_B);
    uint16_t* sBl = (uint16_t*)(gsm + 3 * GTILE_B);

    const int tid  = threadIdx.x;
    const int lane = tid & 31;
    const int wid  = tid >> 5;
    const int g    = lane >> 2;
    const int tig  = lane & 3;
    const int wrow = (wid & 3) * 32;
    const int wcol = (wid >> 2) * 64;

    const int blockRow = blockIdx.y * 128;
    const int blockCol = blockIdx.x * 128;
    const int K = DMODEL;

    float acc[2][8][4];
    #pragma unroll
    for (int mu = 0; mu < 2; mu++)
        #pragma unroll
        for (int nf = 0; nf < 8; nf++)
            #pragma unroll
            for (int r = 0; r < 4; r++) acc[mu][nf][r] = 0.0f;

    for (int k0 = 0; k0 < K; k0 += 32) {
        #pragma unroll
        for (int j = 0; j < 2; j++) {
            int idx = tid + j * 256;
            int row = idx >> 2;
            int seg = idx & 3;
            size_t goff = (size_t)(blockRow + row) * K + k0 + seg * 8;
            *(uint4*)&sAh[row * GSTRIDE + seg * 8] = *(const uint4*)(Ah + goff);
            *(uint4*)&sAl[row * GSTRIDE + seg * 8] = *(const uint4*)(Al + goff);
            size_t boff = (size_t)(blockCol + row) * K + k0 + seg * 8;
            *(uint4*)&sBh[row * GSTRIDE + seg * 8] = *(const uint4*)(Bh + boff);
            *(uint4*)&sBl[row * GSTRIDE + seg * 8] = *(const uint4*)(Bl + boff);
        }
        __syncthreads();

        #pragma unroll
        for (int ks = 0; ks < 2; ks++) {
            const int kb = ks * 16;
            uint32_t ah[2][4], al[2][4];
            #pragma unroll
            for (int mu = 0; mu < 2; mu++) {
                const int ra = (wrow + mu * 16 + g) * GSTRIDE + kb + 2 * tig;
                const int rb = (wrow + mu * 16 + g + 8) * GSTRIDE + kb + 2 * tig;
                ah[mu][0] = *(const uint32_t*)&sAh[ra];
                ah[mu][1] = *(const uint32_t*)&sAh[rb];
                ah[mu][2] = *(const uint32_t*)&sAh[ra + 8];
                ah[mu][3] = *(const uint32_t*)&sAh[rb + 8];
                al[mu][0] = *(const uint32_t*)&sAl[ra];
                al[mu][1] = *(const uint32_t*)&sAl[rb];
                al[mu][2] = *(const uint32_t*)&sAl[ra + 8];
                al[mu][3] = *(const uint32_t*)&sAl[rb + 8];
            }
            #pragma unroll
            for (int nf = 0; nf < 8; nf++) {
                const int rn = (wcol + nf * 8 + g) * GSTRIDE + kb + 2 * tig;
                uint32_t bh[2], bl[2];
                bh[0] = *(const uint32_t*)&sBh[rn];
                bh[1] = *(const uint32_t*)&sBh[rn + 8];
                bl[0] = *(const uint32_t*)&sBl[rn];
                bl[1] = *(const uint32_t*)&sBl[rn + 8];
                #pragma unroll
                for (int mu = 0; mu < 2; mu++) {
                    mma_bf16(acc[mu][nf], ah[mu], bh);
                    mma_bf16(acc[mu][nf], al[mu], bh);
                    mma_bf16(acc[mu][nf], ah[mu], bl);
                }
            }
        }
        __syncthreads();
    }

    #pragma unroll
    for (int mu = 0; mu < 2; mu++) {
        #pragma unroll
        for (int nf = 0; nf < 8; nf++) {
            int row0 = blockRow + wrow + mu * 16 + g;
            int col  = blockCol + wcol + nf * 8 + tig * 2;
            float v0 = alpha * acc[mu][nf][0], v1 = alpha * acc[mu][nf][1];
            float v2 = alpha * acc[mu][nf][2], v3 = alpha * acc[mu][nf][3];
            if (BFOUT) {
                __nv_bfloat16 h0, h1, h2, h3, l0, l1, l2, l3;
                split_bf16(v0, h0, l0); split_bf16(v1, h1, l1);
                split_bf16(v2, h2, l2); split_bf16(v3, h3, l3);
                *(__nv_bfloat162*)(Ch + (size_t)row0 * DMODEL + col) = __halves2bfloat162(h0, h1);
                *(__nv_bfloat162*)(Cl + (size_t)row0 * DMODEL + col) = __halves2bfloat162(l0, l1);
                *(__nv_bfloat162*)(Ch + (size_t)(row0 + 8) * DMODEL + col) = __halves2bfloat162(h2, h3);
                *(__nv_bfloat162*)(Cl + (size_t)(row0 + 8) * DMODEL + col) = __halves2bfloat162(l2, l3);
            } else {
                *(float2*)(C + (size_t)row0 * DMODEL + col)       = make_float2(v0, v1);
                *(float2*)(C + (size_t)(row0 + 8) * DMODEL + col) = make_float2(v2, v3);
            }
        }
    }
}

// ---------------------------------------------------------------------------
// Full-bf16 flash attention v2.
// CTA: 128 q rows, 8 warps, KV tile 64. Q fragments in registers (loaded once).
// QK^T: 3-term bf16. PV: 3-term bf16 with P fragments relayouted IN REGISTERS
// (QK C-frag == PV A-frag for this tiling; no SMEM round trip).
// K/V SMEM stride 72 (conflict-free); V transposed at load.
// ---------------------------------------------------------------------------
#define KS  72
#define VT  72
#define FL_KH 0
#define FL_KL (64 * KS)
#define FL_VH (2 * 64 * KS)
#define FL_VL (2 * 64 * KS + 64 * VT)
#define FLASH_SMEM_BYTES ((FL_VL + 64 * VT) * 2)   // 36864

__global__ __launch_bounds__(256, 2) void flash_bf16_kernel(
    const __nv_bfloat16* __restrict__ Qh, const __nv_bfloat16* __restrict__ Ql,
    const __nv_bfloat16* __restrict__ Kg_h, const __nv_bfloat16* __restrict__ Kg_l,
    const __nv_bfloat16* __restrict__ Vg_h, const __nv_bfloat16* __restrict__ Vg_l,
    const float* __restrict__ bias,
    __nv_bfloat16* __restrict__ Oh, __nv_bfloat16* __restrict__ Ol)
{
    extern __shared__ uint16_t fsm[];
    uint16_t* sKh = fsm + FL_KH;
    uint16_t* sKl = fsm + FL_KL;
    uint16_t* sVh = fsm + FL_VH;
    uint16_t* sVl = fsm + FL_VL;

    const int tid  = threadIdx.x;
    const int lane = tid & 31;
    const int wid  = tid >> 5;
    const int g    = lane >> 2;
    const int tig  = lane & 3;

    const int h = blockIdx.y;
    const int b = blockIdx.z;
    const int qbase = blockIdx.x * 128;
    const int wrow  = wid * 16;

    // ---- Q fragments in registers (hi/lo), 4 k16 steps ----
    uint32_t qfh[4][4], qfl[4][4];
    {
        const uint16_t* qhp = (const uint16_t*)Qh + (size_t)(b * SEQ + qbase + wrow) * DMODEL + h * DEPTH;
        const uint16_t* qlp = (const uint16_t*)Ql + (size_t)(b * SEQ + qbase + wrow) * DMODEL + h * DEPTH;
        #pragma unroll
        for (int ks = 0; ks < 4; ks++) {
            const int c0 = ks * 16 + 2 * tig;
            qfh[ks][0] = *(const uint32_t*)(qhp + (size_t)g * DMODEL + c0);
            qfh[ks][1] = *(const uint32_t*)(qhp + (size_t)(g + 8) * DMODEL + c0);
            qfh[ks][2] = *(const uint32_t*)(qhp + (size_t)g * DMODEL + c0 + 8);
            qfh[ks][3] = *(const uint32_t*)(qhp + (size_t)(g + 8) * DMODEL + c0 + 8);
            qfl[ks][0] = *(const uint32_t*)(qlp + (size_t)g * DMODEL + c0);
            qfl[ks][1] = *(const uint32_t*)(qlp + (size_t)(g + 8) * DMODEL + c0);
            qfl[ks][2] = *(const uint32_t*)(qlp + (size_t)g * DMODEL + c0 + 8);
            qfl[ks][3] = *(const uint32_t*)(qlp + (size_t)(g + 8) * DMODEL + c0 + 8);
        }
    }

    // V-transpose mapping: 4x4 block per thread
    const int vbr = tid >> 4;
    const int vbc = tid & 15;

    float o[8][4];
    #pragma unroll
    for (int nf = 0; nf < 8; nf++)
        #pragma unroll
        for (int r = 0; r < 4; r++) o[nf][r] = 0.0f;
    float m0 = -CUDART_INF_F, m1 = -CUDART_INF_F, l0 = 0.f, l1 = 0.f;

    const float* bp0 = bias + (size_t)(qbase + wrow + g) * SEQ;
    const float* bp8 = bias + (size_t)(qbase + wrow + g + 8) * SEQ;

    for (int kt = 0; kt < SEQ; kt += 64) {
        // ---- K tiles ----
        #pragma unroll
        for (int j = 0; j < 2; j++) {
            int idx = tid + j * 256;
            int row = idx >> 3;
            int seg = idx & 7;
            size_t src = (size_t)(b * SEQ + kt + row) * DMODEL + h * DEPTH + seg * 8;
            *(uint4*)&sKh[row * KS + seg * 8] = *(const uint4*)((const uint16_t*)Kg_h + src);
            *(uint4*)&sKl[row * KS + seg * 8] = *(const uint4*)((const uint16_t*)Kg_l + src);
        }
        // ---- V tiles, transposed via 4x4 register blocks ----
        {
            ushort4 rh[4], rl[4];
            #pragma unroll
            for (int i = 0; i < 4; i++) {
                size_t src = (size_t)(b * SEQ + kt + 4 * vbr + i) * DMODEL + h * DEPTH + 4 * vbc;
                rh[i] = *(const ushort4*)((const uint16_t*)Vg_h + src);
                rl[i] = *(const ushort4*)((const uint16_t*)Vg_l + src);
            }
            *(ushort4*)&sVh[(4 * vbc + 0) * VT + 4 * vbr] = make_ushort4(rh[0].x, rh[1].x, rh[2].x, rh[3].x);
            *(ushort4*)&sVh[(4 * vbc + 1) * VT + 4 * vbr] = make_ushort4(rh[0].y, rh[1].y, rh[2].y, rh[3].y);
            *(ushort4*)&sVh[(4 * vbc + 2) * VT + 4 * vbr] = make_ushort4(rh[0].z, rh[1].z, rh[2].z, rh[3].z);
            *(ushort4*)&sVh[(4 * vbc + 3) * VT + 4 * vbr] = make_ushort4(rh[0].w, rh[1].w, rh[2].w, rh[3].w);
            *(ushort4*)&sVl[(4 * vbc + 0) * VT + 4 * vbr] = make_ushort4(rl[0].x, rl[1].x, rl[2].x, rl[3].x);
            *(ushort4*)&sVl[(4 * vbc + 1) * VT + 4 * vbr] = make_ushort4(rl[0].y, rl[1].y, rl[2].y, rl[3].y);
            *(ushort4*)&sVl[(4 * vbc + 2) * VT + 4 * vbr] = make_ushort4(rl[0].z, rl[1].z, rl[2].z, rl[3].z);
            *(ushort4*)&sVl[(4 * vbc + 3) * VT + 4 * vbr] = make_ushort4(rl[0].w, rl[1].w, rl[2].w, rl[3].w);
        }
        __syncthreads();

        // ---- S = Q @ K^T (3-term bf16) ----
        float s[8][4];
        #pragma unroll
        for (int nf = 0; nf < 8; nf++)
            #pragma unroll
            for (int r = 0; r < 4; r++) s[nf][r] = 0.0f;

        #pragma unroll
        for (int ks = 0; ks < 4; ks++) {
            const int c0 = ks * 16 + 2 * tig;
            #pragma unroll
            for (int nf = 0; nf < 8; nf++) {
                const int kr = (nf * 8 + g) * KS + c0;
                uint32_t bh2[2], bl2[2];
                bh2[0] = *(const uint32_t*)&sKh[kr];
                bh2[1] = *(const uint32_t*)&sKh[kr + 8];
                bl2[0] = *(const uint32_t*)&sKl[kr];
                bl2[1] = *(const uint32_t*)&sKl[kr + 8];
                mma_bf16(s[nf], qfh[ks], bh2);
                mma_bf16(s[nf], qfl[ks], bh2);
                mma_bf16(s[nf], qfh[ks], bl2);
            }
        }

        // ---- bias + row max ----
        float mx0 = -CUDART_INF_F, mx1 = -CUDART_INF_F;
        #pragma unroll
        for (int nf = 0; nf < 8; nf++) {
            float2 b0 = *(const float2*)(bp0 + kt + nf * 8 + tig * 2);
            float2 b1 = *(const float2*)(bp8 + kt + nf * 8 + tig * 2);
            s[nf][0] += b0.x; s[nf][1] += b0.y;
            s[nf][2] += b1.x; s[nf][3] += b1.y;
            mx0 = fmaxf(mx0, fmaxf(s[nf][0], s[nf][1]));
            mx1 = fmaxf(mx1, fmaxf(s[nf][2], s[nf][3]));
        }
        mx0 = fmaxf(mx0, __shfl_xor_sync(0xFFFFFFFFu, mx0, 1));
        mx0 = fmaxf(mx0, __shfl_xor_sync(0xFFFFFFFFu, mx0, 2));
        mx1 = fmaxf(mx1, __shfl_xor_sync(0xFFFFFFFFu, mx1, 1));
        mx1 = fmaxf(mx1, __shfl_xor_sync(0xFFFFFFFFu, mx1, 2));

        // ---- online softmax; P hi/lo packed straight into A-fragments ----
        float nm0 = fmaxf(m0, mx0), nm1 = fmaxf(m1, mx1);
        float c0f = __expf(m0 - nm0), c1f = __expf(m1 - nm1);
        l0 *= c0f; l1 *= c1f; m0 = nm0; m1 = nm1;
        #pragma unroll
        for (int nf = 0; nf < 8; nf++) {
            o[nf][0] *= c0f; o[nf][1] *= c0f; o[nf][2] *= c1f; o[nf][3] *= c1f;
        }
        uint32_t pfh[4][4], pfl[4][4];
        float la0 = 0.f, la1 = 0.f;
        #pragma unroll
        for (int nf = 0; nf < 8; nf++) {
            float p0 = __expf(s[nf][0] - nm0);
            float p1 = __expf(s[nf][1] - nm0);
            float p2 = __expf(s[nf][2] - nm1);
            float p3 = __expf(s[nf][3] - nm1);
            la0 += p0 + p1; la1 += p2 + p3;
            __nv_bfloat16 h0, h1, h2, h3, q0, q1, q2, q3;
            split_bf16(p0, h0, q0); split_bf16(p1, h1, q1);
            split_bf16(p2, h2, q2); split_bf16(p3, h3, q3);
            const int ks = nf >> 1;
            const int rbase = (nf & 1) * 2;   // even nf -> a0,a1; odd nf -> a2,a3
            pfh[ks][rbase + 0] = pack2(h0, h1);   // row g
            pfh[ks][rbase + 1] = pack2(h2, h3);   // row g+8
            pfl[ks][rbase + 0] = pack2(q0, q1);
            pfl[ks][rbase + 1] = pack2(q2, q3);
        }
        la0 += __shfl_xor_sync(0xFFFFFFFFu, la0, 1);
        la0 += __shfl_xor_sync(0xFFFFFFFFu, la0, 2);
        la1 += __shfl_xor_sync(0xFFFFFFFFu, la1, 1);
        la1 += __shfl_xor_sync(0xFFFFFFFFu, la1, 2);
        l0 += la0; l1 += la1;

        // ---- O += P @ V (3-term bf16), P from registers ----
        #pragma unroll
        for (int ks = 0; ks < 4; ks++) {
            const int c0 = ks * 16 + 2 * tig;
            #pragma unroll
            for (int nf = 0; nf < 8; nf++) {
                const int vr = (nf * 8 + g) * VT + c0;
                uint32_t vh2[2], vl2[2];
                vh2[0] = *(const uint32_t*)&sVh[vr];
                vh2[1] = *(const uint32_t*)&sVh[vr + 8];
                vl2[0] = *(const uint32_t*)&sVl[vr];
                vl2[1] = *(const uint32_t*)&sVl[vr + 8];
                mma_bf16(o[nf], pfh[ks], vh2);
                mma_bf16(o[nf], pfl[ks], vh2);
                mma_bf16(o[nf], pfh[ks], vl2);
            }
        }
        __syncthreads();
    }

    // ---- epilogue: normalize, hi/lo split, packed bf16 stores ----
    const float inv0 = 1.0f / l0, inv1 = 1.0f / l1;
    uint16_t* ohp0 = (uint16_t*)Oh + (size_t)(b * SEQ + qbase + wrow + g) * DMODEL + h * DEPTH;
    uint16_t* olp0 = (uint16_t*)Ol + (size_t)(b * SEQ + qbase + wrow + g) * DMODEL + h * DEPTH;
    uint16_t* ohp8 = ohp0 + (size_t)8 * DMODEL;
    uint16_t* olp8 = olp0 + (size_t)8 * DMODEL;
    #pragma unroll
    for (int nf = 0; nf < 8; nf++) {
        float v0 = o[nf][0] * inv0, v1 = o[nf][1] * inv0;
        float v2 = o[nf][2] * inv1, v3 = o[nf][3] * inv1;
        __nv_bfloat16 h0, h1, h2, h3, q0, q1, q2, q3;
        split_bf16(v0, h0, q0); split_bf16(v1, h1, q1);
        split_bf16(v2, h2, q2); split_bf16(v3, h3, q3);
        const int col = nf * 8 + tig * 2;
        *(__nv_bfloat162*)(ohp0 + col) = __halves2bfloat162(h0, h1);
        *(__nv_bfloat162*)(olp0 + col) = __halves2bfloat162(q0, q1);
        *(__nv_bfloat162*)(ohp8 + col) = __halves2bfloat162(h2, h3);
        *(__nv_bfloat162*)(olp8 + col) = __halves2bfloat162(q2, q3);
    }
}

// ---------------------------------------------------------------------------
// Launch
// ---------------------------------------------------------------------------
extern "C" void kernel_launch(void* const* d_in, const int* in_sizes, int n_in,
                              void* d_out, int out_size)
{
    const float* x    = (const float*)d_in[0];
    const float* y    = (const float*)d_in[1];
    const float* bias = (const float*)d_in[2];
    const float* Wq   = (const float*)d_in[3];
    const float* Wk   = (const float*)d_in[4];
    const float* Wv   = (const float*)d_in[5];
    const float* Wo   = (const float*)d_in[6];
    float* out = (float*)d_out;

    __nv_bfloat16 *ah, *al, *yh, *yl, *qh, *ql, *kh, *kl, *vh, *vl;
    __nv_bfloat16 *wqh, *wql, *wkh, *wkl, *wvh, *wvl, *woh, *wol;
    cudaGetSymbolAddress((void**)&ah,  g_ah);
    cudaGetSymbolAddress((void**)&al,  g_al);
    cudaGetSymbolAddress((void**)&yh,  g_yh);
    cudaGetSymbolAddress((void**)&yl,  g_yl);
    cudaGetSymbolAddress((void**)&qh,  g_qh);
    cudaGetSymbolAddress((void**)&ql,  g_ql);
    cudaGetSymbolAddress((void**)&kh,  g_kh);
    cudaGetSymbolAddress((void**)&kl,  g_kl);
    cudaGetSymbolAddress((void**)&vh,  g_vh);
    cudaGetSymbolAddress((void**)&vl,  g_vl);
    cudaGetSymbolAddress((void**)&wqh, g_wqh);
    cudaGetSymbolAddress((void**)&wql, g_wql);
    cudaGetSymbolAddress((void**)&wkh, g_wkh);
    cudaGetSymbolAddress((void**)&wkl, g_wkl);
    cudaGetSymbolAddress((void**)&wvh, g_wvh);
    cudaGetSymbolAddress((void**)&wvl, g_wvl);
    cudaGetSymbolAddress((void**)&woh, g_woh);
    cudaGetSymbolAddress((void**)&wol, g_wol);

    cudaFuncSetAttribute(flash_bf16_kernel,
                         cudaFuncAttributeMaxDynamicSharedMemorySize, FLASH_SMEM_BYTES);
    cudaFuncSetAttribute(bf16_gemm_t<0>,
                         cudaFuncAttributeMaxDynamicSharedMemorySize, GEMM_SMEM);
    cudaFuncSetAttribute(bf16_gemm_t<1>,
                         cudaFuncAttributeMaxDynamicSharedMemorySize, GEMM_SMEM);

    const int n4 = MROWS * DMODEL / 4;
    dim3 sgrid((n4 + 255) / 256);
    split_kernel<<<sgrid, 256, 0, 0>>>(x, ah, al, n4);
    split_kernel<<<sgrid, 256, 0, 0>>>(y, yh, yl, n4);

    dim3 tgrid(32, 32), tblock(32, 8);
    tsplit_kernel<<<tgrid, tblock, 0, 0>>>(Wq, wqh, wql);
    tsplit_kernel<<<tgrid, tblock, 0, 0>>>(Wk, wkh, wkl);
    tsplit_kernel<<<tgrid, tblock, 0, 0>>>(Wv, wvh, wvl);
    tsplit_kernel<<<tgrid, tblock, 0, 0>>>(Wo, woh, wol);

    dim3 ggrid(DMODEL / 128, MROWS / 128);   // (8, 32)

    // q = (x @ Wq) * sqrt(depth) = * 8 ; outputs split bf16
    bf16_gemm_t<1><<<ggrid, 256, GEMM_SMEM, 0>>>(ah, al, wqh, wql, nullptr, qh, ql, 8.0f);
    bf16_gemm_t<1><<<ggrid, 256, GEMM_SMEM, 0>>>(yh, yl, wkh, wkl, nullptr, kh, kl, 1.0f);
    bf16_gemm_t<1><<<ggrid, 256, GEMM_SMEM, 0>>>(yh, yl, wvh, wvl, nullptr, vh, vl, 1.0f);

    dim3 fgrid(SEQ / 128, NHEADS, BATCH);    // (16, 16, 2)
    flash_bf16_kernel<<<fgrid, 256, FLASH_SMEM_BYTES, 0>>>(
        qh, ql, kh, kl, vh, vl, bias, ah, al);

    bf16_gemm_t<0><<<ggrid, 256, GEMM_SMEM, 0>>>(ah, al, woh, wol, out, nullptr, nullptr, 1.0f);
}

// round 10
// speedup vs baseline: 3.9067x; 1.1251x over previous
#include <cuda_runtime.h>
#include <cuda_bf16.h>
#include <math_constants.h>
#include <cstdint>

// Problem constants (fixed by the reference setup)
#define SEQ    2048
#define DMODEL 1024
#define NHEADS 16
#define DEPTH  64
#define BATCH  2
#define MROWS  (BATCH * SEQ)   // 4096

// Scratch (allocation-free rule: __device__ globals). All bf16 hi/lo pairs.
__device__ __nv_bfloat16 g_ah[MROWS * DMODEL];   // x split, later attn split
__device__ __nv_bfloat16 g_al[MROWS * DMODEL];
__device__ __nv_bfloat16 g_yh[MROWS * DMODEL];
__device__ __nv_bfloat16 g_yl[MROWS * DMODEL];
__device__ __nv_bfloat16 g_qh[MROWS * DMODEL];
__device__ __nv_bfloat16 g_ql[MROWS * DMODEL];
__device__ __nv_bfloat16 g_kh[MROWS * DMODEL];
__device__ __nv_bfloat16 g_kl[MROWS * DMODEL];
__device__ __nv_bfloat16 g_vh[MROWS * DMODEL];
__device__ __nv_bfloat16 g_vl[MROWS * DMODEL];
__device__ __nv_bfloat16 g_wqh[DMODEL * DMODEL];
__device__ __nv_bfloat16 g_wql[DMODEL * DMODEL];
__device__ __nv_bfloat16 g_wkh[DMODEL * DMODEL];
__device__ __nv_bfloat16 g_wkl[DMODEL * DMODEL];
__device__ __nv_bfloat16 g_wvh[DMODEL * DMODEL];
__device__ __nv_bfloat16 g_wvl[DMODEL * DMODEL];
__device__ __nv_bfloat16 g_woh[DMODEL * DMODEL];
__device__ __nv_bfloat16 g_wol[DMODEL * DMODEL];

// ---------------------------------------------------------------------------
// Helpers
// ---------------------------------------------------------------------------
__device__ __forceinline__ void mma_bf16(float* c, const uint32_t* a, const uint32_t* b) {
    asm volatile(
        "mma.sync.aligned.m16n8k16.row.col.f32.bf16.bf16.f32 "
        "{%0,%1,%2,%3}, {%4,%5,%6,%7}, {%8,%9}, {%0,%1,%2,%3};"
        : "+f"(c[0]), "+f"(c[1]), "+f"(c[2]), "+f"(c[3])
        : "r"(a[0]), "r"(a[1]), "r"(a[2]), "r"(a[3]), "r"(b[0]), "r"(b[1]));
}

__device__ __forceinline__ void ldsm_x4(uint32_t& r0, uint32_t& r1, uint32_t& r2,
                                        uint32_t& r3, uint32_t addr) {
    asm volatile("ldmatrix.sync.aligned.m8n8.x4.shared.b16 {%0,%1,%2,%3}, [%4];"
        : "=r"(r0), "=r"(r1), "=r"(r2), "=r"(r3) : "r"(addr));
}

__device__ __forceinline__ void ldsm_x4_t(uint32_t& r0, uint32_t& r1, uint32_t& r2,
                                          uint32_t& r3, uint32_t addr) {
    asm volatile("ldmatrix.sync.aligned.m8n8.x4.trans.shared.b16 {%0,%1,%2,%3}, [%4];"
        : "=r"(r0), "=r"(r1), "=r"(r2), "=r"(r3) : "r"(addr));
}

__device__ __forceinline__ uint32_t smem_u32(const void* p) {
    uint32_t a;
    asm("{ .reg .u64 t; cvta.to.shared.u64 t, %1; cvt.u32.u64 %0, t; }" : "=r"(a) : "l"(p));
    return a;
}

__device__ __forceinline__ void split_bf16(float v, __nv_bfloat16& h, __nv_bfloat16& l) {
    h = __float2bfloat16(v);
    l = __float2bfloat16(v - __bfloat162float(h));
}

// Truncation split of a float pair: hi = top-16-bit bf16s packed via prmt;
// lo = (v - hi) rounded to bf16 pair via cvt.rn.bf16x2. h+l == v to ~2^-17.
__device__ __forceinline__ void split_pair_trunc(float v0, float v1,
                                                 uint32_t& hp, uint32_t& lp) {
    uint32_t b0 = __float_as_uint(v0), b1 = __float_as_uint(v1);
    asm("prmt.b32 %0, %1, %2, 0x7632;" : "=r"(hp) : "r"(b0), "r"(b1));
    float l0 = v0 - __uint_as_float(b0 & 0xFFFF0000u);
    float l1 = v1 - __uint_as_float(b1 & 0xFFFF0000u);
    asm("cvt.rn.bf16x2.f32 %0, %1, %2;" : "=r"(lp) : "f"(l1), "f"(l0));
}

// ---------------------------------------------------------------------------
// Prep: elementwise hi/lo bf16 split (row-major, n4 float4 elements)
// ---------------------------------------------------------------------------
__global__ __launch_bounds__(256) void split_kernel(
    const float* __restrict__ in, __nv_bfloat16* __restrict__ oh,
    __nv_bfloat16* __restrict__ ol, int n4)
{
    int i = blockIdx.x * blockDim.x + threadIdx.x;
    if (i >= n4) return;
    float4 v = ((const float4*)in)[i];
    __nv_bfloat16 h0, h1, h2, h3, l0, l1, l2, l3;
    split_bf16(v.x, h0, l0); split_bf16(v.y, h1, l1);
    split_bf16(v.z, h2, l2); split_bf16(v.w, h3, l3);
    __nv_bfloat162* ph = (__nv_bfloat162*)oh;
    __nv_bfloat162* pl = (__nv_bfloat162*)ol;
    ph[i * 2 + 0] = __halves2bfloat162(h0, h1);
    ph[i * 2 + 1] = __halves2bfloat162(h2, h3);
    pl[i * 2 + 0] = __halves2bfloat162(l0, l1);
    pl[i * 2 + 1] = __halves2bfloat162(l2, l3);
}

// ---------------------------------------------------------------------------
// Prep: weight transpose + split. out[n][k] = split(in[k][n]), 1024x1024.
// ---------------------------------------------------------------------------
__global__ __launch_bounds__(256) void tsplit_kernel(
    const float* __restrict__ in, __nv_bfloat16* __restrict__ oh,
    __nv_bfloat16* __restrict__ ol)
{
    __shared__ float tile[32][33];
    int x = blockIdx.x * 32 + threadIdx.x;
    int y = blockIdx.y * 32 + threadIdx.y;
    #pragma unroll
    for (int j = 0; j < 32; j += 8)
        tile[threadIdx.y + j][threadIdx.x] = in[(size_t)(y + j) * DMODEL + x];
    __syncthreads();
    x = blockIdx.y * 32 + threadIdx.x;
    y = blockIdx.x * 32 + threadIdx.y;
    #pragma unroll
    for (int j = 0; j < 32; j += 8) {
        float v = tile[threadIdx.x][threadIdx.y + j];
        __nv_bfloat16 h, l;
        split_bf16(v, h, l);
        oh[(size_t)(y + j) * DMODEL + x] = h;
        ol[(size_t)(y + j) * DMODEL + x] = l;
    }
}

// ---------------------------------------------------------------------------
// 3-term bf16 tensor-core GEMM, templated epilogue (unchanged from R9).
// ---------------------------------------------------------------------------
#define GSTRIDE 56
#define GTILE_B (128 * GSTRIDE * 2)
#define GEMM_SMEM (4 * GTILE_B)                // 57344

template<int BFOUT>
__global__ __launch_bounds__(256, 2) void bf16_gemm_t(
    const __nv_bfloat16* __restrict__ Ah, const __nv_bfloat16* __restrict__ Al,
    const __nv_bfloat16* __restrict__ Bh, const __nv_bfloat16* __restrict__ Bl,
    float* __restrict__ C, __nv_bfloat16* __restrict__ Ch,
    __nv_bfloat16* __restrict__ Cl, float alpha)
{
    extern __shared__ __align__(16) char gsm[];
    uint16_t* sAh = (uint16_t*)gsm;
    uint16_t* sAl = (uint16_t*)(gsm + GTILE_B);
    uint16_t* sBh = (uint16_t*)(gsm + 2 * GTILE_B);
    uint16_t* sBl = (uint16_t*)(gsm + 3 * GTILE_B);

    const int tid  = threadIdx.x;
    const int lane = tid & 31;
    const int wid  = tid >> 5;
    const int g    = lane >> 2;
    const int tig  = lane & 3;
    const int wrow = (wid & 3) * 32;
    const int wcol = (wid >> 2) * 64;

    const int blockRow = blockIdx.y * 128;
    const int blockCol = blockIdx.x * 128;
    const int K = DMODEL;

    float acc[2][8][4];
    #pragma unroll
    for (int mu = 0; mu < 2; mu++)
        #pragma unroll
        for (int nf = 0; nf < 8; nf++)
            #pragma unroll
            for (int r = 0; r < 4; r++) acc[mu][nf][r] = 0.0f;

    for (int k0 = 0; k0 < K; k0 += 32) {
        #pragma unroll
        for (int j = 0; j < 2; j++) {
            int idx = tid + j * 256;
            int row = idx >> 2;
            int seg = idx & 3;
            size_t goff = (size_t)(blockRow + row) * K + k0 + seg * 8;
            *(uint4*)&sAh[row * GSTRIDE + seg * 8] = *(const uint4*)(Ah + goff);
            *(uint4*)&sAl[row * GSTRIDE + seg * 8] = *(const uint4*)(Al + goff);
            size_t boff = (size_t)(blockCol + row) * K + k0 + seg * 8;
            *(uint4*)&sBh[row * GSTRIDE + seg * 8] = *(const uint4*)(Bh + boff);
            *(uint4*)&sBl[row * GSTRIDE + seg * 8] = *(const uint4*)(Bl + boff);
        }
        __syncthreads();

        #pragma unroll
        for (int ks = 0; ks < 2; ks++) {
            const int kb = ks * 16;
            uint32_t ah[2][4], al[2][4];
            #pragma unroll
            for (int mu = 0; mu < 2; mu++) {
                const int ra = (wrow + mu * 16 + g) * GSTRIDE + kb + 2 * tig;
                const int rb = (wrow + mu * 16 + g + 8) * GSTRIDE + kb + 2 * tig;
                ah[mu][0] = *(const uint32_t*)&sAh[ra];
                ah[mu][1] = *(const uint32_t*)&sAh[rb];
                ah[mu][2] = *(const uint32_t*)&sAh[ra + 8];
                ah[mu][3] = *(const uint32_t*)&sAh[rb + 8];
                al[mu][0] = *(const uint32_t*)&sAl[ra];
                al[mu][1] = *(const uint32_t*)&sAl[rb];
                al[mu][2] = *(const uint32_t*)&sAl[ra + 8];
                al[mu][3] = *(const uint32_t*)&sAl[rb + 8];
            }
            #pragma unroll
            for (int nf = 0; nf < 8; nf++) {
                const int rn = (wcol + nf * 8 + g) * GSTRIDE + kb + 2 * tig;
                uint32_t bh[2], bl[2];
                bh[0] = *(const uint32_t*)&sBh[rn];
                bh[1] = *(const uint32_t*)&sBh[rn + 8];
                bl[0] = *(const uint32_t*)&sBl[rn];
                bl[1] = *(const uint32_t*)&sBl[rn + 8];
                #pragma unroll
                for (int mu = 0; mu < 2; mu++) {
                    mma_bf16(acc[mu][nf], ah[mu], bh);
                    mma_bf16(acc[mu][nf], al[mu], bh);
                    mma_bf16(acc[mu][nf], ah[mu], bl);
                }
            }
        }
        __syncthreads();
    }

    #pragma unroll
    for (int mu = 0; mu < 2; mu++) {
        #pragma unroll
        for (int nf = 0; nf < 8; nf++) {
            int row0 = blockRow + wrow + mu * 16 + g;
            int col  = blockCol + wcol + nf * 8 + tig * 2;
            float v0 = alpha * acc[mu][nf][0], v1 = alpha * acc[mu][nf][1];
            float v2 = alpha * acc[mu][nf][2], v3 = alpha * acc[mu][nf][3];
            if (BFOUT) {
                __nv_bfloat16 h0, h1, h2, h3, l0, l1, l2, l3;
                split_bf16(v0, h0, l0); split_bf16(v1, h1, l1);
                split_bf16(v2, h2, l2); split_bf16(v3, h3, l3);
                *(__nv_bfloat162*)(Ch + (size_t)row0 * DMODEL + col) = __halves2bfloat162(h0, h1);
                *(__nv_bfloat162*)(Cl + (size_t)row0 * DMODEL + col) = __halves2bfloat162(l0, l1);
                *(__nv_bfloat162*)(Ch + (size_t)(row0 + 8) * DMODEL + col) = __halves2bfloat162(h2, h3);
                *(__nv_bfloat162*)(Cl + (size_t)(row0 + 8) * DMODEL + col) = __halves2bfloat162(l2, l3);
            } else {
                *(float2*)(C + (size_t)row0 * DMODEL + col)       = make_float2(v0, v1);
                *(float2*)(C + (size_t)(row0 + 8) * DMODEL + col) = make_float2(v2, v3);
            }
        }
    }
}

// ---------------------------------------------------------------------------
// Full-bf16 flash attention v3.
// Q frags in registers; P relayouted in registers (truncation split).
// ALL B-fragments via ldmatrix.x4: K non-trans, V .trans (no manual V transpose).
// K and V both stored row-major [kv][depth], stride 72 (conflict-free LDSM).
// ---------------------------------------------------------------------------
#define KS  72
#define VT  72
#define FL_KH 0
#define FL_KL (64 * KS)
#define FL_VH (2 * 64 * KS)
#define FL_VL (2 * 64 * KS + 64 * VT)
#define FLASH_SMEM_BYTES ((FL_VL + 64 * VT) * 2)   // 36864

__global__ __launch_bounds__(256, 2) void flash_bf16_kernel(
    const __nv_bfloat16* __restrict__ Qh, const __nv_bfloat16* __restrict__ Ql,
    const __nv_bfloat16* __restrict__ Kg_h, const __nv_bfloat16* __restrict__ Kg_l,
    const __nv_bfloat16* __restrict__ Vg_h, const __nv_bfloat16* __restrict__ Vg_l,
    const float* __restrict__ bias,
    __nv_bfloat16* __restrict__ Oh, __nv_bfloat16* __restrict__ Ol)
{
    extern __shared__ uint16_t fsm[];
    const uint32_t smb = smem_u32(fsm);

    const int tid  = threadIdx.x;
    const int lane = tid & 31;
    const int wid  = tid >> 5;
    const int g    = lane >> 2;
    const int tig  = lane & 3;
    const int sec  = lane >> 3;    // ldmatrix section 0..3
    const int rowin = lane & 7;

    const int h = blockIdx.y;
    const int b = blockIdx.z;
    const int qbase = blockIdx.x * 128;
    const int wrow  = wid * 16;

    // ldmatrix lane offsets (uint16 units)
    // K (non-trans): matrices {nf=2p (k-lo, k-hi), nf=2p+1 (k-lo, k-hi)}
    const uint32_t lane_k = (uint32_t)(((sec >> 1) * 8 + rowin) * KS + (sec & 1) * 8);
    // V (.trans): matrices {nf=2p: kv-lo rows, kv-hi rows; nf=2p+1: ...}
    const uint32_t lane_v = (uint32_t)(((sec & 1) * 8 + rowin) * VT + (sec >> 1) * 8);

    // ---- Q fragments in registers (hi/lo), 4 k16 steps ----
    uint32_t qfh[4][4], qfl[4][4];
    {
        const uint16_t* qhp = (const uint16_t*)Qh + (size_t)(b * SEQ + qbase + wrow) * DMODEL + h * DEPTH;
        const uint16_t* qlp = (const uint16_t*)Ql + (size_t)(b * SEQ + qbase + wrow) * DMODEL + h * DEPTH;
        #pragma unroll
        for (int ks = 0; ks < 4; ks++) {
            const int c0 = ks * 16 + 2 * tig;
            qfh[ks][0] = *(const uint32_t*)(qhp + (size_t)g * DMODEL + c0);
            qfh[ks][1] = *(const uint32_t*)(qhp + (size_t)(g + 8) * DMODEL + c0);
            qfh[ks][2] = *(const uint32_t*)(qhp + (size_t)g * DMODEL + c0 + 8);
            qfh[ks][3] = *(const uint32_t*)(qhp + (size_t)(g + 8) * DMODEL + c0 + 8);
            qfl[ks][0] = *(const uint32_t*)(qlp + (size_t)g * DMODEL + c0);
            qfl[ks][1] = *(const uint32_t*)(qlp + (size_t)(g + 8) * DMODEL + c0);
            qfl[ks][2] = *(const uint32_t*)(qlp + (size_t)g * DMODEL + c0 + 8);
            qfl[ks][3] = *(const uint32_t*)(qlp + (size_t)(g + 8) * DMODEL + c0 + 8);
        }
    }

    float o[8][4];
    #pragma unroll
    for (int nf = 0; nf < 8; nf++)
        #pragma unroll
        for (int r = 0; r < 4; r++) o[nf][r] = 0.0f;
    float m0 = -CUDART_INF_F, m1 = -CUDART_INF_F, l0 = 0.f, l1 = 0.f;

    const float* bp0 = bias + (size_t)(qbase + wrow + g) * SEQ;
    const float* bp8 = bias + (size_t)(qbase + wrow + g + 8) * SEQ;

    for (int kt = 0; kt < SEQ; kt += 64) {
        // ---- K and V tiles: straight bf16 copies, row-major [kv][depth] ----
        #pragma unroll
        for (int j = 0; j < 2; j++) {
            int idx = tid + j * 256;
            int row = idx >> 3;
            int seg = idx & 7;
            size_t src = (size_t)(b * SEQ + kt + row) * DMODEL + h * DEPTH + seg * 8;
            *(uint4*)&fsm[FL_KH + row * KS + seg * 8] = *(const uint4*)((const uint16_t*)Kg_h + src);
            *(uint4*)&fsm[FL_KL + row * KS + seg * 8] = *(const uint4*)((const uint16_t*)Kg_l + src);
            *(uint4*)&fsm[FL_VH + row * VT + seg * 8] = *(const uint4*)((const uint16_t*)Vg_h + src);
            *(uint4*)&fsm[FL_VL + row * VT + seg * 8] = *(const uint4*)((const uint16_t*)Vg_l + src);
        }
        __syncthreads();

        // ---- S = Q @ K^T (3-term bf16), B-frags via ldmatrix.x4 ----
        float s[8][4];
        #pragma unroll
        for (int nf = 0; nf < 8; nf++)
            #pragma unroll
            for (int r = 0; r < 4; r++) s[nf][r] = 0.0f;

        #pragma unroll
        for (int ks = 0; ks < 4; ks++) {
            #pragma unroll
            for (int p = 0; p < 4; p++) {
                const uint32_t off = lane_k + (uint32_t)(p * 16 * KS + ks * 16);
                uint32_t bh[4], bl[4];
                ldsm_x4(bh[0], bh[1], bh[2], bh[3], smb + 2 * (FL_KH + off));
                ldsm_x4(bl[0], bl[1], bl[2], bl[3], smb + 2 * (FL_KL + off));
                mma_bf16(s[2 * p],     qfh[ks], bh);
                mma_bf16(s[2 * p],     qfl[ks], bh);
                mma_bf16(s[2 * p],     qfh[ks], bl);
                mma_bf16(s[2 * p + 1], qfh[ks], bh + 2);
                mma_bf16(s[2 * p + 1], qfl[ks], bh + 2);
                mma_bf16(s[2 * p + 1], qfh[ks], bl + 2);
            }
        }

        // ---- bias + row max ----
        float mx0 = -CUDART_INF_F, mx1 = -CUDART_INF_F;
        #pragma unroll
        for (int nf = 0; nf < 8; nf++) {
            float2 b0 = *(const float2*)(bp0 + kt + nf * 8 + tig * 2);
            float2 b1 = *(const float2*)(bp8 + kt + nf * 8 + tig * 2);
            s[nf][0] += b0.x; s[nf][1] += b0.y;
            s[nf][2] += b1.x; s[nf][3] += b1.y;
            mx0 = fmaxf(mx0, fmaxf(s[nf][0], s[nf][1]));
            mx1 = fmaxf(mx1, fmaxf(s[nf][2], s[nf][3]));
        }
        mx0 = fmaxf(mx0, __shfl_xor_sync(0xFFFFFFFFu, mx0, 1));
        mx0 = fmaxf(mx0, __shfl_xor_sync(0xFFFFFFFFu, mx0, 2));
        mx1 = fmaxf(mx1, __shfl_xor_sync(0xFFFFFFFFu, mx1, 1));
        mx1 = fmaxf(mx1, __shfl_xor_sync(0xFFFFFFFFu, mx1, 2));

        // ---- online softmax; P hi/lo packed straight into A-fragments ----
        float nm0 = fmaxf(m0, mx0), nm1 = fmaxf(m1, mx1);
        float c0f = __expf(m0 - nm0), c1f = __expf(m1 - nm1);
        l0 *= c0f; l1 *= c1f; m0 = nm0; m1 = nm1;
        #pragma unroll
        for (int nf = 0; nf < 8; nf++) {
            o[nf][0] *= c0f; o[nf][1] *= c0f; o[nf][2] *= c1f; o[nf][3] *= c1f;
        }
        uint32_t pfh[4][4], pfl[4][4];
        float la0 = 0.f, la1 = 0.f;
        #pragma unroll
        for (int nf = 0; nf < 8; nf++) {
            float p0 = __expf(s[nf][0] - nm0);
            float p1 = __expf(s[nf][1] - nm0);
            float p2 = __expf(s[nf][2] - nm1);
            float p3 = __expf(s[nf][3] - nm1);
            la0 += p0 + p1; la1 += p2 + p3;
            const int ks = nf >> 1;
            const int rbase = (nf & 1) * 2;
            split_pair_trunc(p0, p1, pfh[ks][rbase + 0], pfl[ks][rbase + 0]);   // row g
            split_pair_trunc(p2, p3, pfh[ks][rbase + 1], pfl[ks][rbase + 1]);   // row g+8
        }
        la0 += __shfl_xor_sync(0xFFFFFFFFu, la0, 1);
        la0 += __shfl_xor_sync(0xFFFFFFFFu, la0, 2);
        la1 += __shfl_xor_sync(0xFFFFFFFFu, la1, 1);
        la1 += __shfl_xor_sync(0xFFFFFFFFu, la1, 2);
        l0 += la0; l1 += la1;

        // ---- O += P @ V (3-term bf16); V B-frags via ldmatrix.x4.trans ----
        #pragma unroll
        for (int ks = 0; ks < 4; ks++) {
            #pragma unroll
            for (int p = 0; p < 4; p++) {
                const uint32_t off = lane_v + (uint32_t)(ks * 16 * VT + p * 16);
                uint32_t vh[4], vl[4];
                ldsm_x4_t(vh[0], vh[1], vh[2], vh[3], smb + 2 * (FL_VH + off));
                ldsm_x4_t(vl[0], vl[1], vl[2], vl[3], smb + 2 * (FL_VL + off));
                mma_bf16(o[2 * p],     pfh[ks], vh);
                mma_bf16(o[2 * p],     pfl[ks], vh);
                mma_bf16(o[2 * p],     pfh[ks], vl);
                mma_bf16(o[2 * p + 1], pfh[ks], vh + 2);
                mma_bf16(o[2 * p + 1], pfl[ks], vh + 2);
                mma_bf16(o[2 * p + 1], pfh[ks], vl + 2);
            }
        }
        __syncthreads();
    }

    // ---- epilogue: normalize, hi/lo split, packed bf16 stores ----
    const float inv0 = 1.0f / l0, inv1 = 1.0f / l1;
    uint16_t* ohp0 = (uint16_t*)Oh + (size_t)(b * SEQ + qbase + wrow + g) * DMODEL + h * DEPTH;
    uint16_t* olp0 = (uint16_t*)Ol + (size_t)(b * SEQ + qbase + wrow + g) * DMODEL + h * DEPTH;
    uint16_t* ohp8 = ohp0 + (size_t)8 * DMODEL;
    uint16_t* olp8 = olp0 + (size_t)8 * DMODEL;
    #pragma unroll
    for (int nf = 0; nf < 8; nf++) {
        float v0 = o[nf][0] * inv0, v1 = o[nf][1] * inv0;
        float v2 = o[nf][2] * inv1, v3 = o[nf][3] * inv1;
        uint32_t h01, l01, h23, l23;
        split_pair_trunc(v0, v1, h01, l01);
        split_pair_trunc(v2, v3, h23, l23);
        const int col = nf * 8 + tig * 2;
        *(uint32_t*)(ohp0 + col) = h01;
        *(uint32_t*)(olp0 + col) = l01;
        *(uint32_t*)(ohp8 + col) = h23;
        *(uint32_t*)(olp8 + col) = l23;
    }
}

// ---------------------------------------------------------------------------
// Launch
// ---------------------------------------------------------------------------
extern "C" void kernel_launch(void* const* d_in, const int* in_sizes, int n_in,
                              void* d_out, int out_size)
{
    const float* x    = (const float*)d_in[0];
    const float* y    = (const float*)d_in[1];
    const float* bias = (const float*)d_in[2];
    const float* Wq   = (const float*)d_in[3];
    const float* Wk   = (const float*)d_in[4];
    const float* Wv   = (const float*)d_in[5];
    const float* Wo   = (const float*)d_in[6];
    float* out = (float*)d_out;

    __nv_bfloat16 *ah, *al, *yh, *yl, *qh, *ql, *kh, *kl, *vh, *vl;
    __nv_bfloat16 *wqh, *wql, *wkh, *wkl, *wvh, *wvl, *woh, *wol;
    cudaGetSymbolAddress((void**)&ah,  g_ah);
    cudaGetSymbolAddress((void**)&al,  g_al);
    cudaGetSymbolAddress((void**)&yh,  g_yh);
    cudaGetSymbolAddress((void**)&yl,  g_yl);
    cudaGetSymbolAddress((void**)&qh,  g_qh);
    cudaGetSymbolAddress((void**)&ql,  g_ql);
    cudaGetSymbolAddress((void**)&kh,  g_kh);
    cudaGetSymbolAddress((void**)&kl,  g_kl);
    cudaGetSymbolAddress((void**)&vh,  g_vh);
    cudaGetSymbolAddress((void**)&vl,  g_vl);
    cudaGetSymbolAddress((void**)&wqh, g_wqh);
    cudaGetSymbolAddress((void**)&wql, g_wql);
    cudaGetSymbolAddress((void**)&wkh, g_wkh);
    cudaGetSymbolAddress((void**)&wkl, g_wkl);
    cudaGetSymbolAddress((void**)&wvh, g_wvh);
    cudaGetSymbolAddress((void**)&wvl, g_wvl);
    cudaGetSymbolAddress((void**)&woh, g_woh);
    cudaGetSymbolAddress((void**)&wol, g_wol);

    cudaFuncSetAttribute(flash_bf16_kernel,
                         cudaFuncAttributeMaxDynamicSharedMemorySize, FLASH_SMEM_BYTES);
    cudaFuncSetAttribute(bf16_gemm_t<0>,
                         cudaFuncAttributeMaxDynamicSharedMemorySize, GEMM_SMEM);
    cudaFuncSetAttribute(bf16_gemm_t<1>,
                         cudaFuncAttributeMaxDynamicSharedMemorySize, GEMM_SMEM);

    const int n4 = MROWS * DMODEL / 4;
    dim3 sgrid((n4 + 255) / 256);
    split_kernel<<<sgrid, 256, 0, 0>>>(x, ah, al, n4);
    split_kernel<<<sgrid, 256, 0, 0>>>(y, yh, yl, n4);

    dim3 tgrid(32, 32), tblock(32, 8);
    tsplit_kernel<<<tgrid, tblock, 0, 0>>>(Wq, wqh, wql);
    tsplit_kernel<<<tgrid, tblock, 0, 0>>>(Wk, wkh, wkl);
    tsplit_kernel<<<tgrid, tblock, 0, 0>>>(Wv, wvh, wvl);
    tsplit_kernel<<<tgrid, tblock, 0, 0>>>(Wo, woh, wol);

    dim3 ggrid(DMODEL / 128, MROWS / 128);   // (8, 32)

    // q = (x @ Wq) * sqrt(depth) = * 8 ; outputs split bf16
    bf16_gemm_t<1><<<ggrid, 256, GEMM_SMEM, 0>>>(ah, al, wqh, wql, nullptr, qh, ql, 8.0f);
    bf16_gemm_t<1><<<ggrid, 256, GEMM_SMEM, 0>>>(yh, yl, wkh, wkl, nullptr, kh, kl, 1.0f);
    bf16_gemm_t<1><<<ggrid, 256, GEMM_SMEM, 0>>>(yh, yl, wvh, wvl, nullptr, vh, vl, 1.0f);

    dim3 fgrid(SEQ / 128, NHEADS, BATCH);    // (16, 16, 2)
    flash_bf16_kernel<<<fgrid, 256, FLASH_SMEM_BYTES, 0>>>(
        qh, ql, kh, kl, vh, vl, bias, ah, al);

    bf16_gemm_t<0><<<ggrid, 256, GEMM_SMEM, 0>>>(ah, al, woh, wol, out, nullptr, nullptr, 1.0f);
}

// round 11
// speedup vs baseline: 4.1956x; 1.0739x over previous
#include <cuda_runtime.h>
#include <cuda_bf16.h>
#include <math_constants.h>
#include <cstdint>

// Problem constants (fixed by the reference setup)
#define SEQ    2048
#define DMODEL 1024
#define NHEADS 16
#define DEPTH  64
#define BATCH  2
#define MROWS  (BATCH * SEQ)   // 4096

// Scratch (allocation-free rule: __device__ globals). All bf16 hi/lo pairs.
__device__ __nv_bfloat16 g_ah[MROWS * DMODEL];   // x split, later attn split
__device__ __nv_bfloat16 g_al[MROWS * DMODEL];
__device__ __nv_bfloat16 g_yh[MROWS * DMODEL];
__device__ __nv_bfloat16 g_yl[MROWS * DMODEL];
__device__ __nv_bfloat16 g_qh[MROWS * DMODEL];
__device__ __nv_bfloat16 g_ql[MROWS * DMODEL];
__device__ __nv_bfloat16 g_kh[MROWS * DMODEL];
__device__ __nv_bfloat16 g_kl[MROWS * DMODEL];
__device__ __nv_bfloat16 g_vh[MROWS * DMODEL];
__device__ __nv_bfloat16 g_vl[MROWS * DMODEL];
__device__ __nv_bfloat16 g_wqh[DMODEL * DMODEL];
__device__ __nv_bfloat16 g_wql[DMODEL * DMODEL];
__device__ __nv_bfloat16 g_wkh[DMODEL * DMODEL];
__device__ __nv_bfloat16 g_wkl[DMODEL * DMODEL];
__device__ __nv_bfloat16 g_wvh[DMODEL * DMODEL];
__device__ __nv_bfloat16 g_wvl[DMODEL * DMODEL];
__device__ __nv_bfloat16 g_woh[DMODEL * DMODEL];
__device__ __nv_bfloat16 g_wol[DMODEL * DMODEL];

// ---------------------------------------------------------------------------
// Helpers
// ---------------------------------------------------------------------------
__device__ __forceinline__ void mma_bf16(float* c, const uint32_t* a, const uint32_t* b) {
    asm volatile(
        "mma.sync.aligned.m16n8k16.row.col.f32.bf16.bf16.f32 "
        "{%0,%1,%2,%3}, {%4,%5,%6,%7}, {%8,%9}, {%0,%1,%2,%3};"
        : "+f"(c[0]), "+f"(c[1]), "+f"(c[2]), "+f"(c[3])
        : "r"(a[0]), "r"(a[1]), "r"(a[2]), "r"(a[3]), "r"(b[0]), "r"(b[1]));
}

__device__ __forceinline__ void ldsm_x4(uint32_t& r0, uint32_t& r1, uint32_t& r2,
                                        uint32_t& r3, uint32_t addr) {
    asm volatile("ldmatrix.sync.aligned.m8n8.x4.shared.b16 {%0,%1,%2,%3}, [%4];"
        : "=r"(r0), "=r"(r1), "=r"(r2), "=r"(r3) : "r"(addr));
}

__device__ __forceinline__ void ldsm_x4_t(uint32_t& r0, uint32_t& r1, uint32_t& r2,
                                          uint32_t& r3, uint32_t addr) {
    asm volatile("ldmatrix.sync.aligned.m8n8.x4.trans.shared.b16 {%0,%1,%2,%3}, [%4];"
        : "=r"(r0), "=r"(r1), "=r"(r2), "=r"(r3) : "r"(addr));
}

__device__ __forceinline__ uint32_t smem_u32(const void* p) {
    uint32_t a;
    asm("{ .reg .u64 t; cvta.to.shared.u64 t, %1; cvt.u32.u64 %0, t; }" : "=r"(a) : "l"(p));
    return a;
}

#define CP_ASYNC16(dst, src) \
    asm volatile("cp.async.cg.shared.global [%0], [%1], 16;" :: "r"(dst), "l"(src))
#define CP_COMMIT() asm volatile("cp.async.commit_group;" ::: "memory")
#define CP_WAIT0()  asm volatile("cp.async.wait_group 0;" ::: "memory")
#define CP_WAIT1()  asm volatile("cp.async.wait_group 1;" ::: "memory")

__device__ __forceinline__ void split_bf16(float v, __nv_bfloat16& h, __nv_bfloat16& l) {
    h = __float2bfloat16(v);
    l = __float2bfloat16(v - __bfloat162float(h));
}

// Truncation split of a float pair: hi = top-16-bit bf16s packed via prmt;
// lo = (v - hi) rounded to bf16 pair. h+l == v to ~2^-17.
__device__ __forceinline__ void split_pair_trunc(float v0, float v1,
                                                 uint32_t& hp, uint32_t& lp) {
    uint32_t b0 = __float_as_uint(v0), b1 = __float_as_uint(v1);
    asm("prmt.b32 %0, %1, %2, 0x7632;" : "=r"(hp) : "r"(b0), "r"(b1));
    float l0 = v0 - __uint_as_float(b0 & 0xFFFF0000u);
    float l1 = v1 - __uint_as_float(b1 & 0xFFFF0000u);
    asm("cvt.rn.bf16x2.f32 %0, %1, %2;" : "=r"(lp) : "f"(l1), "f"(l0));
}

// ---------------------------------------------------------------------------
// Prep kernels
// ---------------------------------------------------------------------------
__global__ __launch_bounds__(256) void split_kernel(
    const float* __restrict__ in, __nv_bfloat16* __restrict__ oh,
    __nv_bfloat16* __restrict__ ol, int n4)
{
    int i = blockIdx.x * blockDim.x + threadIdx.x;
    if (i >= n4) return;
    float4 v = ((const float4*)in)[i];
    __nv_bfloat16 h0, h1, h2, h3, l0, l1, l2, l3;
    split_bf16(v.x, h0, l0); split_bf16(v.y, h1, l1);
    split_bf16(v.z, h2, l2); split_bf16(v.w, h3, l3);
    __nv_bfloat162* ph = (__nv_bfloat162*)oh;
    __nv_bfloat162* pl = (__nv_bfloat162*)ol;
    ph[i * 2 + 0] = __halves2bfloat162(h0, h1);
    ph[i * 2 + 1] = __halves2bfloat162(h2, h3);
    pl[i * 2 + 0] = __halves2bfloat162(l0, l1);
    pl[i * 2 + 1] = __halves2bfloat162(l2, l3);
}

__global__ __launch_bounds__(256) void tsplit_kernel(
    const float* __restrict__ in, __nv_bfloat16* __restrict__ oh,
    __nv_bfloat16* __restrict__ ol)
{
    __shared__ float tile[32][33];
    int x = blockIdx.x * 32 + threadIdx.x;
    int y = blockIdx.y * 32 + threadIdx.y;
    #pragma unroll
    for (int j = 0; j < 32; j += 8)
        tile[threadIdx.y + j][threadIdx.x] = in[(size_t)(y + j) * DMODEL + x];
    __syncthreads();
    x = blockIdx.y * 32 + threadIdx.x;
    y = blockIdx.x * 32 + threadIdx.y;
    #pragma unroll
    for (int j = 0; j < 32; j += 8) {
        float v = tile[threadIdx.x][threadIdx.y + j];
        __nv_bfloat16 h, l;
        split_bf16(v, h, l);
        oh[(size_t)(y + j) * DMODEL + x] = h;
        ol[(size_t)(y + j) * DMODEL + x] = l;
    }
}

// ---------------------------------------------------------------------------
// 3-term bf16 GEMM body, cp.async double-buffered.
//   BFOUT=0: C fp32;  BFOUT=1: (Ch, Cl) bf16 hi/lo split.
// CTA tile 128x128, K chunk 32, 8 warps, warp tile 32x64.
// ---------------------------------------------------------------------------
#define GSTRIDE 56
#define GTILE_B (128 * GSTRIDE * 2)            // 14336 bytes
#define GSTAGE_B (4 * GTILE_B)                 // 57344
#define GEMM_SMEM (2 * GSTAGE_B)               // 114688

template<int BFOUT>
__device__ __forceinline__ void gemm_body(
    const __nv_bfloat16* __restrict__ Ah, const __nv_bfloat16* __restrict__ Al,
    const __nv_bfloat16* __restrict__ Bh, const __nv_bfloat16* __restrict__ Bl,
    float* __restrict__ C, __nv_bfloat16* __restrict__ Ch,
    __nv_bfloat16* __restrict__ Cl, float alpha, char* gsm)
{
    const uint32_t smb = smem_u32(gsm);
    const int tid  = threadIdx.x;
    const int lane = tid & 31;
    const int wid  = tid >> 5;
    const int g    = lane >> 2;
    const int tig  = lane & 3;
    const int wrow = (wid & 3) * 32;
    const int wcol = (wid >> 2) * 64;

    const int blockRow = blockIdx.y * 128;
    const int blockCol = blockIdx.x * 128;
    const int K = DMODEL;

    float acc[2][8][4];
    #pragma unroll
    for (int mu = 0; mu < 2; mu++)
        #pragma unroll
        for (int nf = 0; nf < 8; nf++)
            #pragma unroll
            for (int r = 0; r < 4; r++) acc[mu][nf][r] = 0.0f;

    // g2s loader: 8x cp.async(16B) per thread into stage buf
    auto issue_load = [&](int k0, int buf) {
        const uint32_t sb = smb + buf * GSTAGE_B;
        #pragma unroll
        for (int j = 0; j < 2; j++) {
            int idx = tid + j * 256;
            int row = idx >> 2;
            int seg = idx & 3;
            uint32_t soff = (uint32_t)(row * GSTRIDE + seg * 8) * 2;
            size_t goff = (size_t)(blockRow + row) * K + k0 + seg * 8;
            size_t boff = (size_t)(blockCol + row) * K + k0 + seg * 8;
            CP_ASYNC16(sb + soff,               Ah + goff);
            CP_ASYNC16(sb + GTILE_B + soff,     Al + goff);
            CP_ASYNC16(sb + 2 * GTILE_B + soff, Bh + boff);
            CP_ASYNC16(sb + 3 * GTILE_B + soff, Bl + boff);
        }
    };

    issue_load(0, 0);
    CP_COMMIT();

    for (int it = 0; it < 32; it++) {
        if (it + 1 < 32) {
            issue_load((it + 1) * 32, (it + 1) & 1);
            CP_COMMIT();
            CP_WAIT1();
        } else {
            CP_WAIT0();
        }
        __syncthreads();

        char* stage = gsm + (it & 1) * GSTAGE_B;
        uint16_t* sAh = (uint16_t*)stage;
        uint16_t* sAl = (uint16_t*)(stage + GTILE_B);
        uint16_t* sBh = (uint16_t*)(stage + 2 * GTILE_B);
        uint16_t* sBl = (uint16_t*)(stage + 3 * GTILE_B);

        #pragma unroll
        for (int ks = 0; ks < 2; ks++) {
            const int kb = ks * 16;
            uint32_t ah[2][4], al[2][4];
            #pragma unroll
            for (int mu = 0; mu < 2; mu++) {
                const int ra = (wrow + mu * 16 + g) * GSTRIDE + kb + 2 * tig;
                const int rb = (wrow + mu * 16 + g + 8) * GSTRIDE + kb + 2 * tig;
                ah[mu][0] = *(const uint32_t*)&sAh[ra];
                ah[mu][1] = *(const uint32_t*)&sAh[rb];
                ah[mu][2] = *(const uint32_t*)&sAh[ra + 8];
                ah[mu][3] = *(const uint32_t*)&sAh[rb + 8];
                al[mu][0] = *(const uint32_t*)&sAl[ra];
                al[mu][1] = *(const uint32_t*)&sAl[rb];
                al[mu][2] = *(const uint32_t*)&sAl[ra + 8];
                al[mu][3] = *(const uint32_t*)&sAl[rb + 8];
            }
            #pragma unroll
            for (int nf = 0; nf < 8; nf++) {
                const int rn = (wcol + nf * 8 + g) * GSTRIDE + kb + 2 * tig;
                uint32_t bh[2], bl[2];
                bh[0] = *(const uint32_t*)&sBh[rn];
                bh[1] = *(const uint32_t*)&sBh[rn + 8];
                bl[0] = *(const uint32_t*)&sBl[rn];
                bl[1] = *(const uint32_t*)&sBl[rn + 8];
                #pragma unroll
                for (int mu = 0; mu < 2; mu++) {
                    mma_bf16(acc[mu][nf], ah[mu], bh);
                    mma_bf16(acc[mu][nf], al[mu], bh);
                    mma_bf16(acc[mu][nf], ah[mu], bl);
                }
            }
        }
        __syncthreads();
    }

    #pragma unroll
    for (int mu = 0; mu < 2; mu++) {
        #pragma unroll
        for (int nf = 0; nf < 8; nf++) {
            int row0 = blockRow + wrow + mu * 16 + g;
            int col  = blockCol + wcol + nf * 8 + tig * 2;
            float v0 = alpha * acc[mu][nf][0], v1 = alpha * acc[mu][nf][1];
            float v2 = alpha * acc[mu][nf][2], v3 = alpha * acc[mu][nf][3];
            if (BFOUT) {
                __nv_bfloat16 h0, h1, h2, h3, l0, l1, l2, l3;
                split_bf16(v0, h0, l0); split_bf16(v1, h1, l1);
                split_bf16(v2, h2, l2); split_bf16(v3, h3, l3);
                *(__nv_bfloat162*)(Ch + (size_t)row0 * DMODEL + col) = __halves2bfloat162(h0, h1);
                *(__nv_bfloat162*)(Cl + (size_t)row0 * DMODEL + col) = __halves2bfloat162(l0, l1);
                *(__nv_bfloat162*)(Ch + (size_t)(row0 + 8) * DMODEL + col) = __halves2bfloat162(h2, h3);
                *(__nv_bfloat162*)(Cl + (size_t)(row0 + 8) * DMODEL + col) = __halves2bfloat162(l2, l3);
            } else {
                *(float2*)(C + (size_t)row0 * DMODEL + col)       = make_float2(v0, v1);
                *(float2*)(C + (size_t)(row0 + 8) * DMODEL + col) = make_float2(v2, v3);
            }
        }
    }
}

// Batched projection GEMM: z = 0 (q), 1 (k), 2 (v). bf16 hi/lo output.
struct GemmBatch {
    const __nv_bfloat16 *Ah[3], *Al[3], *Bh[3], *Bl[3];
    __nv_bfloat16 *Ch[3], *Cl[3];
    float alpha[3];
};

__global__ __launch_bounds__(256, 2) void bf16_gemm_qkv(GemmBatch gb)
{
    extern __shared__ __align__(16) char gsm[];
    const int z = blockIdx.z;
    gemm_body<1>(gb.Ah[z], gb.Al[z], gb.Bh[z], gb.Bl[z],
                 nullptr, gb.Ch[z], gb.Cl[z], gb.alpha[z], gsm);
}

__global__ __launch_bounds__(256, 2) void bf16_gemm_out(
    const __nv_bfloat16* __restrict__ Ah, const __nv_bfloat16* __restrict__ Al,
    const __nv_bfloat16* __restrict__ Bh, const __nv_bfloat16* __restrict__ Bl,
    float* __restrict__ C)
{
    extern __shared__ __align__(16) char gsm[];
    gemm_body<0>(Ah, Al, Bh, Bl, C, nullptr, nullptr, 1.0f, gsm);
}

// ---------------------------------------------------------------------------
// Full-bf16 flash attention v4: cp.async double-buffered KV pipeline.
// Q frags in registers; P relayouted in registers (truncation split).
// B-fragments via ldmatrix.x4 (K non-trans, V .trans). Stride 72 u16.
// ---------------------------------------------------------------------------
#define KS  72
#define VT  72
#define FL_KH 0
#define FL_KL (64 * KS)
#define FL_VH (2 * 64 * KS)
#define FL_VL (2 * 64 * KS + 64 * VT)
#define FL_STAGE (2 * 64 * KS + 2 * 64 * VT)       // 18432 u16 per stage
#define FLASH_SMEM_BYTES (2 * FL_STAGE * 2)        // 73728

__global__ __launch_bounds__(256, 2) void flash_bf16_kernel(
    const __nv_bfloat16* __restrict__ Qh, const __nv_bfloat16* __restrict__ Ql,
    const __nv_bfloat16* __restrict__ Kg_h, const __nv_bfloat16* __restrict__ Kg_l,
    const __nv_bfloat16* __restrict__ Vg_h, const __nv_bfloat16* __restrict__ Vg_l,
    const float* __restrict__ bias,
    __nv_bfloat16* __restrict__ Oh, __nv_bfloat16* __restrict__ Ol)
{
    extern __shared__ uint16_t fsm[];
    const uint32_t smb = smem_u32(fsm);

    const int tid  = threadIdx.x;
    const int lane = tid & 31;
    const int wid  = tid >> 5;
    const int g    = lane >> 2;
    const int tig  = lane & 3;
    const int sec  = lane >> 3;
    const int rowin = lane & 7;

    const int h = blockIdx.y;
    const int b = blockIdx.z;
    const int qbase = blockIdx.x * 128;
    const int wrow  = wid * 16;

    const uint32_t lane_k = (uint32_t)(((sec >> 1) * 8 + rowin) * KS + (sec & 1) * 8);
    const uint32_t lane_v = (uint32_t)(((sec & 1) * 8 + rowin) * VT + (sec >> 1) * 8);

    // ---- Q fragments in registers (hi/lo), 4 k16 steps ----
    uint32_t qfh[4][4], qfl[4][4];
    {
        const uint16_t* qhp = (const uint16_t*)Qh + (size_t)(b * SEQ + qbase + wrow) * DMODEL + h * DEPTH;
        const uint16_t* qlp = (const uint16_t*)Ql + (size_t)(b * SEQ + qbase + wrow) * DMODEL + h * DEPTH;
        #pragma unroll
        for (int ks = 0; ks < 4; ks++) {
            const int c0 = ks * 16 + 2 * tig;
            qfh[ks][0] = *(const uint32_t*)(qhp + (size_t)g * DMODEL + c0);
            qfh[ks][1] = *(const uint32_t*)(qhp + (size_t)(g + 8) * DMODEL + c0);
            qfh[ks][2] = *(const uint32_t*)(qhp + (size_t)g * DMODEL + c0 + 8);
            qfh[ks][3] = *(const uint32_t*)(qhp + (size_t)(g + 8) * DMODEL + c0 + 8);
            qfl[ks][0] = *(const uint32_t*)(qlp + (size_t)g * DMODEL + c0);
            qfl[ks][1] = *(const uint32_t*)(qlp + (size_t)(g + 8) * DMODEL + c0);
            qfl[ks][2] = *(const uint32_t*)(qlp + (size_t)g * DMODEL + c0 + 8);
            qfl[ks][3] = *(const uint32_t*)(qlp + (size_t)(g + 8) * DMODEL + c0 + 8);
        }
    }

    float o[8][4];
    #pragma unroll
    for (int nf = 0; nf < 8; nf++)
        #pragma unroll
        for (int r = 0; r < 4; r++) o[nf][r] = 0.0f;
    float m0 = -CUDART_INF_F, m1 = -CUDART_INF_F, l0 = 0.f, l1 = 0.f;

    const float* bp0 = bias + (size_t)(qbase + wrow + g) * SEQ;
    const float* bp8 = bias + (size_t)(qbase + wrow + g + 8) * SEQ;

    // KV tile loader: 8x cp.async(16B) per thread into stage buf
    auto load_kv = [&](int kt, int buf) {
        const uint32_t sb = smb + (uint32_t)(buf * FL_STAGE) * 2;
        #pragma unroll
        for (int j = 0; j < 2; j++) {
            int idx = tid + j * 256;
            int row = idx >> 3;
            int seg = idx & 7;
            size_t src = (size_t)(b * SEQ + kt + row) * DMODEL + h * DEPTH + seg * 8;
            uint32_t soff = (uint32_t)(row * KS + seg * 8) * 2;
            CP_ASYNC16(sb + 2 * FL_KH + soff, (const uint16_t*)Kg_h + src);
            CP_ASYNC16(sb + 2 * FL_KL + soff, (const uint16_t*)Kg_l + src);
            CP_ASYNC16(sb + 2 * FL_VH + soff, (const uint16_t*)Vg_h + src);
            CP_ASYNC16(sb + 2 * FL_VL + soff, (const uint16_t*)Vg_l + src);
        }
    };

    load_kv(0, 0);
    CP_COMMIT();

    const int NIT = SEQ / 64;
    for (int it = 0; it < NIT; it++) {
        const int kt = it * 64;
        if (it + 1 < NIT) {
            load_kv(kt + 64, (it + 1) & 1);
            CP_COMMIT();
            CP_WAIT1();
        } else {
            CP_WAIT0();
        }
        __syncthreads();

        const uint32_t sb = smb + (uint32_t)((it & 1) * FL_STAGE) * 2;

        // ---- S = Q @ K^T (3-term bf16) ----
        float s[8][4];
        #pragma unroll
        for (int nf = 0; nf < 8; nf++)
            #pragma unroll
            for (int r = 0; r < 4; r++) s[nf][r] = 0.0f;

        #pragma unroll
        for (int ks = 0; ks < 4; ks++) {
            #pragma unroll
            for (int p = 0; p < 4; p++) {
                const uint32_t off = lane_k + (uint32_t)(p * 16 * KS + ks * 16);
                uint32_t bh[4], bl[4];
                ldsm_x4(bh[0], bh[1], bh[2], bh[3], sb + 2 * (FL_KH + off));
                ldsm_x4(bl[0], bl[1], bl[2], bl[3], sb + 2 * (FL_KL + off));
                mma_bf16(s[2 * p],     qfh[ks], bh);
                mma_bf16(s[2 * p],     qfl[ks], bh);
                mma_bf16(s[2 * p],     qfh[ks], bl);
                mma_bf16(s[2 * p + 1], qfh[ks], bh + 2);
                mma_bf16(s[2 * p + 1], qfl[ks], bh + 2);
                mma_bf16(s[2 * p + 1], qfh[ks], bl + 2);
            }
        }

        // ---- bias + row max ----
        float mx0 = -CUDART_INF_F, mx1 = -CUDART_INF_F;
        #pragma unroll
        for (int nf = 0; nf < 8; nf++) {
            float2 b0 = *(const float2*)(bp0 + kt + nf * 8 + tig * 2);
            float2 b1 = *(const float2*)(bp8 + kt + nf * 8 + tig * 2);
            s[nf][0] += b0.x; s[nf][1] += b0.y;
            s[nf][2] += b1.x; s[nf][3] += b1.y;
            mx0 = fmaxf(mx0, fmaxf(s[nf][0], s[nf][1]));
            mx1 = fmaxf(mx1, fmaxf(s[nf][2], s[nf][3]));
        }
        mx0 = fmaxf(mx0, __shfl_xor_sync(0xFFFFFFFFu, mx0, 1));
        mx0 = fmaxf(mx0, __shfl_xor_sync(0xFFFFFFFFu, mx0, 2));
        mx1 = fmaxf(mx1, __shfl_xor_sync(0xFFFFFFFFu, mx1, 1));
        mx1 = fmaxf(mx1, __shfl_xor_sync(0xFFFFFFFFu, mx1, 2));

        // ---- online softmax; P hi/lo packed straight into A-fragments ----
        float nm0 = fmaxf(m0, mx0), nm1 = fmaxf(m1, mx1);
        float c0f = __expf(m0 - nm0), c1f = __expf(m1 - nm1);
        l0 *= c0f; l1 *= c1f; m0 = nm0; m1 = nm1;
        #pragma unroll
        for (int nf = 0; nf < 8; nf++) {
            o[nf][0] *= c0f; o[nf][1] *= c0f; o[nf][2] *= c1f; o[nf][3] *= c1f;
        }
        uint32_t pfh[4][4], pfl[4][4];
        float la0 = 0.f, la1 = 0.f;
        #pragma unroll
        for (int nf = 0; nf < 8; nf++) {
            float p0 = __expf(s[nf][0] - nm0);
            float p1 = __expf(s[nf][1] - nm0);
            float p2 = __expf(s[nf][2] - nm1);
            float p3 = __expf(s[nf][3] - nm1);
            la0 += p0 + p1; la1 += p2 + p3;
            const int ks = nf >> 1;
            const int rbase = (nf & 1) * 2;
            split_pair_trunc(p0, p1, pfh[ks][rbase + 0], pfl[ks][rbase + 0]);
            split_pair_trunc(p2, p3, pfh[ks][rbase + 1], pfl[ks][rbase + 1]);
        }
        la0 += __shfl_xor_sync(0xFFFFFFFFu, la0, 1);
        la0 += __shfl_xor_sync(0xFFFFFFFFu, la0, 2);
        la1 += __shfl_xor_sync(0xFFFFFFFFu, la1, 1);
        la1 += __shfl_xor_sync(0xFFFFFFFFu, la1, 2);
        l0 += la0; l1 += la1;

        // ---- O += P @ V (3-term bf16); V B-frags via ldmatrix.x4.trans ----
        #pragma unroll
        for (int ks = 0; ks < 4; ks++) {
            #pragma unroll
            for (int p = 0; p < 4; p++) {
                const uint32_t off = lane_v + (uint32_t)(ks * 16 * VT + p * 16);
                uint32_t vh[4], vl[4];
                ldsm_x4_t(vh[0], vh[1], vh[2], vh[3], sb + 2 * (FL_VH + off));
                ldsm_x4_t(vl[0], vl[1], vl[2], vl[3], sb + 2 * (FL_VL + off));
                mma_bf16(o[2 * p],     pfh[ks], vh);
                mma_bf16(o[2 * p],     pfl[ks], vh);
                mma_bf16(o[2 * p],     pfh[ks], vl);
                mma_bf16(o[2 * p + 1], pfh[ks], vh + 2);
                mma_bf16(o[2 * p + 1], pfl[ks], vh + 2);
                mma_bf16(o[2 * p + 1], pfh[ks], vl + 2);
            }
        }
        __syncthreads();
    }

    // ---- epilogue: normalize, hi/lo split, packed bf16 stores ----
    const float inv0 = 1.0f / l0, inv1 = 1.0f / l1;
    uint16_t* ohp0 = (uint16_t*)Oh + (size_t)(b * SEQ + qbase + wrow + g) * DMODEL + h * DEPTH;
    uint16_t* olp0 = (uint16_t*)Ol + (size_t)(b * SEQ + qbase + wrow + g) * DMODEL + h * DEPTH;
    uint16_t* ohp8 = ohp0 + (size_t)8 * DMODEL;
    uint16_t* olp8 = olp0 + (size_t)8 * DMODEL;
    #pragma unroll
    for (int nf = 0; nf < 8; nf++) {
        float v0 = o[nf][0] * inv0, v1 = o[nf][1] * inv0;
        float v2 = o[nf][2] * inv1, v3 = o[nf][3] * inv1;
        uint32_t h01, l01, h23, l23;
        split_pair_trunc(v0, v1, h01, l01);
        split_pair_trunc(v2, v3, h23, l23);
        const int col = nf * 8 + tig * 2;
        *(uint32_t*)(ohp0 + col) = h01;
        *(uint32_t*)(olp0 + col) = l01;
        *(uint32_t*)(ohp8 + col) = h23;
        *(uint32_t*)(olp8 + col) = l23;
    }
}

// ---------------------------------------------------------------------------
// Launch
// ---------------------------------------------------------------------------
extern "C" void kernel_launch(void* const* d_in, const int* in_sizes, int n_in,
                              void* d_out, int out_size)
{
    const float* x    = (const float*)d_in[0];
    const float* y    = (const float*)d_in[1];
    const float* bias = (const float*)d_in[2];
    const float* Wq   = (const float*)d_in[3];
    const float* Wk   = (const float*)d_in[4];
    const float* Wv   = (const float*)d_in[5];
    const float* Wo   = (const float*)d_in[6];
    float* out = (float*)d_out;

    __nv_bfloat16 *ah, *al, *yh, *yl, *qh, *ql, *kh, *kl, *vh, *vl;
    __nv_bfloat16 *wqh, *wql, *wkh, *wkl, *wvh, *wvl, *woh, *wol;
    cudaGetSymbolAddress((void**)&ah,  g_ah);
    cudaGetSymbolAddress((void**)&al,  g_al);
    cudaGetSymbolAddress((void**)&yh,  g_yh);
    cudaGetSymbolAddress((void**)&yl,  g_yl);
    cudaGetSymbolAddress((void**)&qh,  g_qh);
    cudaGetSymbolAddress((void**)&ql,  g_ql);
    cudaGetSymbolAddress((void**)&kh,  g_kh);
    cudaGetSymbolAddress((void**)&kl,  g_kl);
    cudaGetSymbolAddress((void**)&vh,  g_vh);
    cudaGetSymbolAddress((void**)&vl,  g_vl);
    cudaGetSymbolAddress((void**)&wqh, g_wqh);
    cudaGetSymbolAddress((void**)&wql, g_wql);
    cudaGetSymbolAddress((void**)&wkh, g_wkh);
    cudaGetSymbolAddress((void**)&wkl, g_wkl);
    cudaGetSymbolAddress((void**)&wvh, g_wvh);
    cudaGetSymbolAddress((void**)&wvl, g_wvl);
    cudaGetSymbolAddress((void**)&woh, g_woh);
    cudaGetSymbolAddress((void**)&wol, g_wol);

    cudaFuncSetAttribute(flash_bf16_kernel,
                         cudaFuncAttributeMaxDynamicSharedMemorySize, FLASH_SMEM_BYTES);
    cudaFuncSetAttribute(bf16_gemm_qkv,
                         cudaFuncAttributeMaxDynamicSharedMemorySize, GEMM_SMEM);
    cudaFuncSetAttribute(bf16_gemm_out,
                         cudaFuncAttributeMaxDynamicSharedMemorySize, GEMM_SMEM);

    const int n4 = MROWS * DMODEL / 4;
    dim3 sgrid((n4 + 255) / 256);
    split_kernel<<<sgrid, 256, 0, 0>>>(x, ah, al, n4);
    split_kernel<<<sgrid, 256, 0, 0>>>(y, yh, yl, n4);

    dim3 tgrid(32, 32), tblock(32, 8);
    tsplit_kernel<<<tgrid, tblock, 0, 0>>>(Wq, wqh, wql);
    tsplit_kernel<<<tgrid, tblock, 0, 0>>>(Wk, wkh, wkl);
    tsplit_kernel<<<tgrid, tblock, 0, 0>>>(Wv, wvh, wvl);
    tsplit_kernel<<<tgrid, tblock, 0, 0>>>(Wo, woh, wol);

    // Batched q/k/v projections: one launch, grid.z = 3
    GemmBatch gb;
    gb.Ah[0] = ah; gb.Al[0] = al; gb.Bh[0] = wqh; gb.Bl[0] = wql;
    gb.Ch[0] = qh; gb.Cl[0] = ql; gb.alpha[0] = 8.0f;   // * sqrt(depth)
    gb.Ah[1] = yh; gb.Al[1] = yl; gb.Bh[1] = wkh; gb.Bl[1] = wkl;
    gb.Ch[1] = kh; gb.Cl[1] = kl; gb.alpha[1] = 1.0f;
    gb.Ah[2] = yh; gb.Al[2] = yl; gb.Bh[2] = wvh; gb.Bl[2] = wvl;
    gb.Ch[2] = vh; gb.Cl[2] = vl; gb.alpha[2] = 1.0f;

    dim3 qkvgrid(DMODEL / 128, MROWS / 128, 3);   // (8, 32, 3)
    bf16_gemm_qkv<<<qkvgrid, 256, GEMM_SMEM, 0>>>(gb);

    dim3 fgrid(SEQ / 128, NHEADS, BATCH);         // (16, 16, 2)
    flash_bf16_kernel<<<fgrid, 256, FLASH_SMEM_BYTES, 0>>>(
        qh, ql, kh, kl, vh, vl, bias, ah, al);

    dim3 ggrid(DMODEL / 128, MROWS / 128);        // (8, 32)
    bf16_gemm_out<<<ggrid, 256, GEMM_SMEM, 0>>>(ah, al, woh, wol, out);
}

// round 12
// speedup vs baseline: 4.2749x; 1.0189x over previous
#include <cuda_runtime.h>
#include <cuda_bf16.h>
#include <math_constants.h>
#include <cstdint>

// Problem constants (fixed by the reference setup)
#define SEQ    2048
#define DMODEL 1024
#define NHEADS 16
#define DEPTH  64
#define BATCH  2
#define MROWS  (BATCH * SEQ)   // 4096

// Scratch (allocation-free rule: __device__ globals). All bf16 hi/lo pairs.
__device__ __nv_bfloat16 g_ah[MROWS * DMODEL];   // x split, later attn split
__device__ __nv_bfloat16 g_al[MROWS * DMODEL];
__device__ __nv_bfloat16 g_yh[MROWS * DMODEL];
__device__ __nv_bfloat16 g_yl[MROWS * DMODEL];
__device__ __nv_bfloat16 g_qh[MROWS * DMODEL];
__device__ __nv_bfloat16 g_ql[MROWS * DMODEL];
__device__ __nv_bfloat16 g_kh[MROWS * DMODEL];
__device__ __nv_bfloat16 g_kl[MROWS * DMODEL];
__device__ __nv_bfloat16 g_vh[MROWS * DMODEL];
__device__ __nv_bfloat16 g_vl[MROWS * DMODEL];
__device__ __nv_bfloat16 g_wqh[DMODEL * DMODEL];
__device__ __nv_bfloat16 g_wql[DMODEL * DMODEL];
__device__ __nv_bfloat16 g_wkh[DMODEL * DMODEL];
__device__ __nv_bfloat16 g_wkl[DMODEL * DMODEL];
__device__ __nv_bfloat16 g_wvh[DMODEL * DMODEL];
__device__ __nv_bfloat16 g_wvl[DMODEL * DMODEL];
__device__ __nv_bfloat16 g_woh[DMODEL * DMODEL];
__device__ __nv_bfloat16 g_wol[DMODEL * DMODEL];

// ---------------------------------------------------------------------------
// Helpers
// ---------------------------------------------------------------------------
__device__ __forceinline__ void mma_bf16(float* c, const uint32_t* a, const uint32_t* b) {
    asm volatile(
        "mma.sync.aligned.m16n8k16.row.col.f32.bf16.bf16.f32 "
        "{%0,%1,%2,%3}, {%4,%5,%6,%7}, {%8,%9}, {%0,%1,%2,%3};"
        : "+f"(c[0]), "+f"(c[1]), "+f"(c[2]), "+f"(c[3])
        : "r"(a[0]), "r"(a[1]), "r"(a[2]), "r"(a[3]), "r"(b[0]), "r"(b[1]));
}

__device__ __forceinline__ void ldsm_x4(uint32_t& r0, uint32_t& r1, uint32_t& r2,
                                        uint32_t& r3, uint32_t addr) {
    asm volatile("ldmatrix.sync.aligned.m8n8.x4.shared.b16 {%0,%1,%2,%3}, [%4];"
        : "=r"(r0), "=r"(r1), "=r"(r2), "=r"(r3) : "r"(addr));
}

__device__ __forceinline__ void ldsm_x4_t(uint32_t& r0, uint32_t& r1, uint32_t& r2,
                                          uint32_t& r3, uint32_t addr) {
    asm volatile("ldmatrix.sync.aligned.m8n8.x4.trans.shared.b16 {%0,%1,%2,%3}, [%4];"
        : "=r"(r0), "=r"(r1), "=r"(r2), "=r"(r3) : "r"(addr));
}

__device__ __forceinline__ uint32_t smem_u32(const void* p) {
    uint32_t a;
    asm("{ .reg .u64 t; cvta.to.shared.u64 t, %1; cvt.u32.u64 %0, t; }" : "=r"(a) : "l"(p));
    return a;
}

#define CP_ASYNC16(dst, src) \
    asm volatile("cp.async.cg.shared.global [%0], [%1], 16;" :: "r"(dst), "l"(src))
#define CP_COMMIT() asm volatile("cp.async.commit_group;" ::: "memory")
#define CP_WAIT0()  asm volatile("cp.async.wait_group 0;" ::: "memory")
#define CP_WAIT1()  asm volatile("cp.async.wait_group 1;" ::: "memory")

__device__ __forceinline__ void split_bf16(float v, __nv_bfloat16& h, __nv_bfloat16& l) {
    h = __float2bfloat16(v);
    l = __float2bfloat16(v - __bfloat162float(h));
}

// Truncation split of a float pair: hi = top-16-bit bf16s packed via prmt;
// lo = (v - hi) rounded to bf16 pair. h+l == v to ~2^-17.
__device__ __forceinline__ void split_pair_trunc(float v0, float v1,
                                                 uint32_t& hp, uint32_t& lp) {
    uint32_t b0 = __float_as_uint(v0), b1 = __float_as_uint(v1);
    asm("prmt.b32 %0, %1, %2, 0x7632;" : "=r"(hp) : "r"(b0), "r"(b1));
    float l0 = v0 - __uint_as_float(b0 & 0xFFFF0000u);
    float l1 = v1 - __uint_as_float(b1 & 0xFFFF0000u);
    asm("cvt.rn.bf16x2.f32 %0, %1, %2;" : "=r"(lp) : "f"(l1), "f"(l0));
}

// ---------------------------------------------------------------------------
// Prep kernels
// ---------------------------------------------------------------------------
__global__ __launch_bounds__(256) void split_kernel(
    const float* __restrict__ in, __nv_bfloat16* __restrict__ oh,
    __nv_bfloat16* __restrict__ ol, int n4)
{
    int i = blockIdx.x * blockDim.x + threadIdx.x;
    if (i >= n4) return;
    float4 v = ((const float4*)in)[i];
    __nv_bfloat16 h0, h1, h2, h3, l0, l1, l2, l3;
    split_bf16(v.x, h0, l0); split_bf16(v.y, h1, l1);
    split_bf16(v.z, h2, l2); split_bf16(v.w, h3, l3);
    __nv_bfloat162* ph = (__nv_bfloat162*)oh;
    __nv_bfloat162* pl = (__nv_bfloat162*)ol;
    ph[i * 2 + 0] = __halves2bfloat162(h0, h1);
    ph[i * 2 + 1] = __halves2bfloat162(h2, h3);
    pl[i * 2 + 0] = __halves2bfloat162(l0, l1);
    pl[i * 2 + 1] = __halves2bfloat162(l2, l3);
}

__global__ __launch_bounds__(256) void tsplit_kernel(
    const float* __restrict__ in, __nv_bfloat16* __restrict__ oh,
    __nv_bfloat16* __restrict__ ol)
{
    __shared__ float tile[32][33];
    int x = blockIdx.x * 32 + threadIdx.x;
    int y = blockIdx.y * 32 + threadIdx.y;
    #pragma unroll
    for (int j = 0; j < 32; j += 8)
        tile[threadIdx.y + j][threadIdx.x] = in[(size_t)(y + j) * DMODEL + x];
    __syncthreads();
    x = blockIdx.y * 32 + threadIdx.x;
    y = blockIdx.x * 32 + threadIdx.y;
    #pragma unroll
    for (int j = 0; j < 32; j += 8) {
        float v = tile[threadIdx.x][threadIdx.y + j];
        __nv_bfloat16 h, l;
        split_bf16(v, h, l);
        oh[(size_t)(y + j) * DMODEL + x] = h;
        ol[(size_t)(y + j) * DMODEL + x] = l;
    }
}

// ---------------------------------------------------------------------------
// 3-term bf16 GEMM body, cp.async double-buffered + ldmatrix fragments.
//   BFOUT=0: C fp32;  BFOUT=1: (Ch, Cl) bf16 hi/lo split.
// CTA tile 128x128, K chunk 32, 8 warps, warp tile 32x64.
// ---------------------------------------------------------------------------
#define GSTRIDE 56
#define GTILE_B (128 * GSTRIDE * 2)            // 14336 bytes
#define GSTAGE_B (4 * GTILE_B)                 // 57344
#define GEMM_SMEM (2 * GSTAGE_B)               // 114688

template<int BFOUT>
__device__ __forceinline__ void gemm_body(
    const __nv_bfloat16* __restrict__ Ah, const __nv_bfloat16* __restrict__ Al,
    const __nv_bfloat16* __restrict__ Bh, const __nv_bfloat16* __restrict__ Bl,
    float* __restrict__ C, __nv_bfloat16* __restrict__ Ch,
    __nv_bfloat16* __restrict__ Cl, float alpha, char* gsm)
{
    const uint32_t smb = smem_u32(gsm);
    const int tid  = threadIdx.x;
    const int lane = tid & 31;
    const int wid  = tid >> 5;
    const int g    = lane >> 2;
    const int tig  = lane & 3;
    const int sec  = lane >> 3;
    const int rowin = lane & 7;
    const int wrow = (wid & 3) * 32;
    const int wcol = (wid >> 2) * 64;

    const int blockRow = blockIdx.y * 128;
    const int blockCol = blockIdx.x * 128;
    const int K = DMODEL;

    // ldmatrix lane offsets (u16 units, relative to tile base + row/col base)
    // A (m16k16): m0=rows0-7/klo, m1=rows8-15/klo, m2=rows0-7/khi, m3=rows8-15/khi
    const uint32_t lane_a = (uint32_t)(((sec & 1) * 8 + rowin) * GSTRIDE + (sec >> 1) * 8);
    // B (n16k16 pair): m0=n0-7/klo, m1=n0-7/khi, m2=n8-15/klo, m3=n8-15/khi
    const uint32_t lane_b = (uint32_t)(((sec >> 1) * 8 + rowin) * GSTRIDE + (sec & 1) * 8);

    float acc[2][8][4];
    #pragma unroll
    for (int mu = 0; mu < 2; mu++)
        #pragma unroll
        for (int nf = 0; nf < 8; nf++)
            #pragma unroll
            for (int r = 0; r < 4; r++) acc[mu][nf][r] = 0.0f;

    // g2s loader: 8x cp.async(16B) per thread into stage buf
    auto issue_load = [&](int k0, int buf) {
        const uint32_t sb = smb + buf * GSTAGE_B;
        #pragma unroll
        for (int j = 0; j < 2; j++) {
            int idx = tid + j * 256;
            int row = idx >> 2;
            int seg = idx & 3;
            uint32_t soff = (uint32_t)(row * GSTRIDE + seg * 8) * 2;
            size_t goff = (size_t)(blockRow + row) * K + k0 + seg * 8;
            size_t boff = (size_t)(blockCol + row) * K + k0 + seg * 8;
            CP_ASYNC16(sb + soff,               Ah + goff);
            CP_ASYNC16(sb + GTILE_B + soff,     Al + goff);
            CP_ASYNC16(sb + 2 * GTILE_B + soff, Bh + boff);
            CP_ASYNC16(sb + 3 * GTILE_B + soff, Bl + boff);
        }
    };

    issue_load(0, 0);
    CP_COMMIT();

    for (int it = 0; it < 32; it++) {
        if (it + 1 < 32) {
            issue_load((it + 1) * 32, (it + 1) & 1);
            CP_COMMIT();
            CP_WAIT1();
        } else {
            CP_WAIT0();
        }
        __syncthreads();

        const uint32_t sb = smb + (uint32_t)((it & 1) * GSTAGE_B);

        #pragma unroll
        for (int ks = 0; ks < 2; ks++) {
            const int kb = ks * 16;
            uint32_t ah[2][4], al[2][4];
            #pragma unroll
            for (int mu = 0; mu < 2; mu++) {
                const uint32_t abase = (uint32_t)((wrow + mu * 16) * GSTRIDE + kb) + lane_a;
                ldsm_x4(ah[mu][0], ah[mu][1], ah[mu][2], ah[mu][3], sb + 2 * abase);
                ldsm_x4(al[mu][0], al[mu][1], al[mu][2], al[mu][3], sb + GTILE_B + 2 * abase);
            }
            #pragma unroll
            for (int p = 0; p < 4; p++) {
                const uint32_t bbase = (uint32_t)((wcol + p * 16) * GSTRIDE + kb) + lane_b;
                uint32_t bh[4], bl[4];
                ldsm_x4(bh[0], bh[1], bh[2], bh[3], sb + 2 * GTILE_B + 2 * bbase);
                ldsm_x4(bl[0], bl[1], bl[2], bl[3], sb + 3 * GTILE_B + 2 * bbase);
                #pragma unroll
                for (int mu = 0; mu < 2; mu++) {
                    mma_bf16(acc[mu][2 * p],     ah[mu], bh);
                    mma_bf16(acc[mu][2 * p],     al[mu], bh);
                    mma_bf16(acc[mu][2 * p],     ah[mu], bl);
                    mma_bf16(acc[mu][2 * p + 1], ah[mu], bh + 2);
                    mma_bf16(acc[mu][2 * p + 1], al[mu], bh + 2);
                    mma_bf16(acc[mu][2 * p + 1], ah[mu], bl + 2);
                }
            }
        }
        __syncthreads();
    }

    #pragma unroll
    for (int mu = 0; mu < 2; mu++) {
        #pragma unroll
        for (int nf = 0; nf < 8; nf++) {
            int row0 = blockRow + wrow + mu * 16 + g;
            int col  = blockCol + wcol + nf * 8 + tig * 2;
            float v0 = alpha * acc[mu][nf][0], v1 = alpha * acc[mu][nf][1];
            float v2 = alpha * acc[mu][nf][2], v3 = alpha * acc[mu][nf][3];
            if (BFOUT) {
                __nv_bfloat16 h0, h1, h2, h3, l0, l1, l2, l3;
                split_bf16(v0, h0, l0); split_bf16(v1, h1, l1);
                split_bf16(v2, h2, l2); split_bf16(v3, h3, l3);
                *(__nv_bfloat162*)(Ch + (size_t)row0 * DMODEL + col) = __halves2bfloat162(h0, h1);
                *(__nv_bfloat162*)(Cl + (size_t)row0 * DMODEL + col) = __halves2bfloat162(l0, l1);
                *(__nv_bfloat162*)(Ch + (size_t)(row0 + 8) * DMODEL + col) = __halves2bfloat162(h2, h3);
                *(__nv_bfloat162*)(Cl + (size_t)(row0 + 8) * DMODEL + col) = __halves2bfloat162(l2, l3);
            } else {
                *(float2*)(C + (size_t)row0 * DMODEL + col)       = make_float2(v0, v1);
                *(float2*)(C + (size_t)(row0 + 8) * DMODEL + col) = make_float2(v2, v3);
            }
        }
    }
}

// Batched projection GEMM: z = 0 (q), 1 (k), 2 (v). bf16 hi/lo output.
struct GemmBatch {
    const __nv_bfloat16 *Ah[3], *Al[3], *Bh[3], *Bl[3];
    __nv_bfloat16 *Ch[3], *Cl[3];
    float alpha[3];
};

__global__ __launch_bounds__(256, 2) void bf16_gemm_qkv(GemmBatch gb)
{
    extern __shared__ __align__(16) char gsm[];
    const int z = blockIdx.z;
    gemm_body<1>(gb.Ah[z], gb.Al[z], gb.Bh[z], gb.Bl[z],
                 nullptr, gb.Ch[z], gb.Cl[z], gb.alpha[z], gsm);
}

__global__ __launch_bounds__(256, 2) void bf16_gemm_out(
    const __nv_bfloat16* __restrict__ Ah, const __nv_bfloat16* __restrict__ Al,
    const __nv_bfloat16* __restrict__ Bh, const __nv_bfloat16* __restrict__ Bl,
    float* __restrict__ C)
{
    extern __shared__ __align__(16) char gsm[];
    gemm_body<0>(Ah, Al, Bh, Bl, C, nullptr, nullptr, 1.0f, gsm);
}

// ---------------------------------------------------------------------------
// Full-bf16 flash attention v4 (unchanged from R11): cp.async double-buffered
// KV pipeline, Q frags in registers, in-register P relayout, ldmatrix B-frags.
// ---------------------------------------------------------------------------
#define KS  72
#define VT  72
#define FL_KH 0
#define FL_KL (64 * KS)
#define FL_VH (2 * 64 * KS)
#define FL_VL (2 * 64 * KS + 64 * VT)
#define FL_STAGE (2 * 64 * KS + 2 * 64 * VT)       // 18432 u16 per stage
#define FLASH_SMEM_BYTES (2 * FL_STAGE * 2)        // 73728

__global__ __launch_bounds__(256, 2) void flash_bf16_kernel(
    const __nv_bfloat16* __restrict__ Qh, const __nv_bfloat16* __restrict__ Ql,
    const __nv_bfloat16* __restrict__ Kg_h, const __nv_bfloat16* __restrict__ Kg_l,
    const __nv_bfloat16* __restrict__ Vg_h, const __nv_bfloat16* __restrict__ Vg_l,
    const float* __restrict__ bias,
    __nv_bfloat16* __restrict__ Oh, __nv_bfloat16* __restrict__ Ol)
{
    extern __shared__ uint16_t fsm[];
    const uint32_t smb = smem_u32(fsm);

    const int tid  = threadIdx.x;
    const int lane = tid & 31;
    const int wid  = tid >> 5;
    const int g    = lane >> 2;
    const int tig  = lane & 3;
    const int sec  = lane >> 3;
    const int rowin = lane & 7;

    const int h = blockIdx.y;
    const int b = blockIdx.z;
    const int qbase = blockIdx.x * 128;
    const int wrow  = wid * 16;

    const uint32_t lane_k = (uint32_t)(((sec >> 1) * 8 + rowin) * KS + (sec & 1) * 8);
    const uint32_t lane_v = (uint32_t)(((sec & 1) * 8 + rowin) * VT + (sec >> 1) * 8);

    // ---- Q fragments in registers (hi/lo), 4 k16 steps ----
    uint32_t qfh[4][4], qfl[4][4];
    {
        const uint16_t* qhp = (const uint16_t*)Qh + (size_t)(b * SEQ + qbase + wrow) * DMODEL + h * DEPTH;
        const uint16_t* qlp = (const uint16_t*)Ql + (size_t)(b * SEQ + qbase + wrow) * DMODEL + h * DEPTH;
        #pragma unroll
        for (int ks = 0; ks < 4; ks++) {
            const int c0 = ks * 16 + 2 * tig;
            qfh[ks][0] = *(const uint32_t*)(qhp + (size_t)g * DMODEL + c0);
            qfh[ks][1] = *(const uint32_t*)(qhp + (size_t)(g + 8) * DMODEL + c0);
            qfh[ks][2] = *(const uint32_t*)(qhp + (size_t)g * DMODEL + c0 + 8);
            qfh[ks][3] = *(const uint32_t*)(qhp + (size_t)(g + 8) * DMODEL + c0 + 8);
            qfl[ks][0] = *(const uint32_t*)(qlp + (size_t)g * DMODEL + c0);
            qfl[ks][1] = *(const uint32_t*)(qlp + (size_t)(g + 8) * DMODEL + c0);
            qfl[ks][2] = *(const uint32_t*)(qlp + (size_t)g * DMODEL + c0 + 8);
            qfl[ks][3] = *(const uint32_t*)(qlp + (size_t)(g + 8) * DMODEL + c0 + 8);
        }
    }

    float o[8][4];
    #pragma unroll
    for (int nf = 0; nf < 8; nf++)
        #pragma unroll
        for (int r = 0; r < 4; r++) o[nf][r] = 0.0f;
    float m0 = -CUDART_INF_F, m1 = -CUDART_INF_F, l0 = 0.f, l1 = 0.f;

    const float* bp0 = bias + (size_t)(qbase + wrow + g) * SEQ;
    const float* bp8 = bias + (size_t)(qbase + wrow + g + 8) * SEQ;

    // KV tile loader: 8x cp.async(16B) per thread into stage buf
    auto load_kv = [&](int kt, int buf) {
        const uint32_t sb = smb + (uint32_t)(buf * FL_STAGE) * 2;
        #pragma unroll
        for (int j = 0; j < 2; j++) {
            int idx = tid + j * 256;
            int row = idx >> 3;
            int seg = idx & 7;
            size_t src = (size_t)(b * SEQ + kt + row) * DMODEL + h * DEPTH + seg * 8;
            uint32_t soff = (uint32_t)(row * KS + seg * 8) * 2;
            CP_ASYNC16(sb + 2 * FL_KH + soff, (const uint16_t*)Kg_h + src);
            CP_ASYNC16(sb + 2 * FL_KL + soff, (const uint16_t*)Kg_l + src);
            CP_ASYNC16(sb + 2 * FL_VH + soff, (const uint16_t*)Vg_h + src);
            CP_ASYNC16(sb + 2 * FL_VL + soff, (const uint16_t*)Vg_l + src);
        }
    };

    load_kv(0, 0);
    CP_COMMIT();

    const int NIT = SEQ / 64;
    for (int it = 0; it < NIT; it++) {
        const int kt = it * 64;
        if (it + 1 < NIT) {
            load_kv(kt + 64, (it + 1) & 1);
            CP_COMMIT();
            CP_WAIT1();
        } else {
            CP_WAIT0();
        }
        __syncthreads();

        const uint32_t sb = smb + (uint32_t)((it & 1) * FL_STAGE) * 2;

        // ---- S = Q @ K^T (3-term bf16) ----
        float s[8][4];
        #pragma unroll
        for (int nf = 0; nf < 8; nf++)
            #pragma unroll
            for (int r = 0; r < 4; r++) s[nf][r] = 0.0f;

        #pragma unroll
        for (int ks = 0; ks < 4; ks++) {
            #pragma unroll
            for (int p = 0; p < 4; p++) {
                const uint32_t off = lane_k + (uint32_t)(p * 16 * KS + ks * 16);
                uint32_t bh[4], bl[4];
                ldsm_x4(bh[0], bh[1], bh[2], bh[3], sb + 2 * (FL_KH + off));
                ldsm_x4(bl[0], bl[1], bl[2], bl[3], sb + 2 * (FL_KL + off));
                mma_bf16(s[2 * p],     qfh[ks], bh);
                mma_bf16(s[2 * p],     qfl[ks], bh);
                mma_bf16(s[2 * p],     qfh[ks], bl);
                mma_bf16(s[2 * p + 1], qfh[ks], bh + 2);
                mma_bf16(s[2 * p + 1], qfl[ks], bh + 2);
                mma_bf16(s[2 * p + 1], qfh[ks], bl + 2);
            }
        }

        // ---- bias + row max ----
        float mx0 = -CUDART_INF_F, mx1 = -CUDART_INF_F;
        #pragma unroll
        for (int nf = 0; nf < 8; nf++) {
            float2 b0 = *(const float2*)(bp0 + kt + nf * 8 + tig * 2);
            float2 b1 = *(const float2*)(bp8 + kt + nf * 8 + tig * 2);
            s[nf][0] += b0.x; s[nf][1] += b0.y;
            s[nf][2] += b1.x; s[nf][3] += b1.y;
            mx0 = fmaxf(mx0, fmaxf(s[nf][0], s[nf][1]));
            mx1 = fmaxf(mx1, fmaxf(s[nf][2], s[nf][3]));
        }
        mx0 = fmaxf(mx0, __shfl_xor_sync(0xFFFFFFFFu, mx0, 1));
        mx0 = fmaxf(mx0, __shfl_xor_sync(0xFFFFFFFFu, mx0, 2));
        mx1 = fmaxf(mx1, __shfl_xor_sync(0xFFFFFFFFu, mx1, 1));
        mx1 = fmaxf(mx1, __shfl_xor_sync(0xFFFFFFFFu, mx1, 2));

        // ---- online softmax; P hi/lo packed straight into A-fragments ----
        float nm0 = fmaxf(m0, mx0), nm1 = fmaxf(m1, mx1);
        float c0f = __expf(m0 - nm0), c1f = __expf(m1 - nm1);
        l0 *= c0f; l1 *= c1f; m0 = nm0; m1 = nm1;
        #pragma unroll
        for (int nf = 0; nf < 8; nf++) {
            o[nf][0] *= c0f; o[nf][1] *= c0f; o[nf][2] *= c1f; o[nf][3] *= c1f;
        }
        uint32_t pfh[4][4], pfl[4][4];
        float la0 = 0.f, la1 = 0.f;
        #pragma unroll
        for (int nf = 0; nf < 8; nf++) {
            float p0 = __expf(s[nf][0] - nm0);
            float p1 = __expf(s[nf][1] - nm0);
            float p2 = __expf(s[nf][2] - nm1);
            float p3 = __expf(s[nf][3] - nm1);
            la0 += p0 + p1; la1 += p2 + p3;
            const int ks = nf >> 1;
            const int rbase = (nf & 1) * 2;
            split_pair_trunc(p0, p1, pfh[ks][rbase + 0], pfl[ks][rbase + 0]);
            split_pair_trunc(p2, p3, pfh[ks][rbase + 1], pfl[ks][rbase + 1]);
        }
        la0 += __shfl_xor_sync(0xFFFFFFFFu, la0, 1);
        la0 += __shfl_xor_sync(0xFFFFFFFFu, la0, 2);
        la1 += __shfl_xor_sync(0xFFFFFFFFu, la1, 1);
        la1 += __shfl_xor_sync(0xFFFFFFFFu, la1, 2);
        l0 += la0; l1 += la1;

        // ---- O += P @ V (3-term bf16); V B-frags via ldmatrix.x4.trans ----
        #pragma unroll
        for (int ks = 0; ks < 4; ks++) {
            #pragma unroll
            for (int p = 0; p < 4; p++) {
                const uint32_t off = lane_v + (uint32_t)(ks * 16 * VT + p * 16);
                uint32_t vh[4], vl[4];
                ldsm_x4_t(vh[0], vh[1], vh[2], vh[3], sb + 2 * (FL_VH + off));
                ldsm_x4_t(vl[0], vl[1], vl[2], vl[3], sb + 2 * (FL_VL + off));
                mma_bf16(o[2 * p],     pfh[ks], vh);
                mma_bf16(o[2 * p],     pfl[ks], vh);
                mma_bf16(o[2 * p],     pfh[ks], vl);
                mma_bf16(o[2 * p + 1], pfh[ks], vh + 2);
                mma_bf16(o[2 * p + 1], pfl[ks], vh + 2);
                mma_bf16(o[2 * p + 1], pfh[ks], vl + 2);
            }
        }
        __syncthreads();
    }

    // ---- epilogue: normalize, hi/lo split, packed bf16 stores ----
    const float inv0 = 1.0f / l0, inv1 = 1.0f / l1;
    uint16_t* ohp0 = (uint16_t*)Oh + (size_t)(b * SEQ + qbase + wrow + g) * DMODEL + h * DEPTH;
    uint16_t* olp0 = (uint16_t*)Ol + (size_t)(b * SEQ + qbase + wrow + g) * DMODEL + h * DEPTH;
    uint16_t* ohp8 = ohp0 + (size_t)8 * DMODEL;
    uint16_t* olp8 = olp0 + (size_t)8 * DMODEL;
    #pragma unroll
    for (int nf = 0; nf < 8; nf++) {
        float v0 = o[nf][0] * inv0, v1 = o[nf][1] * inv0;
        float v2 = o[nf][2] * inv1, v3 = o[nf][3] * inv1;
        uint32_t h01, l01, h23, l23;
        split_pair_trunc(v0, v1, h01, l01);
        split_pair_trunc(v2, v3, h23, l23);
        const int col = nf * 8 + tig * 2;
        *(uint32_t*)(ohp0 + col) = h01;
        *(uint32_t*)(olp0 + col) = l01;
        *(uint32_t*)(ohp8 + col) = h23;
        *(uint32_t*)(olp8 + col) = l23;
    }
}

// ---------------------------------------------------------------------------
// Launch
// ---------------------------------------------------------------------------
extern "C" void kernel_launch(void* const* d_in, const int* in_sizes, int n_in,
                              void* d_out, int out_size)
{
    const float* x    = (const float*)d_in[0];
    const float* y    = (const float*)d_in[1];
    const float* bias = (const float*)d_in[2];
    const float* Wq   = (const float*)d_in[3];
    const float* Wk   = (const float*)d_in[4];
    const float* Wv   = (const float*)d_in[5];
    const float* Wo   = (const float*)d_in[6];
    float* out = (float*)d_out;

    __nv_bfloat16 *ah, *al, *yh, *yl, *qh, *ql, *kh, *kl, *vh, *vl;
    __nv_bfloat16 *wqh, *wql, *wkh, *wkl, *wvh, *wvl, *woh, *wol;
    cudaGetSymbolAddress((void**)&ah,  g_ah);
    cudaGetSymbolAddress((void**)&al,  g_al);
    cudaGetSymbolAddress((void**)&yh,  g_yh);
    cudaGetSymbolAddress((void**)&yl,  g_yl);
    cudaGetSymbolAddress((void**)&qh,  g_qh);
    cudaGetSymbolAddress((void**)&ql,  g_ql);
    cudaGetSymbolAddress((void**)&kh,  g_kh);
    cudaGetSymbolAddress((void**)&kl,  g_kl);
    cudaGetSymbolAddress((void**)&vh,  g_vh);
    cudaGetSymbolAddress((void**)&vl,  g_vl);
    cudaGetSymbolAddress((void**)&wqh, g_wqh);
    cudaGetSymbolAddress((void**)&wql, g_wql);
    cudaGetSymbolAddress((void**)&wkh, g_wkh);
    cudaGetSymbolAddress((void**)&wkl, g_wkl);
    cudaGetSymbolAddress((void**)&wvh, g_wvh);
    cudaGetSymbolAddress((void**)&wvl, g_wvl);
    cudaGetSymbolAddress((void**)&woh, g_woh);
    cudaGetSymbolAddress((void**)&wol, g_wol);

    cudaFuncSetAttribute(flash_bf16_kernel,
                         cudaFuncAttributeMaxDynamicSharedMemorySize, FLASH_SMEM_BYTES);
    cudaFuncSetAttribute(bf16_gemm_qkv,
                         cudaFuncAttributeMaxDynamicSharedMemorySize, GEMM_SMEM);
    cudaFuncSetAttribute(bf16_gemm_out,
                         cudaFuncAttributeMaxDynamicSharedMemorySize, GEMM_SMEM);

    const int n4 = MROWS * DMODEL / 4;
    dim3 sgrid((n4 + 255) / 256);
    split_kernel<<<sgrid, 256, 0, 0>>>(x, ah, al, n4);
    split_kernel<<<sgrid, 256, 0, 0>>>(y, yh, yl, n4);

    dim3 tgrid(32, 32), tblock(32, 8);
    tsplit_kernel<<<tgrid, tblock, 0, 0>>>(Wq, wqh, wql);
    tsplit_kernel<<<tgrid, tblock, 0, 0>>>(Wk, wkh, wkl);
    tsplit_kernel<<<tgrid, tblock, 0, 0>>>(Wv, wvh, wvl);
    tsplit_kernel<<<tgrid, tblock, 0, 0>>>(Wo, woh, wol);

    // Batched q/k/v projections: one launch, grid.z = 3
    GemmBatch gb;
    gb.Ah[0] = ah; gb.Al[0] = al; gb.Bh[0] = wqh; gb.Bl[0] = wql;
    gb.Ch[0] = qh; gb.Cl[0] = ql; gb.alpha[0] = 8.0f;   // * sqrt(depth)
    gb.Ah[1] = yh; gb.Al[1] = yl; gb.Bh[1] = wkh; gb.Bl[1] = wkl;
    gb.Ch[1] = kh; gb.Cl[1] = kl; gb.alpha[1] = 1.0f;
    gb.Ah[2] = yh; gb.Al[2] = yl; gb.Bh[2] = wvh; gb.Bl[2] = wvl;
    gb.Ch[2] = vh; gb.Cl[2] = vl; gb.alpha[2] = 1.0f;

    dim3 qkvgrid(DMODEL / 128, MROWS / 128, 3);   // (8, 32, 3)
    bf16_gemm_qkv<<<qkvgrid, 256, GEMM_SMEM, 0>>>(gb);

    dim3 fgrid(SEQ / 128, NHEADS, BATCH);         // (16, 16, 2)
    flash_bf16_kernel<<<fgrid, 256, FLASH_SMEM_BYTES, 0>>>(
        qh, ql, kh, kl, vh, vl, bias, ah, al);

    dim3 ggrid(DMODEL / 128, MROWS / 128);        // (8, 32)
    bf16_gemm_out<<<ggrid, 256, GEMM_SMEM, 0>>>(ah, al, woh, wol, out);
}

// round 13
// speedup vs baseline: 4.4300x; 1.0363x over previous
#include <cuda_runtime.h>
#include <cuda_bf16.h>
#include <math_constants.h>
#include <cstdint>

// Problem constants (fixed by the reference setup)
#define SEQ    2048
#define DMODEL 1024
#define NHEADS 16
#define DEPTH  64
#define BATCH  2
#define MROWS  (BATCH * SEQ)   // 4096

// Scratch (allocation-free rule: __device__ globals). All bf16 hi/lo pairs.
__device__ __nv_bfloat16 g_ah[MROWS * DMODEL];   // x split, later attn split
__device__ __nv_bfloat16 g_al[MROWS * DMODEL];
__device__ __nv_bfloat16 g_yh[MROWS * DMODEL];
__device__ __nv_bfloat16 g_yl[MROWS * DMODEL];
__device__ __nv_bfloat16 g_qh[MROWS * DMODEL];
__device__ __nv_bfloat16 g_ql[MROWS * DMODEL];
__device__ __nv_bfloat16 g_kh[MROWS * DMODEL];
__device__ __nv_bfloat16 g_kl[MROWS * DMODEL];
__device__ __nv_bfloat16 g_vh[MROWS * DMODEL];
__device__ __nv_bfloat16 g_vl[MROWS * DMODEL];
__device__ __nv_bfloat16 g_wqh[DMODEL * DMODEL];
__device__ __nv_bfloat16 g_wql[DMODEL * DMODEL];
__device__ __nv_bfloat16 g_wkh[DMODEL * DMODEL];
__device__ __nv_bfloat16 g_wkl[DMODEL * DMODEL];
__device__ __nv_bfloat16 g_wvh[DMODEL * DMODEL];
__device__ __nv_bfloat16 g_wvl[DMODEL * DMODEL];
__device__ __nv_bfloat16 g_woh[DMODEL * DMODEL];
__device__ __nv_bfloat16 g_wol[DMODEL * DMODEL];
__device__ int g_bias_nonzero;

// ---------------------------------------------------------------------------
// Helpers
// ---------------------------------------------------------------------------
__device__ __forceinline__ void mma_bf16(float* c, const uint32_t* a, const uint32_t* b) {
    asm volatile(
        "mma.sync.aligned.m16n8k16.row.col.f32.bf16.bf16.f32 "
        "{%0,%1,%2,%3}, {%4,%5,%6,%7}, {%8,%9}, {%0,%1,%2,%3};"
        : "+f"(c[0]), "+f"(c[1]), "+f"(c[2]), "+f"(c[3])
        : "r"(a[0]), "r"(a[1]), "r"(a[2]), "r"(a[3]), "r"(b[0]), "r"(b[1]));
}

__device__ __forceinline__ void ldsm_x4(uint32_t& r0, uint32_t& r1, uint32_t& r2,
                                        uint32_t& r3, uint32_t addr) {
    asm volatile("ldmatrix.sync.aligned.m8n8.x4.shared.b16 {%0,%1,%2,%3}, [%4];"
        : "=r"(r0), "=r"(r1), "=r"(r2), "=r"(r3) : "r"(addr));
}

__device__ __forceinline__ void ldsm_x4_t(uint32_t& r0, uint32_t& r1, uint32_t& r2,
                                          uint32_t& r3, uint32_t addr) {
    asm volatile("ldmatrix.sync.aligned.m8n8.x4.trans.shared.b16 {%0,%1,%2,%3}, [%4];"
        : "=r"(r0), "=r"(r1), "=r"(r2), "=r"(r3) : "r"(addr));
}

__device__ __forceinline__ uint32_t smem_u32(const void* p) {
    uint32_t a;
    asm("{ .reg .u64 t; cvta.to.shared.u64 t, %1; cvt.u32.u64 %0, t; }" : "=r"(a) : "l"(p));
    return a;
}

#define CP_ASYNC16(dst, src) \
    asm volatile("cp.async.cg.shared.global [%0], [%1], 16;" :: "r"(dst), "l"(src))
#define CP_COMMIT() asm volatile("cp.async.commit_group;" ::: "memory")
#define CP_WAIT0()  asm volatile("cp.async.wait_group 0;" ::: "memory")
#define CP_WAIT1()  asm volatile("cp.async.wait_group 1;" ::: "memory")

__device__ __forceinline__ void split_bf16(float v, __nv_bfloat16& h, __nv_bfloat16& l) {
    h = __float2bfloat16(v);
    l = __float2bfloat16(v - __bfloat162float(h));
}

// Truncation split of a float pair: hi = top-16-bit bf16s packed via prmt;
// lo = (v - hi) rounded to bf16 pair. h+l == v to ~2^-17.
__device__ __forceinline__ void split_pair_trunc(float v0, float v1,
                                                 uint32_t& hp, uint32_t& lp) {
    uint32_t b0 = __float_as_uint(v0), b1 = __float_as_uint(v1);
    asm("prmt.b32 %0, %1, %2, 0x7632;" : "=r"(hp) : "r"(b0), "r"(b1));
    float l0 = v0 - __uint_as_float(b0 & 0xFFFF0000u);
    float l1 = v1 - __uint_as_float(b1 & 0xFFFF0000u);
    asm("cvt.rn.bf16x2.f32 %0, %1, %2;" : "=r"(lp) : "f"(l1), "f"(l0));
}

// ---------------------------------------------------------------------------
// Bias zero-detection (correct for arbitrary bias; fast path when all-zero)
// ---------------------------------------------------------------------------
__global__ void reset_flag_kernel() { g_bias_nonzero = 0; }

__global__ __launch_bounds__(256) void bias_check_kernel(
    const float* __restrict__ bias, int n4)
{
    int i = blockIdx.x * blockDim.x + threadIdx.x;
    int stride = gridDim.x * blockDim.x;
    int local = 0;
    for (; i < n4; i += stride) {
        float4 v = ((const float4*)bias)[i];
        if (v.x != 0.f || v.y != 0.f || v.z != 0.f || v.w != 0.f) { local = 1; break; }
    }
    if (__syncthreads_or(local))
        if (threadIdx.x == 0) atomicOr(&g_bias_nonzero, 1);
}

// ---------------------------------------------------------------------------
// Prep kernels (batched)
// ---------------------------------------------------------------------------
struct SplitBatch {
    const float* in[2];
    __nv_bfloat16 *oh[2], *ol[2];
};

__global__ __launch_bounds__(256) void split_kernel(SplitBatch sb, int n4)
{
    int i = blockIdx.x * blockDim.x + threadIdx.x;
    if (i >= n4) return;
    const int z = blockIdx.z;
    float4 v = ((const float4*)sb.in[z])[i];
    __nv_bfloat16 h0, h1, h2, h3, l0, l1, l2, l3;
    split_bf16(v.x, h0, l0); split_bf16(v.y, h1, l1);
    split_bf16(v.z, h2, l2); split_bf16(v.w, h3, l3);
    __nv_bfloat162* ph = (__nv_bfloat162*)sb.oh[z];
    __nv_bfloat162* pl = (__nv_bfloat162*)sb.ol[z];
    ph[i * 2 + 0] = __halves2bfloat162(h0, h1);
    ph[i * 2 + 1] = __halves2bfloat162(h2, h3);
    pl[i * 2 + 0] = __halves2bfloat162(l0, l1);
    pl[i * 2 + 1] = __halves2bfloat162(l2, l3);
}

struct TsplitBatch {
    const float* in[4];
    __nv_bfloat16 *oh[4], *ol[4];
};

__global__ __launch_bounds__(256) void tsplit_kernel(TsplitBatch tb)
{
    __shared__ float tile[32][33];
    const int z = blockIdx.z;
    const float* in = tb.in[z];
    __nv_bfloat16* oh = tb.oh[z];
    __nv_bfloat16* ol = tb.ol[z];
    int x = blockIdx.x * 32 + threadIdx.x;
    int y = blockIdx.y * 32 + threadIdx.y;
    #pragma unroll
    for (int j = 0; j < 32; j += 8)
        tile[threadIdx.y + j][threadIdx.x] = in[(size_t)(y + j) * DMODEL + x];
    __syncthreads();
    x = blockIdx.y * 32 + threadIdx.x;
    y = blockIdx.x * 32 + threadIdx.y;
    #pragma unroll
    for (int j = 0; j < 32; j += 8) {
        float v = tile[threadIdx.x][threadIdx.y + j];
        __nv_bfloat16 h, l;
        split_bf16(v, h, l);
        oh[(size_t)(y + j) * DMODEL + x] = h;
        ol[(size_t)(y + j) * DMODEL + x] = l;
    }
}

// ---------------------------------------------------------------------------
// 3-term bf16 GEMM body, cp.async double-buffered + ldmatrix fragments.
// ---------------------------------------------------------------------------
#define GSTRIDE 56
#define GTILE_B (128 * GSTRIDE * 2)            // 14336 bytes
#define GSTAGE_B (4 * GTILE_B)                 // 57344
#define GEMM_SMEM (2 * GSTAGE_B)               // 114688

template<int BFOUT>
__device__ __forceinline__ void gemm_body(
    const __nv_bfloat16* __restrict__ Ah, const __nv_bfloat16* __restrict__ Al,
    const __nv_bfloat16* __restrict__ Bh, const __nv_bfloat16* __restrict__ Bl,
    float* __restrict__ C, __nv_bfloat16* __restrict__ Ch,
    __nv_bfloat16* __restrict__ Cl, float alpha, char* gsm)
{
    const uint32_t smb = smem_u32(gsm);
    const int tid  = threadIdx.x;
    const int lane = tid & 31;
    const int wid  = tid >> 5;
    const int g    = lane >> 2;
    const int tig  = lane & 3;
    const int sec  = lane >> 3;
    const int rowin = lane & 7;
    const int wrow = (wid & 3) * 32;
    const int wcol = (wid >> 2) * 64;

    const int blockRow = blockIdx.y * 128;
    const int blockCol = blockIdx.x * 128;
    const int K = DMODEL;

    const uint32_t lane_a = (uint32_t)(((sec & 1) * 8 + rowin) * GSTRIDE + (sec >> 1) * 8);
    const uint32_t lane_b = (uint32_t)(((sec >> 1) * 8 + rowin) * GSTRIDE + (sec & 1) * 8);

    float acc[2][8][4];
    #pragma unroll
    for (int mu = 0; mu < 2; mu++)
        #pragma unroll
        for (int nf = 0; nf < 8; nf++)
            #pragma unroll
            for (int r = 0; r < 4; r++) acc[mu][nf][r] = 0.0f;

    auto issue_load = [&](int k0, int buf) {
        const uint32_t sb = smb + buf * GSTAGE_B;
        #pragma unroll
        for (int j = 0; j < 2; j++) {
            int idx = tid + j * 256;
            int row = idx >> 2;
            int seg = idx & 3;
            uint32_t soff = (uint32_t)(row * GSTRIDE + seg * 8) * 2;
            size_t goff = (size_t)(blockRow + row) * K + k0 + seg * 8;
            size_t boff = (size_t)(blockCol + row) * K + k0 + seg * 8;
            CP_ASYNC16(sb + soff,               Ah + goff);
            CP_ASYNC16(sb + GTILE_B + soff,     Al + goff);
            CP_ASYNC16(sb + 2 * GTILE_B + soff, Bh + boff);
            CP_ASYNC16(sb + 3 * GTILE_B + soff, Bl + boff);
        }
    };

    issue_load(0, 0);
    CP_COMMIT();

    for (int it = 0; it < 32; it++) {
        if (it + 1 < 32) {
            issue_load((it + 1) * 32, (it + 1) & 1);
            CP_COMMIT();
            CP_WAIT1();
        } else {
            CP_WAIT0();
        }
        __syncthreads();

        const uint32_t sb = smb + (uint32_t)((it & 1) * GSTAGE_B);

        #pragma unroll
        for (int ks = 0; ks < 2; ks++) {
            const int kb = ks * 16;
            uint32_t ah[2][4], al[2][4];
            #pragma unroll
            for (int mu = 0; mu < 2; mu++) {
                const uint32_t abase = (uint32_t)((wrow + mu * 16) * GSTRIDE + kb) + lane_a;
                ldsm_x4(ah[mu][0], ah[mu][1], ah[mu][2], ah[mu][3], sb + 2 * abase);
                ldsm_x4(al[mu][0], al[mu][1], al[mu][2], al[mu][3], sb + GTILE_B + 2 * abase);
            }
            #pragma unroll
            for (int p = 0; p < 4; p++) {
                const uint32_t bbase = (uint32_t)((wcol + p * 16) * GSTRIDE + kb) + lane_b;
                uint32_t bh[4], bl[4];
                ldsm_x4(bh[0], bh[1], bh[2], bh[3], sb + 2 * GTILE_B + 2 * bbase);
                ldsm_x4(bl[0], bl[1], bl[2], bl[3], sb + 3 * GTILE_B + 2 * bbase);
                #pragma unroll
                for (int mu = 0; mu < 2; mu++) {
                    mma_bf16(acc[mu][2 * p],     ah[mu], bh);
                    mma_bf16(acc[mu][2 * p],     al[mu], bh);
                    mma_bf16(acc[mu][2 * p],     ah[mu], bl);
                    mma_bf16(acc[mu][2 * p + 1], ah[mu], bh + 2);
                    mma_bf16(acc[mu][2 * p + 1], al[mu], bh + 2);
                    mma_bf16(acc[mu][2 * p + 1], ah[mu], bl + 2);
                }
            }
        }
        __syncthreads();
    }

    #pragma unroll
    for (int mu = 0; mu < 2; mu++) {
        #pragma unroll
        for (int nf = 0; nf < 8; nf++) {
            int row0 = blockRow + wrow + mu * 16 + g;
            int col  = blockCol + wcol + nf * 8 + tig * 2;
            float v0 = alpha * acc[mu][nf][0], v1 = alpha * acc[mu][nf][1];
            float v2 = alpha * acc[mu][nf][2], v3 = alpha * acc[mu][nf][3];
            if (BFOUT) {
                __nv_bfloat16 h0, h1, h2, h3, l0, l1, l2, l3;
                split_bf16(v0, h0, l0); split_bf16(v1, h1, l1);
                split_bf16(v2, h2, l2); split_bf16(v3, h3, l3);
                *(__nv_bfloat162*)(Ch + (size_t)row0 * DMODEL + col) = __halves2bfloat162(h0, h1);
                *(__nv_bfloat162*)(Cl + (size_t)row0 * DMODEL + col) = __halves2bfloat162(l0, l1);
                *(__nv_bfloat162*)(Ch + (size_t)(row0 + 8) * DMODEL + col) = __halves2bfloat162(h2, h3);
                *(__nv_bfloat162*)(Cl + (size_t)(row0 + 8) * DMODEL + col) = __halves2bfloat162(l2, l3);
            } else {
                *(float2*)(C + (size_t)row0 * DMODEL + col)       = make_float2(v0, v1);
                *(float2*)(C + (size_t)(row0 + 8) * DMODEL + col) = make_float2(v2, v3);
            }
        }
    }
}

struct GemmBatch {
    const __nv_bfloat16 *Ah[3], *Al[3], *Bh[3], *Bl[3];
    __nv_bfloat16 *Ch[3], *Cl[3];
    float alpha[3];
};

__global__ __launch_bounds__(256, 2) void bf16_gemm_qkv(GemmBatch gb)
{
    extern __shared__ __align__(16) char gsm[];
    const int z = blockIdx.z;
    gemm_body<1>(gb.Ah[z], gb.Al[z], gb.Bh[z], gb.Bl[z],
                 nullptr, gb.Ch[z], gb.Cl[z], gb.alpha[z], gsm);
}

__global__ __launch_bounds__(256, 2) void bf16_gemm_out(
    const __nv_bfloat16* __restrict__ Ah, const __nv_bfloat16* __restrict__ Al,
    const __nv_bfloat16* __restrict__ Bh, const __nv_bfloat16* __restrict__ Bl,
    float* __restrict__ C)
{
    extern __shared__ __align__(16) char gsm[];
    gemm_body<0>(Ah, Al, Bh, Bl, C, nullptr, nullptr, 1.0f, gsm);
}

// ---------------------------------------------------------------------------
// Full-bf16 flash attention v5: v4 + zero-bias fast path.
// ---------------------------------------------------------------------------
#define KS  72
#define VT  72
#define FL_KH 0
#define FL_KL (64 * KS)
#define FL_VH (2 * 64 * KS)
#define FL_VL (2 * 64 * KS + 64 * VT)
#define FL_STAGE (2 * 64 * KS + 2 * 64 * VT)       // 18432 u16 per stage
#define FLASH_SMEM_BYTES (2 * FL_STAGE * 2)        // 73728

__global__ __launch_bounds__(256, 2) void flash_bf16_kernel(
    const __nv_bfloat16* __restrict__ Qh, const __nv_bfloat16* __restrict__ Ql,
    const __nv_bfloat16* __restrict__ Kg_h, const __nv_bfloat16* __restrict__ Kg_l,
    const __nv_bfloat16* __restrict__ Vg_h, const __nv_bfloat16* __restrict__ Vg_l,
    const float* __restrict__ bias,
    __nv_bfloat16* __restrict__ Oh, __nv_bfloat16* __restrict__ Ol)
{
    extern __shared__ uint16_t fsm[];
    const uint32_t smb = smem_u32(fsm);

    const int tid  = threadIdx.x;
    const int lane = tid & 31;
    const int wid  = tid >> 5;
    const int g    = lane >> 2;
    const int tig  = lane & 3;
    const int sec  = lane >> 3;
    const int rowin = lane & 7;

    const int h = blockIdx.y;
    const int b = blockIdx.z;
    const int qbase = blockIdx.x * 128;
    const int wrow  = wid * 16;

    const int bias_on = g_bias_nonzero;

    const uint32_t lane_k = (uint32_t)(((sec >> 1) * 8 + rowin) * KS + (sec & 1) * 8);
    const uint32_t lane_v = (uint32_t)(((sec & 1) * 8 + rowin) * VT + (sec >> 1) * 8);

    // ---- Q fragments in registers (hi/lo), 4 k16 steps ----
    uint32_t qfh[4][4], qfl[4][4];
    {
        const uint16_t* qhp = (const uint16_t*)Qh + (size_t)(b * SEQ + qbase + wrow) * DMODEL + h * DEPTH;
        const uint16_t* qlp = (const uint16_t*)Ql + (size_t)(b * SEQ + qbase + wrow) * DMODEL + h * DEPTH;
        #pragma unroll
        for (int ks = 0; ks < 4; ks++) {
            const int c0 = ks * 16 + 2 * tig;
            qfh[ks][0] = *(const uint32_t*)(qhp + (size_t)g * DMODEL + c0);
            qfh[ks][1] = *(const uint32_t*)(qhp + (size_t)(g + 8) * DMODEL + c0);
            qfh[ks][2] = *(const uint32_t*)(qhp + (size_t)g * DMODEL + c0 + 8);
            qfh[ks][3] = *(const uint32_t*)(qhp + (size_t)(g + 8) * DMODEL + c0 + 8);
            qfl[ks][0] = *(const uint32_t*)(qlp + (size_t)g * DMODEL + c0);
            qfl[ks][1] = *(const uint32_t*)(qlp + (size_t)(g + 8) * DMODEL + c0);
            qfl[ks][2] = *(const uint32_t*)(qlp + (size_t)g * DMODEL + c0 + 8);
            qfl[ks][3] = *(const uint32_t*)(qlp + (size_t)(g + 8) * DMODEL + c0 + 8);
        }
    }

    float o[8][4];
    #pragma unroll
    for (int nf = 0; nf < 8; nf++)
        #pragma unroll
        for (int r = 0; r < 4; r++) o[nf][r] = 0.0f;
    float m0 = -CUDART_INF_F, m1 = -CUDART_INF_F, l0 = 0.f, l1 = 0.f;

    const float* bp0 = bias + (size_t)(qbase + wrow + g) * SEQ;
    const float* bp8 = bias + (size_t)(qbase + wrow + g + 8) * SEQ;

    auto load_kv = [&](int kt, int buf) {
        const uint32_t sb = smb + (uint32_t)(buf * FL_STAGE) * 2;
        #pragma unroll
        for (int j = 0; j < 2; j++) {
            int idx = tid + j * 256;
            int row = idx >> 3;
            int seg = idx & 7;
            size_t src = (size_t)(b * SEQ + kt + row) * DMODEL + h * DEPTH + seg * 8;
            uint32_t soff = (uint32_t)(row * KS + seg * 8) * 2;
            CP_ASYNC16(sb + 2 * FL_KH + soff, (const uint16_t*)Kg_h + src);
            CP_ASYNC16(sb + 2 * FL_KL + soff, (const uint16_t*)Kg_l + src);
            CP_ASYNC16(sb + 2 * FL_VH + soff, (const uint16_t*)Vg_h + src);
            CP_ASYNC16(sb + 2 * FL_VL + soff, (const uint16_t*)Vg_l + src);
        }
    };

    load_kv(0, 0);
    CP_COMMIT();

    const int NIT = SEQ / 64;
    for (int it = 0; it < NIT; it++) {
        const int kt = it * 64;
        if (it + 1 < NIT) {
            load_kv(kt + 64, (it + 1) & 1);
            CP_COMMIT();
            CP_WAIT1();
        } else {
            CP_WAIT0();
        }
        __syncthreads();

        const uint32_t sb = smb + (uint32_t)((it & 1) * FL_STAGE) * 2;

        // ---- S = Q @ K^T (3-term bf16) ----
        float s[8][4];
        #pragma unroll
        for (int nf = 0; nf < 8; nf++)
            #pragma unroll
            for (int r = 0; r < 4; r++) s[nf][r] = 0.0f;

        #pragma unroll
        for (int ks = 0; ks < 4; ks++) {
            #pragma unroll
            for (int p = 0; p < 4; p++) {
                const uint32_t off = lane_k + (uint32_t)(p * 16 * KS + ks * 16);
                uint32_t bh[4], bl[4];
                ldsm_x4(bh[0], bh[1], bh[2], bh[3], sb + 2 * (FL_KH + off));
                ldsm_x4(bl[0], bl[1], bl[2], bl[3], sb + 2 * (FL_KL + off));
                mma_bf16(s[2 * p],     qfh[ks], bh);
                mma_bf16(s[2 * p],     qfl[ks], bh);
                mma_bf16(s[2 * p],     qfh[ks], bl);
                mma_bf16(s[2 * p + 1], qfh[ks], bh + 2);
                mma_bf16(s[2 * p + 1], qfl[ks], bh + 2);
                mma_bf16(s[2 * p + 1], qfh[ks], bl + 2);
            }
        }

        // ---- bias (only when nonzero) + row max ----
        float mx0 = -CUDART_INF_F, mx1 = -CUDART_INF_F;
        if (bias_on) {
            #pragma unroll
            for (int nf = 0; nf < 8; nf++) {
                float2 b0 = *(const float2*)(bp0 + kt + nf * 8 + tig * 2);
                float2 b1 = *(const float2*)(bp8 + kt + nf * 8 + tig * 2);
                s[nf][0] += b0.x; s[nf][1] += b0.y;
                s[nf][2] += b1.x; s[nf][3] += b1.y;
            }
        }
        #pragma unroll
        for (int nf = 0; nf < 8; nf++) {
            mx0 = fmaxf(mx0, fmaxf(s[nf][0], s[nf][1]));
            mx1 = fmaxf(mx1, fmaxf(s[nf][2], s[nf][3]));
        }
        mx0 = fmaxf(mx0, __shfl_xor_sync(0xFFFFFFFFu, mx0, 1));
        mx0 = fmaxf(mx0, __shfl_xor_sync(0xFFFFFFFFu, mx0, 2));
        mx1 = fmaxf(mx1, __shfl_xor_sync(0xFFFFFFFFu, mx1, 1));
        mx1 = fmaxf(mx1, __shfl_xor_sync(0xFFFFFFFFu, mx1, 2));

        // ---- online softmax; P hi/lo packed straight into A-fragments ----
        float nm0 = fmaxf(m0, mx0), nm1 = fmaxf(m1, mx1);
        float c0f = __expf(m0 - nm0), c1f = __expf(m1 - nm1);
        l0 *= c0f; l1 *= c1f; m0 = nm0; m1 = nm1;
        #pragma unroll
        for (int nf = 0; nf < 8; nf++) {
            o[nf][0] *= c0f; o[nf][1] *= c0f; o[nf][2] *= c1f; o[nf][3] *= c1f;
        }
        uint32_t pfh[4][4], pfl[4][4];
        float la0 = 0.f, la1 = 0.f;
        #pragma unroll
        for (int nf = 0; nf < 8; nf++) {
            float p0 = __expf(s[nf][0] - nm0);
            float p1 = __expf(s[nf][1] - nm0);
            float p2 = __expf(s[nf][2] - nm1);
            float p3 = __expf(s[nf][3] - nm1);
            la0 += p0 + p1; la1 += p2 + p3;
            const int ks = nf >> 1;
            const int rbase = (nf & 1) * 2;
            split_pair_trunc(p0, p1, pfh[ks][rbase + 0], pfl[ks][rbase + 0]);
            split_pair_trunc(p2, p3, pfh[ks][rbase + 1], pfl[ks][rbase + 1]);
        }
        la0 += __shfl_xor_sync(0xFFFFFFFFu, la0, 1);
        la0 += __shfl_xor_sync(0xFFFFFFFFu, la0, 2);
        la1 += __shfl_xor_sync(0xFFFFFFFFu, la1, 1);
        la1 += __shfl_xor_sync(0xFFFFFFFFu, la1, 2);
        l0 += la0; l1 += la1;

        // ---- O += P @ V (3-term bf16); V B-frags via ldmatrix.x4.trans ----
        #pragma unroll
        for (int ks = 0; ks < 4; ks++) {
            #pragma unroll
            for (int p = 0; p < 4; p++) {
                const uint32_t off = lane_v + (uint32_t)(ks * 16 * VT + p * 16);
                uint32_t vh[4], vl[4];
                ldsm_x4_t(vh[0], vh[1], vh[2], vh[3], sb + 2 * (FL_VH + off));
                ldsm_x4_t(vl[0], vl[1], vl[2], vl[3], sb + 2 * (FL_VL + off));
                mma_bf16(o[2 * p],     pfh[ks], vh);
                mma_bf16(o[2 * p],     pfl[ks], vh);
                mma_bf16(o[2 * p],     pfh[ks], vl);
                mma_bf16(o[2 * p + 1], pfh[ks], vh + 2);
                mma_bf16(o[2 * p + 1], pfl[ks], vh + 2);
                mma_bf16(o[2 * p + 1], pfh[ks], vl + 2);
            }
        }
        __syncthreads();
    }

    // ---- epilogue: normalize, hi/lo split, packed bf16 stores ----
    const float inv0 = 1.0f / l0, inv1 = 1.0f / l1;
    uint16_t* ohp0 = (uint16_t*)Oh + (size_t)(b * SEQ + qbase + wrow + g) * DMODEL + h * DEPTH;
    uint16_t* olp0 = (uint16_t*)Ol + (size_t)(b * SEQ + qbase + wrow + g) * DMODEL + h * DEPTH;
    uint16_t* ohp8 = ohp0 + (size_t)8 * DMODEL;
    uint16_t* olp8 = olp0 + (size_t)8 * DMODEL;
    #pragma unroll
    for (int nf = 0; nf < 8; nf++) {
        float v0 = o[nf][0] * inv0, v1 = o[nf][1] * inv0;
        float v2 = o[nf][2] * inv1, v3 = o[nf][3] * inv1;
        uint32_t h01, l01, h23, l23;
        split_pair_trunc(v0, v1, h01, l01);
        split_pair_trunc(v2, v3, h23, l23);
        const int col = nf * 8 + tig * 2;
        *(uint32_t*)(ohp0 + col) = h01;
        *(uint32_t*)(olp0 + col) = l01;
        *(uint32_t*)(ohp8 + col) = h23;
        *(uint32_t*)(olp8 + col) = l23;
    }
}

// ---------------------------------------------------------------------------
// Launch
// ---------------------------------------------------------------------------
extern "C" void kernel_launch(void* const* d_in, const int* in_sizes, int n_in,
                              void* d_out, int out_size)
{
    const float* x    = (const float*)d_in[0];
    const float* y    = (const float*)d_in[1];
    const float* bias = (const float*)d_in[2];
    const float* Wq   = (const float*)d_in[3];
    const float* Wk   = (const float*)d_in[4];
    const float* Wv   = (const float*)d_in[5];
    const float* Wo   = (const float*)d_in[6];
    float* out = (float*)d_out;

    __nv_bfloat16 *ah, *al, *yh, *yl, *qh, *ql, *kh, *kl, *vh, *vl;
    __nv_bfloat16 *wqh, *wql, *wkh, *wkl, *wvh, *wvl, *woh, *wol;
    cudaGetSymbolAddress((void**)&ah,  g_ah);
    cudaGetSymbolAddress((void**)&al,  g_al);
    cudaGetSymbolAddress((void**)&yh,  g_yh);
    cudaGetSymbolAddress((void**)&yl,  g_yl);
    cudaGetSymbolAddress((void**)&qh,  g_qh);
    cudaGetSymbolAddress((void**)&ql,  g_ql);
    cudaGetSymbolAddress((void**)&kh,  g_kh);
    cudaGetSymbolAddress((void**)&kl,  g_kl);
    cudaGetSymbolAddress((void**)&vh,  g_vh);
    cudaGetSymbolAddress((void**)&vl,  g_vl);
    cudaGetSymbolAddress((void**)&wqh, g_wqh);
    cudaGetSymbolAddress((void**)&wql, g_wql);
    cudaGetSymbolAddress((void**)&wkh, g_wkh);
    cudaGetSymbolAddress((void**)&wkl, g_wkl);
    cudaGetSymbolAddress((void**)&wvh, g_wvh);
    cudaGetSymbolAddress((void**)&wvl, g_wvl);
    cudaGetSymbolAddress((void**)&woh, g_woh);
    cudaGetSymbolAddress((void**)&wol, g_wol);

    cudaFuncSetAttribute(flash_bf16_kernel,
                         cudaFuncAttributeMaxDynamicSharedMemorySize, FLASH_SMEM_BYTES);
    cudaFuncSetAttribute(bf16_gemm_qkv,
                         cudaFuncAttributeMaxDynamicSharedMemorySize, GEMM_SMEM);
    cudaFuncSetAttribute(bf16_gemm_out,
                         cudaFuncAttributeMaxDynamicSharedMemorySize, GEMM_SMEM);

    // Bias zero-detection (fast path trigger; correct for any input)
    reset_flag_kernel<<<1, 1, 0, 0>>>();
    bias_check_kernel<<<256, 256, 0, 0>>>(bias, SEQ * SEQ / 4);

    // Batched prep: x & y splits (grid.z=2), 4 weight transpose-splits (grid.z=4)
    const int n4 = MROWS * DMODEL / 4;
    SplitBatch sb;
    sb.in[0] = x; sb.oh[0] = ah; sb.ol[0] = al;
    sb.in[1] = y; sb.oh[1] = yh; sb.ol[1] = yl;
    dim3 sgrid((n4 + 255) / 256, 1, 2);
    split_kernel<<<sgrid, 256, 0, 0>>>(sb, n4);

    TsplitBatch tb;
    tb.in[0] = Wq; tb.oh[0] = wqh; tb.ol[0] = wql;
    tb.in[1] = Wk; tb.oh[1] = wkh; tb.ol[1] = wkl;
    tb.in[2] = Wv; tb.oh[2] = wvh; tb.ol[2] = wvl;
    tb.in[3] = Wo; tb.oh[3] = woh; tb.ol[3] = wol;
    dim3 tgrid(32, 32, 4), tblock(32, 8);
    tsplit_kernel<<<tgrid, tblock, 0, 0>>>(tb);

    // Batched q/k/v projections: one launch, grid.z = 3
    GemmBatch gb;
    gb.Ah[0] = ah; gb.Al[0] = al; gb.Bh[0] = wqh; gb.Bl[0] = wql;
    gb.Ch[0] = qh; gb.Cl[0] = ql; gb.alpha[0] = 8.0f;   // * sqrt(depth)
    gb.Ah[1] = yh; gb.Al[1] = yl; gb.Bh[1] = wkh; gb.Bl[1] = wkl;
    gb.Ch[1] = kh; gb.Cl[1] = kl; gb.alpha[1] = 1.0f;
    gb.Ah[2] = yh; gb.Al[2] = yl; gb.Bh[2] = wvh; gb.Bl[2] = wvl;
    gb.Ch[2] = vh; gb.Cl[2] = vl; gb.alpha[2] = 1.0f;

    dim3 qkvgrid(DMODEL / 128, MROWS / 128, 3);   // (8, 32, 3)
    bf16_gemm_qkv<<<qkvgrid, 256, GEMM_SMEM, 0>>>(gb);

    dim3 fgrid(SEQ / 128, NHEADS, BATCH);         // (16, 16, 2)
    flash_bf16_kernel<<<fgrid, 256, FLASH_SMEM_BYTES, 0>>>(
        qh, ql, kh, kl, vh, vl, bias, ah, al);

    dim3 ggrid(DMODEL / 128, MROWS / 128);        // (8, 32)
    bf16_gemm_out<<<ggrid, 256, GEMM_SMEM, 0>>>(ah, al, woh, wol, out);
}

// round 14
// speedup vs baseline: 4.7348x; 1.0688x over previous
#include <cuda_runtime.h>
#include <cuda_bf16.h>
#include <math_constants.h>
#include <cstdint>

// Problem constants (fixed by the reference setup)
#define SEQ    2048
#define DMODEL 1024
#define NHEADS 16
#define DEPTH  64
#define BATCH  2
#define MROWS  (BATCH * SEQ)   // 4096

// Scratch (allocation-free rule: __device__ globals). All bf16 hi/lo pairs.
// Weights stored [K][N] (NO transpose) — GEMM uses ldmatrix.trans for B-frags.
__device__ __nv_bfloat16 g_ah[MROWS * DMODEL];   // x split, later attn split
__device__ __nv_bfloat16 g_al[MROWS * DMODEL];
__device__ __nv_bfloat16 g_yh[MROWS * DMODEL];
__device__ __nv_bfloat16 g_yl[MROWS * DMODEL];
__device__ __nv_bfloat16 g_qh[MROWS * DMODEL];
__device__ __nv_bfloat16 g_ql[MROWS * DMODEL];
__device__ __nv_bfloat16 g_kh[MROWS * DMODEL];
__device__ __nv_bfloat16 g_kl[MROWS * DMODEL];
__device__ __nv_bfloat16 g_vh[MROWS * DMODEL];
__device__ __nv_bfloat16 g_vl[MROWS * DMODEL];
__device__ __nv_bfloat16 g_wqh[DMODEL * DMODEL];
__device__ __nv_bfloat16 g_wql[DMODEL * DMODEL];
__device__ __nv_bfloat16 g_wkh[DMODEL * DMODEL];
__device__ __nv_bfloat16 g_wkl[DMODEL * DMODEL];
__device__ __nv_bfloat16 g_wvh[DMODEL * DMODEL];
__device__ __nv_bfloat16 g_wvl[DMODEL * DMODEL];
__device__ __nv_bfloat16 g_woh[DMODEL * DMODEL];
__device__ __nv_bfloat16 g_wol[DMODEL * DMODEL];
__device__ int g_bias_nonzero;

// ---------------------------------------------------------------------------
// Helpers
// ---------------------------------------------------------------------------
__device__ __forceinline__ void mma_bf16(float* c, const uint32_t* a, const uint32_t* b) {
    asm volatile(
        "mma.sync.aligned.m16n8k16.row.col.f32.bf16.bf16.f32 "
        "{%0,%1,%2,%3}, {%4,%5,%6,%7}, {%8,%9}, {%0,%1,%2,%3};"
        : "+f"(c[0]), "+f"(c[1]), "+f"(c[2]), "+f"(c[3])
        : "r"(a[0]), "r"(a[1]), "r"(a[2]), "r"(a[3]), "r"(b[0]), "r"(b[1]));
}

__device__ __forceinline__ void ldsm_x4(uint32_t& r0, uint32_t& r1, uint32_t& r2,
                                        uint32_t& r3, uint32_t addr) {
    asm volatile("ldmatrix.sync.aligned.m8n8.x4.shared.b16 {%0,%1,%2,%3}, [%4];"
        : "=r"(r0), "=r"(r1), "=r"(r2), "=r"(r3) : "r"(addr));
}

__device__ __forceinline__ void ldsm_x4_t(uint32_t& r0, uint32_t& r1, uint32_t& r2,
                                          uint32_t& r3, uint32_t addr) {
    asm volatile("ldmatrix.sync.aligned.m8n8.x4.trans.shared.b16 {%0,%1,%2,%3}, [%4];"
        : "=r"(r0), "=r"(r1), "=r"(r2), "=r"(r3) : "r"(addr));
}

__device__ __forceinline__ uint32_t smem_u32(const void* p) {
    uint32_t a;
    asm("{ .reg .u64 t; cvta.to.shared.u64 t, %1; cvt.u32.u64 %0, t; }" : "=r"(a) : "l"(p));
    return a;
}

#define CP_ASYNC16(dst, src) \
    asm volatile("cp.async.cg.shared.global [%0], [%1], 16;" :: "r"(dst), "l"(src))
#define CP_COMMIT() asm volatile("cp.async.commit_group;" ::: "memory")
#define CP_WAIT0()  asm volatile("cp.async.wait_group 0;" ::: "memory")
#define CP_WAIT1()  asm volatile("cp.async.wait_group 1;" ::: "memory")

__device__ __forceinline__ void split_bf16(float v, __nv_bfloat16& h, __nv_bfloat16& l) {
    h = __float2bfloat16(v);
    l = __float2bfloat16(v - __bfloat162float(h));
}

// Truncation split of a float pair: hi = top-16-bit bf16s packed via prmt;
// lo = (v - hi) rounded to bf16 pair. h+l == v to ~2^-17.
__device__ __forceinline__ void split_pair_trunc(float v0, float v1,
                                                 uint32_t& hp, uint32_t& lp) {
    uint32_t b0 = __float_as_uint(v0), b1 = __float_as_uint(v1);
    asm("prmt.b32 %0, %1, %2, 0x7632;" : "=r"(hp) : "r"(b0), "r"(b1));
    float l0 = v0 - __uint_as_float(b0 & 0xFFFF0000u);
    float l1 = v1 - __uint_as_float(b1 & 0xFFFF0000u);
    asm("cvt.rn.bf16x2.f32 %0, %1, %2;" : "=r"(lp) : "f"(l1), "f"(l0));
}

// ---------------------------------------------------------------------------
// Bias zero-detection (correct for arbitrary bias; fast path when all-zero)
// ---------------------------------------------------------------------------
__global__ void reset_flag_kernel() { g_bias_nonzero = 0; }

__global__ __launch_bounds__(256) void bias_check_kernel(
    const float* __restrict__ bias, int n4)
{
    int i = blockIdx.x * blockDim.x + threadIdx.x;
    int stride = gridDim.x * blockDim.x;
    int local = 0;
    for (; i < n4; i += stride) {
        float4 v = ((const float4*)bias)[i];
        if (v.x != 0.f || v.y != 0.f || v.z != 0.f || v.w != 0.f) { local = 1; break; }
    }
    if (__syncthreads_or(local))
        if (threadIdx.x == 0) atomicOr(&g_bias_nonzero, 1);
}

// ---------------------------------------------------------------------------
// Batched elementwise hi/lo split: x, y, and the 4 weights (no transpose).
// ---------------------------------------------------------------------------
struct SplitBatch {
    const float* in[6];
    __nv_bfloat16 *oh[6], *ol[6];
    int n4[6];
};

__global__ __launch_bounds__(256) void split_kernel(SplitBatch sb)
{
    const int z = blockIdx.z;
    int i = blockIdx.x * blockDim.x + threadIdx.x;
    if (i >= sb.n4[z]) return;
    float4 v = ((const float4*)sb.in[z])[i];
    __nv_bfloat16 h0, h1, h2, h3, l0, l1, l2, l3;
    split_bf16(v.x, h0, l0); split_bf16(v.y, h1, l1);
    split_bf16(v.z, h2, l2); split_bf16(v.w, h3, l3);
    __nv_bfloat162* ph = (__nv_bfloat162*)sb.oh[z];
    __nv_bfloat162* pl = (__nv_bfloat162*)sb.ol[z];
    ph[i * 2 + 0] = __halves2bfloat162(h0, h1);
    ph[i * 2 + 1] = __halves2bfloat162(h2, h3);
    pl[i * 2 + 0] = __halves2bfloat162(l0, l1);
    pl[i * 2 + 1] = __halves2bfloat162(l2, l3);
}

// ---------------------------------------------------------------------------
// 3-term bf16 GEMM body: A [M][K] row-major, W [K][N] row-major (NOT transposed;
// B-frags come from ldmatrix.x4.trans). cp.async double-buffered, ldmatrix A.
// CTA tile 128x128, K chunk 32, 8 warps, warp tile 32x64.
// ---------------------------------------------------------------------------
#define GSTRIDE 56
#define WSTRIDE 136                             // W tile row stride (u16): trans-LDSM conflict-free
#define ATILE_B (128 * GSTRIDE * 2)             // 14336 bytes
#define WTILE_B (32 * WSTRIDE * 2)              // 8704 bytes
#define GSTAGE_B (2 * ATILE_B + 2 * WTILE_B)    // 46080
#define GEMM_SMEM (2 * GSTAGE_B)                // 92160

template<int BFOUT>
__device__ __forceinline__ void gemm_body(
    const __nv_bfloat16* __restrict__ Ah, const __nv_bfloat16* __restrict__ Al,
    const __nv_bfloat16* __restrict__ Wh, const __nv_bfloat16* __restrict__ Wl,
    float* __restrict__ C, __nv_bfloat16* __restrict__ Ch,
    __nv_bfloat16* __restrict__ Cl, float alpha, char* gsm)
{
    const uint32_t smb = smem_u32(gsm);
    const int tid  = threadIdx.x;
    const int lane = tid & 31;
    const int wid  = tid >> 5;
    const int g    = lane >> 2;
    const int tig  = lane & 3;
    const int sec  = lane >> 3;
    const int rowin = lane & 7;
    const int wrow = (wid & 3) * 32;
    const int wcol = (wid >> 2) * 64;

    const int blockRow = blockIdx.y * 128;
    const int blockCol = blockIdx.x * 128;
    const int K = DMODEL;

    // A frags: non-trans ldmatrix on [M][K] tile (stride GSTRIDE)
    const uint32_t lane_a = (uint32_t)(((sec & 1) * 8 + rowin) * GSTRIDE + (sec >> 1) * 8);
    // B frags: trans ldmatrix on W [K][N] tile (stride WSTRIDE); mirrors flash V path.
    // m0=(k-lo, n-lo), m1=(k-hi, n-lo), m2=(k-lo, n-hi), m3=(k-hi, n-hi)
    const uint32_t lane_w = (uint32_t)(((sec & 1) * 8 + rowin) * WSTRIDE + (sec >> 1) * 8);

    float acc[2][8][4];
    #pragma unroll
    for (int mu = 0; mu < 2; mu++)
        #pragma unroll
        for (int nf = 0; nf < 8; nf++)
            #pragma unroll
            for (int r = 0; r < 4; r++) acc[mu][nf][r] = 0.0f;

    // g2s loader: A 128x32, W 32x128 (hi+lo each); 8x cp.async(16B) per thread
    auto issue_load = [&](int k0, int buf) {
        const uint32_t sb = smb + buf * GSTAGE_B;
        #pragma unroll
        for (int j = 0; j < 2; j++) {
            int idx = tid + j * 256;               // 0..511
            // A: row = m (0..127), seg = 4 x 8-u16
            int arow = idx >> 2;
            int aseg = idx & 3;
            uint32_t asoff = (uint32_t)(arow * GSTRIDE + aseg * 8) * 2;
            size_t agoff = (size_t)(blockRow + arow) * K + k0 + aseg * 8;
            CP_ASYNC16(sb + asoff,           Ah + agoff);
            CP_ASYNC16(sb + ATILE_B + asoff, Al + agoff);
            // W: row = k (0..31), seg = 16 x 8-u16 covering 128 n-cols
            int wrow_ = idx >> 4;
            int wseg  = idx & 15;
            uint32_t wsoff = (uint32_t)(wrow_ * WSTRIDE + wseg * 8) * 2;
            size_t wgoff = (size_t)(k0 + wrow_) * DMODEL + blockCol + wseg * 8;
            CP_ASYNC16(sb + 2 * ATILE_B + wsoff,           Wh + wgoff);
            CP_ASYNC16(sb + 2 * ATILE_B + WTILE_B + wsoff, Wl + wgoff);
        }
    };

    issue_load(0, 0);
    CP_COMMIT();

    for (int it = 0; it < 32; it++) {
        if (it + 1 < 32) {
            issue_load((it + 1) * 32, (it + 1) & 1);
            CP_COMMIT();
            CP_WAIT1();
        } else {
            CP_WAIT0();
        }
        __syncthreads();

        const uint32_t sb = smb + (uint32_t)((it & 1) * GSTAGE_B);
        const uint32_t wb = sb + 2 * ATILE_B;

        #pragma unroll
        for (int ks = 0; ks < 2; ks++) {
            const int kb = ks * 16;
            uint32_t ah[2][4], al[2][4];
            #pragma unroll
            for (int mu = 0; mu < 2; mu++) {
                const uint32_t abase = (uint32_t)((wrow + mu * 16) * GSTRIDE + kb) + lane_a;
                ldsm_x4(ah[mu][0], ah[mu][1], ah[mu][2], ah[mu][3], sb + 2 * abase);
                ldsm_x4(al[mu][0], al[mu][1], al[mu][2], al[mu][3], sb + ATILE_B + 2 * abase);
            }
            #pragma unroll
            for (int p = 0; p < 4; p++) {
                const uint32_t wbase = (uint32_t)(kb * WSTRIDE + wcol + p * 16) + lane_w;
                uint32_t bh[4], bl[4];
                ldsm_x4_t(bh[0], bh[1], bh[2], bh[3], wb + 2 * wbase);
                ldsm_x4_t(bl[0], bl[1], bl[2], bl[3], wb + WTILE_B + 2 * wbase);
                #pragma unroll
                for (int mu = 0; mu < 2; mu++) {
                    mma_bf16(acc[mu][2 * p],     ah[mu], bh);
                    mma_bf16(acc[mu][2 * p],     al[mu], bh);
                    mma_bf16(acc[mu][2 * p],     ah[mu], bl);
                    mma_bf16(acc[mu][2 * p + 1], ah[mu], bh + 2);
                    mma_bf16(acc[mu][2 * p + 1], al[mu], bh + 2);
                    mma_bf16(acc[mu][2 * p + 1], ah[mu], bl + 2);
                }
            }
        }
        __syncthreads();
    }

    #pragma unroll
    for (int mu = 0; mu < 2; mu++) {
        #pragma unroll
        for (int nf = 0; nf < 8; nf++) {
            int row0 = blockRow + wrow + mu * 16 + g;
            int col  = blockCol + wcol + nf * 8 + tig * 2;
            float v0 = alpha * acc[mu][nf][0], v1 = alpha * acc[mu][nf][1];
            float v2 = alpha * acc[mu][nf][2], v3 = alpha * acc[mu][nf][3];
            if (BFOUT) {
                __nv_bfloat16 h0, h1, h2, h3, l0, l1, l2, l3;
                split_bf16(v0, h0, l0); split_bf16(v1, h1, l1);
                split_bf16(v2, h2, l2); split_bf16(v3, h3, l3);
                *(__nv_bfloat162*)(Ch + (size_t)row0 * DMODEL + col) = __halves2bfloat162(h0, h1);
                *(__nv_bfloat162*)(Cl + (size_t)row0 * DMODEL + col) = __halves2bfloat162(l0, l1);
                *(__nv_bfloat162*)(Ch + (size_t)(row0 + 8) * DMODEL + col) = __halves2bfloat162(h2, h3);
                *(__nv_bfloat162*)(Cl + (size_t)(row0 + 8) * DMODEL + col) = __halves2bfloat162(l2, l3);
            } else {
                *(float2*)(C + (size_t)row0 * DMODEL + col)       = make_float2(v0, v1);
                *(float2*)(C + (size_t)(row0 + 8) * DMODEL + col) = make_float2(v2, v3);
            }
        }
    }
}

struct GemmBatch {
    const __nv_bfloat16 *Ah[3], *Al[3], *Bh[3], *Bl[3];
    __nv_bfloat16 *Ch[3], *Cl[3];
    float alpha[3];
};

__global__ __launch_bounds__(256, 2) void bf16_gemm_qkv(GemmBatch gb)
{
    extern __shared__ __align__(16) char gsm[];
    const int z = blockIdx.z;
    gemm_body<1>(gb.Ah[z], gb.Al[z], gb.Bh[z], gb.Bl[z],
                 nullptr, gb.Ch[z], gb.Cl[z], gb.alpha[z], gsm);
}

__global__ __launch_bounds__(256, 2) void bf16_gemm_out(
    const __nv_bfloat16* __restrict__ Ah, const __nv_bfloat16* __restrict__ Al,
    const __nv_bfloat16* __restrict__ Bh, const __nv_bfloat16* __restrict__ Bl,
    float* __restrict__ C)
{
    extern __shared__ __align__(16) char gsm[];
    gemm_body<0>(Ah, Al, Bh, Bl, C, nullptr, nullptr, 1.0f, gsm);
}

// ---------------------------------------------------------------------------
// Full-bf16 flash attention v5 (unchanged from R13): cp.async double-buffered
// KV pipeline, reg Q frags, reg P relayout, ldmatrix B-frags, zero-bias skip.
// ---------------------------------------------------------------------------
#define KS  72
#define VT  72
#define FL_KH 0
#define FL_KL (64 * KS)
#define FL_VH (2 * 64 * KS)
#define FL_VL (2 * 64 * KS + 64 * VT)
#define FL_STAGE (2 * 64 * KS + 2 * 64 * VT)       // 18432 u16 per stage
#define FLASH_SMEM_BYTES (2 * FL_STAGE * 2)        // 73728

__global__ __launch_bounds__(256, 2) void flash_bf16_kernel(
    const __nv_bfloat16* __restrict__ Qh, const __nv_bfloat16* __restrict__ Ql,
    const __nv_bfloat16* __restrict__ Kg_h, const __nv_bfloat16* __restrict__ Kg_l,
    const __nv_bfloat16* __restrict__ Vg_h, const __nv_bfloat16* __restrict__ Vg_l,
    const float* __restrict__ bias,
    __nv_bfloat16* __restrict__ Oh, __nv_bfloat16* __restrict__ Ol)
{
    extern __shared__ uint16_t fsm[];
    const uint32_t smb = smem_u32(fsm);

    const int tid  = threadIdx.x;
    const int lane = tid & 31;
    const int wid  = tid >> 5;
    const int g    = lane >> 2;
    const int tig  = lane & 3;
    const int sec  = lane >> 3;
    const int rowin = lane & 7;

    const int h = blockIdx.y;
    const int b = blockIdx.z;
    const int qbase = blockIdx.x * 128;
    const int wrow  = wid * 16;

    const int bias_on = g_bias_nonzero;

    const uint32_t lane_k = (uint32_t)(((sec >> 1) * 8 + rowin) * KS + (sec & 1) * 8);
    const uint32_t lane_v = (uint32_t)(((sec & 1) * 8 + rowin) * VT + (sec >> 1) * 8);

    uint32_t qfh[4][4], qfl[4][4];
    {
        const uint16_t* qhp = (const uint16_t*)Qh + (size_t)(b * SEQ + qbase + wrow) * DMODEL + h * DEPTH;
        const uint16_t* qlp = (const uint16_t*)Ql + (size_t)(b * SEQ + qbase + wrow) * DMODEL + h * DEPTH;
        #pragma unroll
        for (int ks = 0; ks < 4; ks++) {
            const int c0 = ks * 16 + 2 * tig;
            qfh[ks][0] = *(const uint32_t*)(qhp + (size_t)g * DMODEL + c0);
            qfh[ks][1] = *(const uint32_t*)(qhp + (size_t)(g + 8) * DMODEL + c0);
            qfh[ks][2] = *(const uint32_t*)(qhp + (size_t)g * DMODEL + c0 + 8);
            qfh[ks][3] = *(const uint32_t*)(qhp + (size_t)(g + 8) * DMODEL + c0 + 8);
            qfl[ks][0] = *(const uint32_t*)(qlp + (size_t)g * DMODEL + c0);
            qfl[ks][1] = *(const uint32_t*)(qlp + (size_t)(g + 8) * DMODEL + c0);
            qfl[ks][2] = *(const uint32_t*)(qlp + (size_t)g * DMODEL + c0 + 8);
            qfl[ks][3] = *(const uint32_t*)(qlp + (size_t)(g + 8) * DMODEL + c0 + 8);
        }
    }

    float o[8][4];
    #pragma unroll
    for (int nf = 0; nf < 8; nf++)
        #pragma unroll
        for (int r = 0; r < 4; r++) o[nf][r] = 0.0f;
    float m0 = -CUDART_INF_F, m1 = -CUDART_INF_F, l0 = 0.f, l1 = 0.f;

    const float* bp0 = bias + (size_t)(qbase + wrow + g) * SEQ;
    const float* bp8 = bias + (size_t)(qbase + wrow + g + 8) * SEQ;

    auto load_kv = [&](int kt, int buf) {
        const uint32_t sb = smb + (uint32_t)(buf * FL_STAGE) * 2;
        #pragma unroll
        for (int j = 0; j < 2; j++) {
            int idx = tid + j * 256;
            int row = idx >> 3;
            int seg = idx & 7;
            size_t src = (size_t)(b * SEQ + kt + row) * DMODEL + h * DEPTH + seg * 8;
            uint32_t soff = (uint32_t)(row * KS + seg * 8) * 2;
            CP_ASYNC16(sb + 2 * FL_KH + soff, (const uint16_t*)Kg_h + src);
            CP_ASYNC16(sb + 2 * FL_KL + soff, (const uint16_t*)Kg_l + src);
            CP_ASYNC16(sb + 2 * FL_VH + soff, (const uint16_t*)Vg_h + src);
            CP_ASYNC16(sb + 2 * FL_VL + soff, (const uint16_t*)Vg_l + src);
        }
    };

    load_kv(0, 0);
    CP_COMMIT();

    const int NIT = SEQ / 64;
    for (int it = 0; it < NIT; it++) {
        const int kt = it * 64;
        if (it + 1 < NIT) {
            load_kv(kt + 64, (it + 1) & 1);
            CP_COMMIT();
            CP_WAIT1();
        } else {
            CP_WAIT0();
        }
        __syncthreads();

        const uint32_t sb = smb + (uint32_t)((it & 1) * FL_STAGE) * 2;

        float s[8][4];
        #pragma unroll
        for (int nf = 0; nf < 8; nf++)
            #pragma unroll
            for (int r = 0; r < 4; r++) s[nf][r] = 0.0f;

        #pragma unroll
        for (int ks = 0; ks < 4; ks++) {
            #pragma unroll
            for (int p = 0; p < 4; p++) {
                const uint32_t off = lane_k + (uint32_t)(p * 16 * KS + ks * 16);
                uint32_t bh[4], bl[4];
                ldsm_x4(bh[0], bh[1], bh[2], bh[3], sb + 2 * (FL_KH + off));
                ldsm_x4(bl[0], bl[1], bl[2], bl[3], sb + 2 * (FL_KL + off));
                mma_bf16(s[2 * p],     qfh[ks], bh);
                mma_bf16(s[2 * p],     qfl[ks], bh);
                mma_bf16(s[2 * p],     qfh[ks], bl);
                mma_bf16(s[2 * p + 1], qfh[ks], bh + 2);
                mma_bf16(s[2 * p + 1], qfl[ks], bh + 2);
                mma_bf16(s[2 * p + 1], qfh[ks], bl + 2);
            }
        }

        float mx0 = -CUDART_INF_F, mx1 = -CUDART_INF_F;
        if (bias_on) {
            #pragma unroll
            for (int nf = 0; nf < 8; nf++) {
                float2 b0 = *(const float2*)(bp0 + kt + nf * 8 + tig * 2);
                float2 b1 = *(const float2*)(bp8 + kt + nf * 8 + tig * 2);
                s[nf][0] += b0.x; s[nf][1] += b0.y;
                s[nf][2] += b1.x; s[nf][3] += b1.y;
            }
        }
        #pragma unroll
        for (int nf = 0; nf < 8; nf++) {
            mx0 = fmaxf(mx0, fmaxf(s[nf][0], s[nf][1]));
            mx1 = fmaxf(mx1, fmaxf(s[nf][2], s[nf][3]));
        }
        mx0 = fmaxf(mx0, __shfl_xor_sync(0xFFFFFFFFu, mx0, 1));
        mx0 = fmaxf(mx0, __shfl_xor_sync(0xFFFFFFFFu, mx0, 2));
        mx1 = fmaxf(mx1, __shfl_xor_sync(0xFFFFFFFFu, mx1, 1));
        mx1 = fmaxf(mx1, __shfl_xor_sync(0xFFFFFFFFu, mx1, 2));

        float nm0 = fmaxf(m0, mx0), nm1 = fmaxf(m1, mx1);
        float c0f = __expf(m0 - nm0), c1f = __expf(m1 - nm1);
        l0 *= c0f; l1 *= c1f; m0 = nm0; m1 = nm1;
        #pragma unroll
        for (int nf = 0; nf < 8; nf++) {
            o[nf][0] *= c0f; o[nf][1] *= c0f; o[nf][2] *= c1f; o[nf][3] *= c1f;
        }
        uint32_t pfh[4][4], pfl[4][4];
        float la0 = 0.f, la1 = 0.f;
        #pragma unroll
        for (int nf = 0; nf < 8; nf++) {
            float p0 = __expf(s[nf][0] - nm0);
            float p1 = __expf(s[nf][1] - nm0);
            float p2 = __expf(s[nf][2] - nm1);
            float p3 = __expf(s[nf][3] - nm1);
            la0 += p0 + p1; la1 += p2 + p3;
            const int ks = nf >> 1;
            const int rbase = (nf & 1) * 2;
            split_pair_trunc(p0, p1, pfh[ks][rbase + 0], pfl[ks][rbase + 0]);
            split_pair_trunc(p2, p3, pfh[ks][rbase + 1], pfl[ks][rbase + 1]);
        }
        la0 += __shfl_xor_sync(0xFFFFFFFFu, la0, 1);
        la0 += __shfl_xor_sync(0xFFFFFFFFu, la0, 2);
        la1 += __shfl_xor_sync(0xFFFFFFFFu, la1, 1);
        la1 += __shfl_xor_sync(0xFFFFFFFFu, la1, 2);
        l0 += la0; l1 += la1;

        #pragma unroll
        for (int ks = 0; ks < 4; ks++) {
            #pragma unroll
            for (int p = 0; p < 4; p++) {
                const uint32_t off = lane_v + (uint32_t)(ks * 16 * VT + p * 16);
                uint32_t vh[4], vl[4];
                ldsm_x4_t(vh[0], vh[1], vh[2], vh[3], sb + 2 * (FL_VH + off));
                ldsm_x4_t(vl[0], vl[1], vl[2], vl[3], sb + 2 * (FL_VL + off));
                mma_bf16(o[2 * p],     pfh[ks], vh);
                mma_bf16(o[2 * p],     pfl[ks], vh);
                mma_bf16(o[2 * p],     pfh[ks], vl);
                mma_bf16(o[2 * p + 1], pfh[ks], vh + 2);
                mma_bf16(o[2 * p + 1], pfl[ks], vh + 2);
                mma_bf16(o[2 * p + 1], pfh[ks], vl + 2);
            }
        }
        __syncthreads();
    }

    const float inv0 = 1.0f / l0, inv1 = 1.0f / l1;
    uint16_t* ohp0 = (uint16_t*)Oh + (size_t)(b * SEQ + qbase + wrow + g) * DMODEL + h * DEPTH;
    uint16_t* olp0 = (uint16_t*)Ol + (size_t)(b * SEQ + qbase + wrow + g) * DMODEL + h * DEPTH;
    uint16_t* ohp8 = ohp0 + (size_t)8 * DMODEL;
    uint16_t* olp8 = olp0 + (size_t)8 * DMODEL;
    #pragma unroll
    for (int nf = 0; nf < 8; nf++) {
        float v0 = o[nf][0] * inv0, v1 = o[nf][1] * inv0;
        float v2 = o[nf][2] * inv1, v3 = o[nf][3] * inv1;
        uint32_t h01, l01, h23, l23;
        split_pair_trunc(v0, v1, h01, l01);
        split_pair_trunc(v2, v3, h23, l23);
        const int col = nf * 8 + tig * 2;
        *(uint32_t*)(ohp0 + col) = h01;
        *(uint32_t*)(olp0 + col) = l01;
        *(uint32_t*)(ohp8 + col) = h23;
        *(uint32_t*)(olp8 + col) = l23;
    }
}

// ---------------------------------------------------------------------------
// Launch
// ---------------------------------------------------------------------------
extern "C" void kernel_launch(void* const* d_in, const int* in_sizes, int n_in,
                              void* d_out, int out_size)
{
    const float* x    = (const float*)d_in[0];
    const float* y    = (const float*)d_in[1];
    const float* bias = (const float*)d_in[2];
    const float* Wq   = (const float*)d_in[3];
    const float* Wk   = (const float*)d_in[4];
    const float* Wv   = (const float*)d_in[5];
    const float* Wo   = (const float*)d_in[6];
    float* out = (float*)d_out;

    __nv_bfloat16 *ah, *al, *yh, *yl, *qh, *ql, *kh, *kl, *vh, *vl;
    __nv_bfloat16 *wqh, *wql, *wkh, *wkl, *wvh, *wvl, *woh, *wol;
    cudaGetSymbolAddress((void**)&ah,  g_ah);
    cudaGetSymbolAddress((void**)&al,  g_al);
    cudaGetSymbolAddress((void**)&yh,  g_yh);
    cudaGetSymbolAddress((void**)&yl,  g_yl);
    cudaGetSymbolAddress((void**)&qh,  g_qh);
    cudaGetSymbolAddress((void**)&ql,  g_ql);
    cudaGetSymbolAddress((void**)&kh,  g_kh);
    cudaGetSymbolAddress((void**)&kl,  g_kl);
    cudaGetSymbolAddress((void**)&vh,  g_vh);
    cudaGetSymbolAddress((void**)&vl,  g_vl);
    cudaGetSymbolAddress((void**)&wqh, g_wqh);
    cudaGetSymbolAddress((void**)&wql, g_wql);
    cudaGetSymbolAddress((void**)&wkh, g_wkh);
    cudaGetSymbolAddress((void**)&wkl, g_wkl);
    cudaGetSymbolAddress((void**)&wvh, g_wvh);
    cudaGetSymbolAddress((void**)&wvl, g_wvl);
    cudaGetSymbolAddress((void**)&woh, g_woh);
    cudaGetSymbolAddress((void**)&wol, g_wol);

    cudaFuncSetAttribute(flash_bf16_kernel,
                         cudaFuncAttributeMaxDynamicSharedMemorySize, FLASH_SMEM_BYTES);
    cudaFuncSetAttribute(bf16_gemm_qkv,
                         cudaFuncAttributeMaxDynamicSharedMemorySize, GEMM_SMEM);
    cudaFuncSetAttribute(bf16_gemm_out,
                         cudaFuncAttributeMaxDynamicSharedMemorySize, GEMM_SMEM);

    // Bias zero-detection (fast path trigger; correct for any input)
    reset_flag_kernel<<<1, 1, 0, 0>>>();
    bias_check_kernel<<<512, 256, 0, 0>>>(bias, SEQ * SEQ / 4);

    // One batched elementwise split: x, y, and the 4 weights (stored [K][N])
    const int n4_xy = MROWS * DMODEL / 4;        // 1048576
    const int n4_w  = DMODEL * DMODEL / 4;       // 262144
    SplitBatch sb;
    sb.in[0] = x;  sb.oh[0] = ah;  sb.ol[0] = al;  sb.n4[0] = n4_xy;
    sb.in[1] = y;  sb.oh[1] = yh;  sb.ol[1] = yl;  sb.n4[1] = n4_xy;
    sb.in[2] = Wq; sb.oh[2] = wqh; sb.ol[2] = wql; sb.n4[2] = n4_w;
    sb.in[3] = Wk; sb.oh[3] = wkh; sb.ol[3] = wkl; sb.n4[3] = n4_w;
    sb.in[4] = Wv; sb.oh[4] = wvh; sb.ol[4] = wvl; sb.n4[4] = n4_w;
    sb.in[5] = Wo; sb.oh[5] = woh; sb.ol[5] = wol; sb.n4[5] = n4_w;
    dim3 sgrid((n4_xy + 255) / 256, 1, 6);
    split_kernel<<<sgrid, 256, 0, 0>>>(sb);

    // Batched q/k/v projections: one launch, grid.z = 3
    GemmBatch gb;
    gb.Ah[0] = ah; gb.Al[0] = al; gb.Bh[0] = wqh; gb.Bl[0] = wql;
    gb.Ch[0] = qh; gb.Cl[0] = ql; gb.alpha[0] = 8.0f;   // * sqrt(depth)
    gb.Ah[1] = yh; gb.Al[1] = yl; gb.Bh[1] = wkh; gb.Bl[1] = wkl;
    gb.Ch[1] = kh; gb.Cl[1] = kl; gb.alpha[1] = 1.0f;
    gb.Ah[2] = yh; gb.Al[2] = yl; gb.Bh[2] = wvh; gb.Bl[2] = wvl;
    gb.Ch[2] = vh; gb.Cl[2] = vl; gb.alpha[2] = 1.0f;

    dim3 qkvgrid(DMODEL / 128, MROWS / 128, 3);   // (8, 32, 3)
    bf16_gemm_qkv<<<qkvgrid, 256, GEMM_SMEM, 0>>>(gb);

    dim3 fgrid(SEQ / 128, NHEADS, BATCH);         // (16, 16, 2)
    flash_bf16_kernel<<<fgrid, 256, FLASH_SMEM_BYTES, 0>>>(
        qh, ql, kh, kl, vh, vl, bias, ah, al);

    dim3 ggrid(DMODEL / 128, MROWS / 128);        // (8, 32)
    bf16_gemm_out<<<ggrid, 256, GEMM_SMEM, 0>>>(ah, al, woh, wol, out);
}

// round 15
// speedup vs baseline: 4.7485x; 1.0029x over previous
#include <cuda_runtime.h>
#include <cuda_bf16.h>
#include <math_constants.h>
#include <cstdint>

// Problem constants (fixed by the reference setup)
#define SEQ    2048
#define DMODEL 1024
#define NHEADS 16
#define DEPTH  64
#define BATCH  2
#define MROWS  (BATCH * SEQ)   // 4096

// Scratch (allocation-free rule: __device__ globals). All bf16 hi/lo pairs.
// Weights stored [K][N] (NO transpose) — GEMM uses ldmatrix.trans for B-frags.
__device__ __nv_bfloat16 g_ah[MROWS * DMODEL];   // x split, later attn split
__device__ __nv_bfloat16 g_al[MROWS * DMODEL];
__device__ __nv_bfloat16 g_yh[MROWS * DMODEL];
__device__ __nv_bfloat16 g_yl[MROWS * DMODEL];
__device__ __nv_bfloat16 g_qh[MROWS * DMODEL];
__device__ __nv_bfloat16 g_ql[MROWS * DMODEL];
__device__ __nv_bfloat16 g_kh[MROWS * DMODEL];
__device__ __nv_bfloat16 g_kl[MROWS * DMODEL];
__device__ __nv_bfloat16 g_vh[MROWS * DMODEL];
__device__ __nv_bfloat16 g_vl[MROWS * DMODEL];
__device__ __nv_bfloat16 g_wqh[DMODEL * DMODEL];
__device__ __nv_bfloat16 g_wql[DMODEL * DMODEL];
__device__ __nv_bfloat16 g_wkh[DMODEL * DMODEL];
__device__ __nv_bfloat16 g_wkl[DMODEL * DMODEL];
__device__ __nv_bfloat16 g_wvh[DMODEL * DMODEL];
__device__ __nv_bfloat16 g_wvl[DMODEL * DMODEL];
__device__ __nv_bfloat16 g_woh[DMODEL * DMODEL];
__device__ __nv_bfloat16 g_wol[DMODEL * DMODEL];
__device__ int g_bias_nonzero;

// ---------------------------------------------------------------------------
// Helpers
// ---------------------------------------------------------------------------
__device__ __forceinline__ void mma_bf16(float* c, const uint32_t* a, const uint32_t* b) {
    asm volatile(
        "mma.sync.aligned.m16n8k16.row.col.f32.bf16.bf16.f32 "
        "{%0,%1,%2,%3}, {%4,%5,%6,%7}, {%8,%9}, {%0,%1,%2,%3};"
        : "+f"(c[0]), "+f"(c[1]), "+f"(c[2]), "+f"(c[3])
        : "r"(a[0]), "r"(a[1]), "r"(a[2]), "r"(a[3]), "r"(b[0]), "r"(b[1]));
}

__device__ __forceinline__ void ldsm_x4(uint32_t& r0, uint32_t& r1, uint32_t& r2,
                                        uint32_t& r3, uint32_t addr) {
    asm volatile("ldmatrix.sync.aligned.m8n8.x4.shared.b16 {%0,%1,%2,%3}, [%4];"
        : "=r"(r0), "=r"(r1), "=r"(r2), "=r"(r3) : "r"(addr));
}

__device__ __forceinline__ void ldsm_x4_t(uint32_t& r0, uint32_t& r1, uint32_t& r2,
                                          uint32_t& r3, uint32_t addr) {
    asm volatile("ldmatrix.sync.aligned.m8n8.x4.trans.shared.b16 {%0,%1,%2,%3}, [%4];"
        : "=r"(r0), "=r"(r1), "=r"(r2), "=r"(r3) : "r"(addr));
}

__device__ __forceinline__ uint32_t smem_u32(const void* p) {
    uint32_t a;
    asm("{ .reg .u64 t; cvta.to.shared.u64 t, %1; cvt.u32.u64 %0, t; }" : "=r"(a) : "l"(p));
    return a;
}

#define CP_ASYNC16(dst, src) \
    asm volatile("cp.async.cg.shared.global [%0], [%1], 16;" :: "r"(dst), "l"(src))
#define CP_COMMIT() asm volatile("cp.async.commit_group;" ::: "memory")
#define CP_WAIT0()  asm volatile("cp.async.wait_group 0;" ::: "memory")
#define CP_WAIT1()  asm volatile("cp.async.wait_group 1;" ::: "memory")

__device__ __forceinline__ void split_bf16(float v, __nv_bfloat16& h, __nv_bfloat16& l) {
    h = __float2bfloat16(v);
    l = __float2bfloat16(v - __bfloat162float(h));
}

// Truncation split of a float pair: hi = top-16-bit bf16s packed via prmt;
// lo = (v - hi) rounded to bf16 pair. h+l == v to ~2^-17.
__device__ __forceinline__ void split_pair_trunc(float v0, float v1,
                                                 uint32_t& hp, uint32_t& lp) {
    uint32_t b0 = __float_as_uint(v0), b1 = __float_as_uint(v1);
    asm("prmt.b32 %0, %1, %2, 0x7632;" : "=r"(hp) : "r"(b0), "r"(b1));
    float l0 = v0 - __uint_as_float(b0 & 0xFFFF0000u);
    float l1 = v1 - __uint_as_float(b1 & 0xFFFF0000u);
    asm("cvt.rn.bf16x2.f32 %0, %1, %2;" : "=r"(lp) : "f"(l1), "f"(l0));
}

// ---------------------------------------------------------------------------
// Bias zero-detection (correct for arbitrary bias; fast path when all-zero)
// ---------------------------------------------------------------------------
__global__ void reset_flag_kernel() { g_bias_nonzero = 0; }

__global__ __launch_bounds__(256) void bias_check_kernel(
    const float* __restrict__ bias, int n4)
{
    int i = blockIdx.x * blockDim.x + threadIdx.x;
    int stride = gridDim.x * blockDim.x;
    int local = 0;
    for (; i < n4; i += stride) {
        float4 v = ((const float4*)bias)[i];
        if (v.x != 0.f || v.y != 0.f || v.z != 0.f || v.w != 0.f) { local = 1; break; }
    }
    if (__syncthreads_or(local))
        if (threadIdx.x == 0) atomicOr(&g_bias_nonzero, 1);
}

// ---------------------------------------------------------------------------
// Batched elementwise hi/lo split: x, y, and the 4 weights (no transpose).
// ---------------------------------------------------------------------------
struct SplitBatch {
    const float* in[6];
    __nv_bfloat16 *oh[6], *ol[6];
    int n4[6];
};

__global__ __launch_bounds__(256) void split_kernel(SplitBatch sb)
{
    const int z = blockIdx.z;
    int i = blockIdx.x * blockDim.x + threadIdx.x;
    if (i >= sb.n4[z]) return;
    float4 v = ((const float4*)sb.in[z])[i];
    __nv_bfloat16 h0, h1, h2, h3, l0, l1, l2, l3;
    split_bf16(v.x, h0, l0); split_bf16(v.y, h1, l1);
    split_bf16(v.z, h2, l2); split_bf16(v.w, h3, l3);
    __nv_bfloat162* ph = (__nv_bfloat162*)sb.oh[z];
    __nv_bfloat162* pl = (__nv_bfloat162*)sb.ol[z];
    ph[i * 2 + 0] = __halves2bfloat162(h0, h1);
    ph[i * 2 + 1] = __halves2bfloat162(h2, h3);
    pl[i * 2 + 0] = __halves2bfloat162(l0, l1);
    pl[i * 2 + 1] = __halves2bfloat162(l2, l3);
}

// ---------------------------------------------------------------------------
// 3-term bf16 GEMM body: A [M][K] row-major, W [K][N] row-major.
// cp.async double-buffered, ldmatrix frags, RAW-chain-free MMA ordering.
// CTA tile 128x128, K chunk 32, 8 warps, warp tile 32x64.
// ---------------------------------------------------------------------------
#define GSTRIDE 56
#define WSTRIDE 136                             // W tile row stride (u16): trans-LDSM conflict-free
#define ATILE_B (128 * GSTRIDE * 2)             // 14336 bytes
#define WTILE_B (32 * WSTRIDE * 2)              // 8704 bytes
#define GSTAGE_B (2 * ATILE_B + 2 * WTILE_B)    // 46080
#define GEMM_SMEM (2 * GSTAGE_B)                // 92160

template<int BFOUT>
__device__ __forceinline__ void gemm_body(
    const __nv_bfloat16* __restrict__ Ah, const __nv_bfloat16* __restrict__ Al,
    const __nv_bfloat16* __restrict__ Wh, const __nv_bfloat16* __restrict__ Wl,
    float* __restrict__ C, __nv_bfloat16* __restrict__ Ch,
    __nv_bfloat16* __restrict__ Cl, float alpha, char* gsm)
{
    const uint32_t smb = smem_u32(gsm);
    const int tid  = threadIdx.x;
    const int lane = tid & 31;
    const int wid  = tid >> 5;
    const int g    = lane >> 2;
    const int tig  = lane & 3;
    const int sec  = lane >> 3;
    const int rowin = lane & 7;
    const int wrow = (wid & 3) * 32;
    const int wcol = (wid >> 2) * 64;

    const int blockRow = blockIdx.y * 128;
    const int blockCol = blockIdx.x * 128;
    const int K = DMODEL;

    const uint32_t lane_a = (uint32_t)(((sec & 1) * 8 + rowin) * GSTRIDE + (sec >> 1) * 8);
    const uint32_t lane_w = (uint32_t)(((sec & 1) * 8 + rowin) * WSTRIDE + (sec >> 1) * 8);

    float acc[2][8][4];
    #pragma unroll
    for (int mu = 0; mu < 2; mu++)
        #pragma unroll
        for (int nf = 0; nf < 8; nf++)
            #pragma unroll
            for (int r = 0; r < 4; r++) acc[mu][nf][r] = 0.0f;

    auto issue_load = [&](int k0, int buf) {
        const uint32_t sb = smb + buf * GSTAGE_B;
        #pragma unroll
        for (int j = 0; j < 2; j++) {
            int idx = tid + j * 256;
            int arow = idx >> 2;
            int aseg = idx & 3;
            uint32_t asoff = (uint32_t)(arow * GSTRIDE + aseg * 8) * 2;
            size_t agoff = (size_t)(blockRow + arow) * K + k0 + aseg * 8;
            CP_ASYNC16(sb + asoff,           Ah + agoff);
            CP_ASYNC16(sb + ATILE_B + asoff, Al + agoff);
            int wrow_ = idx >> 4;
            int wseg  = idx & 15;
            uint32_t wsoff = (uint32_t)(wrow_ * WSTRIDE + wseg * 8) * 2;
            size_t wgoff = (size_t)(k0 + wrow_) * DMODEL + blockCol + wseg * 8;
            CP_ASYNC16(sb + 2 * ATILE_B + wsoff,           Wh + wgoff);
            CP_ASYNC16(sb + 2 * ATILE_B + WTILE_B + wsoff, Wl + wgoff);
        }
    };

    issue_load(0, 0);
    CP_COMMIT();

    for (int it = 0; it < 32; it++) {
        if (it + 1 < 32) {
            issue_load((it + 1) * 32, (it + 1) & 1);
            CP_COMMIT();
            CP_WAIT1();
        } else {
            CP_WAIT0();
        }
        __syncthreads();

        const uint32_t sb = smb + (uint32_t)((it & 1) * GSTAGE_B);
        const uint32_t wb = sb + 2 * ATILE_B;

        #pragma unroll
        for (int ks = 0; ks < 2; ks++) {
            const int kb = ks * 16;
            uint32_t ah[2][4], al[2][4];
            #pragma unroll
            for (int mu = 0; mu < 2; mu++) {
                const uint32_t abase = (uint32_t)((wrow + mu * 16) * GSTRIDE + kb) + lane_a;
                ldsm_x4(ah[mu][0], ah[mu][1], ah[mu][2], ah[mu][3], sb + 2 * abase);
                ldsm_x4(al[mu][0], al[mu][1], al[mu][2], al[mu][3], sb + ATILE_B + 2 * abase);
            }
            #pragma unroll
            for (int p = 0; p < 4; p++) {
                const uint32_t wbase = (uint32_t)(kb * WSTRIDE + wcol + p * 16) + lane_w;
                uint32_t bh[4], bl[4];
                ldsm_x4_t(bh[0], bh[1], bh[2], bh[3], wb + 2 * wbase);
                ldsm_x4_t(bl[0], bl[1], bl[2], bl[3], wb + WTILE_B + 2 * wbase);
                // Term-outer ordering: same accumulator revisited only every
                // 4 MMAs (breaks the RAW chain on acc registers).
                mma_bf16(acc[0][2 * p],     ah[0], bh);
                mma_bf16(acc[1][2 * p],     ah[1], bh);
                mma_bf16(acc[0][2 * p + 1], ah[0], bh + 2);
                mma_bf16(acc[1][2 * p + 1], ah[1], bh + 2);
                mma_bf16(acc[0][2 * p],     al[0], bh);
                mma_bf16(acc[1][2 * p],     al[1], bh);
                mma_bf16(acc[0][2 * p + 1], al[0], bh + 2);
                mma_bf16(acc[1][2 * p + 1], al[1], bh + 2);
                mma_bf16(acc[0][2 * p],     ah[0], bl);
                mma_bf16(acc[1][2 * p],     ah[1], bl);
                mma_bf16(acc[0][2 * p + 1], ah[0], bl + 2);
                mma_bf16(acc[1][2 * p + 1], ah[1], bl + 2);
            }
        }
        __syncthreads();
    }

    #pragma unroll
    for (int mu = 0; mu < 2; mu++) {
        #pragma unroll
        for (int nf = 0; nf < 8; nf++) {
            int row0 = blockRow + wrow + mu * 16 + g;
            int col  = blockCol + wcol + nf * 8 + tig * 2;
            float v0 = alpha * acc[mu][nf][0], v1 = alpha * acc[mu][nf][1];
            float v2 = alpha * acc[mu][nf][2], v3 = alpha * acc[mu][nf][3];
            if (BFOUT) {
                __nv_bfloat16 h0, h1, h2, h3, l0, l1, l2, l3;
                split_bf16(v0, h0, l0); split_bf16(v1, h1, l1);
                split_bf16(v2, h2, l2); split_bf16(v3, h3, l3);
                *(__nv_bfloat162*)(Ch + (size_t)row0 * DMODEL + col) = __halves2bfloat162(h0, h1);
                *(__nv_bfloat162*)(Cl + (size_t)row0 * DMODEL + col) = __halves2bfloat162(l0, l1);
                *(__nv_bfloat162*)(Ch + (size_t)(row0 + 8) * DMODEL + col) = __halves2bfloat162(h2, h3);
                *(__nv_bfloat162*)(Cl + (size_t)(row0 + 8) * DMODEL + col) = __halves2bfloat162(l2, l3);
            } else {
                *(float2*)(C + (size_t)row0 * DMODEL + col)       = make_float2(v0, v1);
                *(float2*)(C + (size_t)(row0 + 8) * DMODEL + col) = make_float2(v2, v3);
            }
        }
    }
}

struct GemmBatch {
    const __nv_bfloat16 *Ah[3], *Al[3], *Bh[3], *Bl[3];
    __nv_bfloat16 *Ch[3], *Cl[3];
    float alpha[3];
};

__global__ __launch_bounds__(256, 2) void bf16_gemm_qkv(GemmBatch gb)
{
    extern __shared__ __align__(16) char gsm[];
    const int z = blockIdx.z;
    gemm_body<1>(gb.Ah[z], gb.Al[z], gb.Bh[z], gb.Bl[z],
                 nullptr, gb.Ch[z], gb.Cl[z], gb.alpha[z], gsm);
}

__global__ __launch_bounds__(256, 2) void bf16_gemm_out(
    const __nv_bfloat16* __restrict__ Ah, const __nv_bfloat16* __restrict__ Al,
    const __nv_bfloat16* __restrict__ Bh, const __nv_bfloat16* __restrict__ Bl,
    float* __restrict__ C)
{
    extern __shared__ __align__(16) char gsm[];
    gemm_body<0>(Ah, Al, Bh, Bl, C, nullptr, nullptr, 1.0f, gsm);
}

// ---------------------------------------------------------------------------
// Full-bf16 flash attention v6: v5 with RAW-chain-free MMA ordering.
// ---------------------------------------------------------------------------
#define KS  72
#define VT  72
#define FL_KH 0
#define FL_KL (64 * KS)
#define FL_VH (2 * 64 * KS)
#define FL_VL (2 * 64 * KS + 64 * VT)
#define FL_STAGE (2 * 64 * KS + 2 * 64 * VT)       // 18432 u16 per stage
#define FLASH_SMEM_BYTES (2 * FL_STAGE * 2)        // 73728

__global__ __launch_bounds__(256, 2) void flash_bf16_kernel(
    const __nv_bfloat16* __restrict__ Qh, const __nv_bfloat16* __restrict__ Ql,
    const __nv_bfloat16* __restrict__ Kg_h, const __nv_bfloat16* __restrict__ Kg_l,
    const __nv_bfloat16* __restrict__ Vg_h, const __nv_bfloat16* __restrict__ Vg_l,
    const float* __restrict__ bias,
    __nv_bfloat16* __restrict__ Oh, __nv_bfloat16* __restrict__ Ol)
{
    extern __shared__ uint16_t fsm[];
    const uint32_t smb = smem_u32(fsm);

    const int tid  = threadIdx.x;
    const int lane = tid & 31;
    const int wid  = tid >> 5;
    const int g    = lane >> 2;
    const int tig  = lane & 3;
    const int sec  = lane >> 3;
    const int rowin = lane & 7;

    const int h = blockIdx.y;
    const int b = blockIdx.z;
    const int qbase = blockIdx.x * 128;
    const int wrow  = wid * 16;

    const int bias_on = g_bias_nonzero;

    const uint32_t lane_k = (uint32_t)(((sec >> 1) * 8 + rowin) * KS + (sec & 1) * 8);
    const uint32_t lane_v = (uint32_t)(((sec & 1) * 8 + rowin) * VT + (sec >> 1) * 8);

    uint32_t qfh[4][4], qfl[4][4];
    {
        const uint16_t* qhp = (const uint16_t*)Qh + (size_t)(b * SEQ + qbase + wrow) * DMODEL + h * DEPTH;
        const uint16_t* qlp = (const uint16_t*)Ql + (size_t)(b * SEQ + qbase + wrow) * DMODEL + h * DEPTH;
        #pragma unroll
        for (int ks = 0; ks < 4; ks++) {
            const int c0 = ks * 16 + 2 * tig;
            qfh[ks][0] = *(const uint32_t*)(qhp + (size_t)g * DMODEL + c0);
            qfh[ks][1] = *(const uint32_t*)(qhp + (size_t)(g + 8) * DMODEL + c0);
            qfh[ks][2] = *(const uint32_t*)(qhp + (size_t)g * DMODEL + c0 + 8);
            qfh[ks][3] = *(const uint32_t*)(qhp + (size_t)(g + 8) * DMODEL + c0 + 8);
            qfl[ks][0] = *(const uint32_t*)(qlp + (size_t)g * DMODEL + c0);
            qfl[ks][1] = *(const uint32_t*)(qlp + (size_t)(g + 8) * DMODEL + c0);
            qfl[ks][2] = *(const uint32_t*)(qlp + (size_t)g * DMODEL + c0 + 8);
            qfl[ks][3] = *(const uint32_t*)(qlp + (size_t)(g + 8) * DMODEL + c0 + 8);
        }
    }

    float o[8][4];
    #pragma unroll
    for (int nf = 0; nf < 8; nf++)
        #pragma unroll
        for (int r = 0; r < 4; r++) o[nf][r] = 0.0f;
    float m0 = -CUDART_INF_F, m1 = -CUDART_INF_F, l0 = 0.f, l1 = 0.f;

    const float* bp0 = bias + (size_t)(qbase + wrow + g) * SEQ;
    const float* bp8 = bias + (size_t)(qbase + wrow + g + 8) * SEQ;

    auto load_kv = [&](int kt, int buf) {
        const uint32_t sb = smb + (uint32_t)(buf * FL_STAGE) * 2;
        #pragma unroll
        for (int j = 0; j < 2; j++) {
            int idx = tid + j * 256;
            int row = idx >> 3;
            int seg = idx & 7;
            size_t src = (size_t)(b * SEQ + kt + row) * DMODEL + h * DEPTH + seg * 8;
            uint32_t soff = (uint32_t)(row * KS + seg * 8) * 2;
            CP_ASYNC16(sb + 2 * FL_KH + soff, (const uint16_t*)Kg_h + src);
            CP_ASYNC16(sb + 2 * FL_KL + soff, (const uint16_t*)Kg_l + src);
            CP_ASYNC16(sb + 2 * FL_VH + soff, (const uint16_t*)Vg_h + src);
            CP_ASYNC16(sb + 2 * FL_VL + soff, (const uint16_t*)Vg_l + src);
        }
    };

    load_kv(0, 0);
    CP_COMMIT();

    const int NIT = SEQ / 64;
    for (int it = 0; it < NIT; it++) {
        const int kt = it * 64;
        if (it + 1 < NIT) {
            load_kv(kt + 64, (it + 1) & 1);
            CP_COMMIT();
            CP_WAIT1();
        } else {
            CP_WAIT0();
        }
        __syncthreads();

        const uint32_t sb = smb + (uint32_t)((it & 1) * FL_STAGE) * 2;

        float s[8][4];
        #pragma unroll
        for (int nf = 0; nf < 8; nf++)
            #pragma unroll
            for (int r = 0; r < 4; r++) s[nf][r] = 0.0f;

        #pragma unroll
        for (int ks = 0; ks < 4; ks++) {
            #pragma unroll
            for (int p = 0; p < 4; p++) {
                const uint32_t off = lane_k + (uint32_t)(p * 16 * KS + ks * 16);
                uint32_t bh[4], bl[4];
                ldsm_x4(bh[0], bh[1], bh[2], bh[3], sb + 2 * (FL_KH + off));
                ldsm_x4(bl[0], bl[1], bl[2], bl[3], sb + 2 * (FL_KL + off));
                // Pair-interleaved: s[2p] / s[2p+1] alternate (spacing 2)
                mma_bf16(s[2 * p],     qfh[ks], bh);
                mma_bf16(s[2 * p + 1], qfh[ks], bh + 2);
                mma_bf16(s[2 * p],     qfl[ks], bh);
                mma_bf16(s[2 * p + 1], qfl[ks], bh + 2);
                mma_bf16(s[2 * p],     qfh[ks], bl);
                mma_bf16(s[2 * p + 1], qfh[ks], bl + 2);
            }
        }

        float mx0 = -CUDART_INF_F, mx1 = -CUDART_INF_F;
        if (bias_on) {
            #pragma unroll
            for (int nf = 0; nf < 8; nf++) {
                float2 b0 = *(const float2*)(bp0 + kt + nf * 8 + tig * 2);
                float2 b1 = *(const float2*)(bp8 + kt + nf * 8 + tig * 2);
                s[nf][0] += b0.x; s[nf][1] += b0.y;
                s[nf][2] += b1.x; s[nf][3] += b1.y;
            }
        }
        #pragma unroll
        for (int nf = 0; nf < 8; nf++) {
            mx0 = fmaxf(mx0, fmaxf(s[nf][0], s[nf][1]));
            mx1 = fmaxf(mx1, fmaxf(s[nf][2], s[nf][3]));
        }
        mx0 = fmaxf(mx0, __shfl_xor_sync(0xFFFFFFFFu, mx0, 1));
        mx0 = fmaxf(mx0, __shfl_xor_sync(0xFFFFFFFFu, mx0, 2));
        mx1 = fmaxf(mx1, __shfl_xor_sync(0xFFFFFFFFu, mx1, 1));
        mx1 = fmaxf(mx1, __shfl_xor_sync(0xFFFFFFFFu, mx1, 2));

        float nm0 = fmaxf(m0, mx0), nm1 = fmaxf(m1, mx1);
        float c0f = __expf(m0 - nm0), c1f = __expf(m1 - nm1);
        l0 *= c0f; l1 *= c1f; m0 = nm0; m1 = nm1;
        #pragma unroll
        for (int nf = 0; nf < 8; nf++) {
            o[nf][0] *= c0f; o[nf][1] *= c0f; o[nf][2] *= c1f; o[nf][3] *= c1f;
        }
        uint32_t pfh[4][4], pfl[4][4];
        float la0 = 0.f, la1 = 0.f;
        #pragma unroll
        for (int nf = 0; nf < 8; nf++) {
            float p0 = __expf(s[nf][0] - nm0);
            float p1 = __expf(s[nf][1] - nm0);
            float p2 = __expf(s[nf][2] - nm1);
            float p3 = __expf(s[nf][3] - nm1);
            la0 += p0 + p1; la1 += p2 + p3;
            const int ks = nf >> 1;
            const int rbase = (nf & 1) * 2;
            split_pair_trunc(p0, p1, pfh[ks][rbase + 0], pfl[ks][rbase + 0]);
            split_pair_trunc(p2, p3, pfh[ks][rbase + 1], pfl[ks][rbase + 1]);
        }
        la0 += __shfl_xor_sync(0xFFFFFFFFu, la0, 1);
        la0 += __shfl_xor_sync(0xFFFFFFFFu, la0, 2);
        la1 += __shfl_xor_sync(0xFFFFFFFFu, la1, 1);
        la1 += __shfl_xor_sync(0xFFFFFFFFu, la1, 2);
        l0 += la0; l1 += la1;

        #pragma unroll
        for (int ks = 0; ks < 4; ks++) {
            #pragma unroll
            for (int p = 0; p < 4; p++) {
                const uint32_t off = lane_v + (uint32_t)(ks * 16 * VT + p * 16);
                uint32_t vh[4], vl[4];
                ldsm_x4_t(vh[0], vh[1], vh[2], vh[3], sb + 2 * (FL_VH + off));
                ldsm_x4_t(vl[0], vl[1], vl[2], vl[3], sb + 2 * (FL_VL + off));
                // Pair-interleaved: o[2p] / o[2p+1] alternate (spacing 2)
                mma_bf16(o[2 * p],     pfh[ks], vh);
                mma_bf16(o[2 * p + 1], pfh[ks], vh + 2);
                mma_bf16(o[2 * p],     pfl[ks], vh);
                mma_bf16(o[2 * p + 1], pfl[ks], vh + 2);
                mma_bf16(o[2 * p],     pfh[ks], vl);
                mma_bf16(o[2 * p + 1], pfh[ks], vl + 2);
            }
        }
        __syncthreads();
    }

    const float inv0 = 1.0f / l0, inv1 = 1.0f / l1;
    uint16_t* ohp0 = (uint16_t*)Oh + (size_t)(b * SEQ + qbase + wrow + g) * DMODEL + h * DEPTH;
    uint16_t* olp0 = (uint16_t*)Ol + (size_t)(b * SEQ + qbase + wrow + g) * DMODEL + h * DEPTH;
    uint16_t* ohp8 = ohp0 + (size_t)8 * DMODEL;
    uint16_t* olp8 = olp0 + (size_t)8 * DMODEL;
    #pragma unroll
    for (int nf = 0; nf < 8; nf++) {
        float v0 = o[nf][0] * inv0, v1 = o[nf][1] * inv0;
        float v2 = o[nf][2] * inv1, v3 = o[nf][3] * inv1;
        uint32_t h01, l01, h23, l23;
        split_pair_trunc(v0, v1, h01, l01);
        split_pair_trunc(v2, v3, h23, l23);
        const int col = nf * 8 + tig * 2;
        *(uint32_t*)(ohp0 + col) = h01;
        *(uint32_t*)(olp0 + col) = l01;
        *(uint32_t*)(ohp8 + col) = h23;
        *(uint32_t*)(olp8 + col) = l23;
    }
}

// ---------------------------------------------------------------------------
// Launch
// ---------------------------------------------------------------------------
extern "C" void kernel_launch(void* const* d_in, const int* in_sizes, int n_in,
                              void* d_out, int out_size)
{
    const float* x    = (const float*)d_in[0];
    const float* y    = (const float*)d_in[1];
    const float* bias = (const float*)d_in[2];
    const float* Wq   = (const float*)d_in[3];
    const float* Wk   = (const float*)d_in[4];
    const float* Wv   = (const float*)d_in[5];
    const float* Wo   = (const float*)d_in[6];
    float* out = (float*)d_out;

    __nv_bfloat16 *ah, *al, *yh, *yl, *qh, *ql, *kh, *kl, *vh, *vl;
    __nv_bfloat16 *wqh, *wql, *wkh, *wkl, *wvh, *wvl, *woh, *wol;
    cudaGetSymbolAddress((void**)&ah,  g_ah);
    cudaGetSymbolAddress((void**)&al,  g_al);
    cudaGetSymbolAddress((void**)&yh,  g_yh);
    cudaGetSymbolAddress((void**)&yl,  g_yl);
    cudaGetSymbolAddress((void**)&qh,  g_qh);
    cudaGetSymbolAddress((void**)&ql,  g_ql);
    cudaGetSymbolAddress((void**)&kh,  g_kh);
    cudaGetSymbolAddress((void**)&kl,  g_kl);
    cudaGetSymbolAddress((void**)&vh,  g_vh);
    cudaGetSymbolAddress((void**)&vl,  g_vl);
    cudaGetSymbolAddress((void**)&wqh, g_wqh);
    cudaGetSymbolAddress((void**)&wql, g_wql);
    cudaGetSymbolAddress((void**)&wkh, g_wkh);
    cudaGetSymbolAddress((void**)&wkl, g_wkl);
    cudaGetSymbolAddress((void**)&wvh, g_wvh);
    cudaGetSymbolAddress((void**)&wvl, g_wvl);
    cudaGetSymbolAddress((void**)&woh, g_woh);
    cudaGetSymbolAddress((void**)&wol, g_wol);

    cudaFuncSetAttribute(flash_bf16_kernel,
                         cudaFuncAttributeMaxDynamicSharedMemorySize, FLASH_SMEM_BYTES);
    cudaFuncSetAttribute(bf16_gemm_qkv,
                         cudaFuncAttributeMaxDynamicSharedMemorySize, GEMM_SMEM);
    cudaFuncSetAttribute(bf16_gemm_out,
                         cudaFuncAttributeMaxDynamicSharedMemorySize, GEMM_SMEM);

    // Bias zero-detection (fast path trigger; correct for any input)
    reset_flag_kernel<<<1, 1, 0, 0>>>();
    bias_check_kernel<<<512, 256, 0, 0>>>(bias, SEQ * SEQ / 4);

    // One batched elementwise split: x, y, and the 4 weights (stored [K][N])
    const int n4_xy = MROWS * DMODEL / 4;        // 1048576
    const int n4_w  = DMODEL * DMODEL / 4;       // 262144
    SplitBatch sb;
    sb.in[0] = x;  sb.oh[0] = ah;  sb.ol[0] = al;  sb.n4[0] = n4_xy;
    sb.in[1] = y;  sb.oh[1] = yh;  sb.ol[1] = yl;  sb.n4[1] = n4_xy;
    sb.in[2] = Wq; sb.oh[2] = wqh; sb.ol[2] = wql; sb.n4[2] = n4_w;
    sb.in[3] = Wk; sb.oh[3] = wkh; sb.ol[3] = wkl; sb.n4[3] = n4_w;
    sb.in[4] = Wv; sb.oh[4] = wvh; sb.ol[4] = wvl; sb.n4[4] = n4_w;
    sb.in[5] = Wo; sb.oh[5] = woh; sb.ol[5] = wol; sb.n4[5] = n4_w;
    dim3 sgrid((n4_xy + 255) / 256, 1, 6);
    split_kernel<<<sgrid, 256, 0, 0>>>(sb);

    // Batched q/k/v projections: one launch, grid.z = 3
    GemmBatch gb;
    gb.Ah[0] = ah; gb.Al[0] = al; gb.Bh[0] = wqh; gb.Bl[0] = wql;
    gb.Ch[0] = qh; gb.Cl[0] = ql; gb.alpha[0] = 8.0f;   // * sqrt(depth)
    gb.Ah[1] = yh; gb.Al[1] = yl; gb.Bh[1] = wkh; gb.Bl[1] = wkl;
    gb.Ch[1] = kh; gb.Cl[1] = kl; gb.alpha[1] = 1.0f;
    gb.Ah[2] = yh; gb.Al[2] = yl; gb.Bh[2] = wvh; gb.Bl[2] = wvl;
    gb.Ch[2] = vh; gb.Cl[2] = vl; gb.alpha[2] = 1.0f;

    dim3 qkvgrid(DMODEL / 128, MROWS / 128, 3);   // (8, 32, 3)
    bf16_gemm_qkv<<<qkvgrid, 256, GEMM_SMEM, 0>>>(gb);

    dim3 fgrid(SEQ / 128, NHEADS, BATCH);         // (16, 16, 2)
    flash_bf16_kernel<<<fgrid, 256, FLASH_SMEM_BYTES, 0>>>(
        qh, ql, kh, kl, vh, vl, bias, ah, al);

    dim3 ggrid(DMODEL / 128, MROWS / 128);        // (8, 32)
    bf16_gemm_out<<<ggrid, 256, GEMM_SMEM, 0>>>(ah, al, woh, wol, out);
}